// round 10
// baseline (speedup 1.0000x reference)
#include <cuda_runtime.h>
#include <cuda_bf16.h>
#include <math.h>

#define HW 16384
#define HH 128
#define WW 128
#define NB 4

typedef unsigned long long u64;
typedef unsigned int u32;
typedef __nv_bfloat16 bf16;

// ---------------- f32x2 helpers (attention) ---------------------------------
__device__ __forceinline__ u64 pack2(float lo, float hi) {
    u64 r; asm("mov.b64 %0,{%1,%2};" : "=l"(r) : "f"(lo), "f"(hi)); return r;
}
__device__ __forceinline__ void unpack2(u64 v, float& lo, float& hi) {
    asm("mov.b64 {%0,%1},%2;" : "=f"(lo), "=f"(hi) : "l"(v));
}
__device__ __forceinline__ u64 ffma2(u64 a, u64 b, u64 c) {
    u64 r; asm("fma.rn.f32x2 %0,%1,%2,%3;" : "=l"(r) : "l"(a), "l"(b), "l"(c)); return r;
}

// ---------------- scratch ----------------------------------------------------
__device__ __align__(256) float g_qkv [NB * 192 * HW];
__device__ __align__(256) float g_v   [NB * 64  * HW];
__device__ __align__(256) float g_qg  [NB * 64  * HW];
__device__ __align__(256) float g_kv  [NB * 128 * 256];
__device__ __align__(256) float g_xp  [NB * 128 * 256];
__device__ __align__(256) bf16  g_xh  [NB * 128 * HW];
__device__ __align__(256) bf16  g_xl  [NB * 128 * HW];
__device__ __align__(256) bf16  g_qkh [NB * 64 * HW];
__device__ __align__(256) bf16  g_qkl [NB * 64 * HW];
__device__ __align__(256) bf16  g_ch  [NB * 128 * HW];
__device__ __align__(256) bf16  g_cl  [NB * 128 * HW];
__device__ __align__(256) bf16  g_w1h [256 * 128];
__device__ __align__(256) bf16  g_w1l [256 * 128];
__device__ __align__(256) bf16  g_wa1h[64 * 64];
__device__ __align__(256) bf16  g_wa1l[64 * 64];
__device__ __align__(256) bf16  g_wa2h[64 * 64];
__device__ __align__(256) bf16  g_wa2l[64 * 64];
__device__ __align__(256) bf16  g_wph [128 * 128];
__device__ __align__(256) bf16  g_wpl [128 * 128];
__device__ __align__(256) float g_b1  [256];

// ---------------- mma / cp.async helpers ------------------------------------
__device__ __forceinline__ u32 smem_u32(const void* p) {
    u32 a;
    asm("{ .reg .u64 t; cvta.to.shared.u64 t, %1; cvt.u32.u64 %0, t; }"
        : "=r"(a) : "l"(p));
    return a;
}
__device__ __forceinline__ void ldm_x4(u32 a, u32& r0, u32& r1, u32& r2, u32& r3) {
    asm volatile("ldmatrix.sync.aligned.m8n8.x4.shared.b16 {%0,%1,%2,%3},[%4];"
                 : "=r"(r0), "=r"(r1), "=r"(r2), "=r"(r3) : "r"(a));
}
__device__ __forceinline__ void ldm_x4t(u32 a, u32& r0, u32& r1, u32& r2, u32& r3) {
    asm volatile("ldmatrix.sync.aligned.m8n8.x4.trans.shared.b16 {%0,%1,%2,%3},[%4];"
                 : "=r"(r0), "=r"(r1), "=r"(r2), "=r"(r3) : "r"(a));
}
__device__ __forceinline__ void mma_bf16(float* c, const u32* a, u32 b0, u32 b1) {
    asm volatile(
        "mma.sync.aligned.m16n8k16.row.col.f32.bf16.bf16.f32 "
        "{%0,%1,%2,%3},{%4,%5,%6,%7},{%8,%9},{%0,%1,%2,%3};"
        : "+f"(c[0]), "+f"(c[1]), "+f"(c[2]), "+f"(c[3])
        : "r"(a[0]), "r"(a[1]), "r"(a[2]), "r"(a[3]), "r"(b0), "r"(b1));
}
__device__ __forceinline__ void cpa16(u32 d, const void* s) {
    asm volatile("cp.async.cg.shared.global [%0],[%1],16;" :: "r"(d), "l"(s));
}
__device__ __forceinline__ void cp_commit() {
    asm volatile("cp.async.commit_group;" ::: "memory");
}
template<int N> __device__ __forceinline__ void cp_wait() {
    asm volatile("cp.async.wait_group %0;" :: "n"(N) : "memory");
}
__device__ __forceinline__ void split2(float x0, float x1, u32& h, u32& l) {
    bf16 h0 = __float2bfloat16(x0);
    bf16 h1 = __float2bfloat16(x1);
    float r0 = x0 - __bfloat162float(h0);
    float r1 = x1 - __bfloat162float(h1);
    __nv_bfloat162 hp; hp.x = h0; hp.y = h1;
    __nv_bfloat162 lp; lp.x = __float2bfloat16(r0); lp.y = __float2bfloat16(r1);
    h = *reinterpret_cast<u32*>(&hp);
    l = *reinterpret_cast<u32*>(&lp);
}
__device__ __forceinline__ void split1(float x, bf16* hd, bf16* ld, size_t o) {
    bf16 h = __float2bfloat16(x);
    hd[o] = h;
    ld[o] = __float2bfloat16(x - __bfloat162float(h));
}

// ---------------- GEMM geometry ----------------------------------------------
#define APITCH 40
#define BPITCH 264
#define APB (64 * APITCH * 2)
#define BPB (32 * BPITCH * 2)
#define SMEM_BYTES (4 * APB + 4 * BPB)

// ---------------- generic bf16-split tensor-core GEMM -----------------------
// grid = (oc_tiles, px_tiles, batch): oc fastest so consecutive blocks share
// the same B (X) tile through L2.
template<bool DUAL>
__global__ void __launch_bounds__(256, 2) gemm_bf16(
    const bf16* __restrict__ Xh, const bf16* __restrict__ Xl,
    const bf16* __restrict__ Wh, const bf16* __restrict__ Wl,
    const float* __restrict__ bias, int IC, int NPIX,
    float* dstf, int dstf_stride,
    float* dstf2, int dst2_stride, int oc_split)
{
    extern __shared__ __align__(16) char sm[];
    const int tid = threadIdx.x;
    const int lane = tid & 31, warp = tid >> 5;
    const int oc0 = blockIdx.x * 64;
    const int px0 = blockIdx.y * 256;
    const int b   = blockIdx.z;
    const u32 smb = smem_u32(sm);

    const bf16* Xhb = Xh + (size_t)b * IC * NPIX;
    const bf16* Xlb = Xl + (size_t)b * IC * NPIX;

    const int ar = tid >> 2, ac = (tid & 3) * 8;
    const int bc = (tid & 31) * 8, br0 = tid >> 5;
    const int nk = IC >> 5;

    float c[4][4][4];
    #pragma unroll
    for (int i = 0; i < 4; i++)
        #pragma unroll
        for (int j = 0; j < 4; j++)
            #pragma unroll
            for (int q = 0; q < 4; q++) c[i][j][q] = 0.f;

    auto issue = [&](int it) {
        const int st = it & 1;
        const int k0 = it << 5;
        u32 aD = smb + st * 2 * APB + (u32)(ar * APITCH + ac) * 2;
        const size_t aO = (size_t)(oc0 + ar) * IC + k0 + ac;
        cpa16(aD, Wh + aO);
        cpa16(aD + APB, Wl + aO);
        const u32 bBase = smb + 4 * APB + st * 2 * BPB;
        #pragma unroll
        for (int i = 0; i < 4; i++) {
            const int brr = br0 + i * 8;
            u32 bD = bBase + (u32)(brr * BPITCH + bc) * 2;
            const size_t bO = (size_t)(k0 + brr) * NPIX + px0 + bc;
            cpa16(bD, Xhb + bO);
            cpa16(bD + BPB, Xlb + bO);
        }
        cp_commit();
    };

    issue(0);

    const int grp = lane >> 3, lr = lane & 7;
    const int r8  = (grp & 1) * 8 + lr;
    const int kh8 = (grp >> 1) * 8;
    const int wn32 = warp * 32;

    for (int it = 0; it < nk; it++) {
        if (it + 1 < nk) { issue(it + 1); cp_wait<1>(); }
        else             { cp_wait<0>(); }
        __syncthreads();
        const int st = it & 1;
        const u32 aHi = smb + st * 2 * APB, aLo = aHi + APB;
        const u32 bHi = smb + 4 * APB + st * 2 * BPB, bLo = bHi + BPB;
        #pragma unroll
        for (int ks = 0; ks < 2; ks++) {
            u32 bh[2][4], bl[2][4];
            #pragma unroll
            for (int g = 0; g < 2; g++) {
                const u32 off = (u32)((ks * 16 + r8) * BPITCH + wn32 + g * 16 + kh8) * 2;
                ldm_x4t(bHi + off, bh[g][0], bh[g][1], bh[g][2], bh[g][3]);
                ldm_x4t(bLo + off, bl[g][0], bl[g][1], bl[g][2], bl[g][3]);
            }
            #pragma unroll
            for (int mi = 0; mi < 4; mi++) {
                u32 ah[4], al[4];
                const u32 aoff = (u32)((mi * 16 + r8) * APITCH + ks * 16 + kh8) * 2;
                ldm_x4(aHi + aoff, ah[0], ah[1], ah[2], ah[3]);
                ldm_x4(aLo + aoff, al[0], al[1], al[2], al[3]);
                #pragma unroll
                for (int nj = 0; nj < 4; nj++) {
                    const int g = nj >> 1, s2 = nj & 1;
                    mma_bf16(c[mi][nj], ah, bh[g][2 * s2], bh[g][2 * s2 + 1]);
                    mma_bf16(c[mi][nj], ah, bl[g][2 * s2], bl[g][2 * s2 + 1]);
                    mma_bf16(c[mi][nj], al, bh[g][2 * s2], bh[g][2 * s2 + 1]);
                }
            }
        }
        __syncthreads();
    }

    // ---- epilogue
    const int r4 = lane >> 2, c2 = (lane & 3) * 2;
    #pragma unroll
    for (int mi = 0; mi < 4; mi++) {
        #pragma unroll
        for (int h = 0; h < 2; h++) {
            const int oc = oc0 + mi * 16 + h * 8 + r4;
            const float bv = bias[oc];
            #pragma unroll
            for (int nj = 0; nj < 4; nj++) {
                const int px = px0 + wn32 + nj * 8 + c2;
                const float v0 = c[mi][nj][h * 2]     + bv;
                const float v1 = c[mi][nj][h * 2 + 1] + bv;
                if (DUAL) {
                    if (oc < oc_split)
                        *reinterpret_cast<float2*>(dstf + (size_t)b * dstf_stride
                            + (size_t)oc * NPIX + px) = make_float2(v0, v1);
                    else
                        *reinterpret_cast<float2*>(dstf2 + (size_t)b * dst2_stride
                            + (size_t)(oc - oc_split) * NPIX + px) = make_float2(v0, v1);
                } else {
                    *reinterpret_cast<float2*>(dstf + (size_t)b * dstf_stride
                        + (size_t)oc * NPIX + px) = make_float2(v0, v1);
                }
            }
        }
    }
}

// ---------------- fused a1->swish->a2->tanh*v, 128-px tiles -----------------
#define F2PITCH 136
#define F2STG (32 * F2PITCH * 2)
#define F2W1H (4 * F2STG)
#define F2W1L (F2W1H + 64 * 72 * 2)
#define F2W2H (F2W1L + 64 * 72 * 2)
#define F2W2L (F2W2H + 64 * 72 * 2)
#define F2SMEM (F2W2L + 64 * 72 * 2)

__global__ void __launch_bounds__(256, 3) fused_a1a2(
    const bf16* __restrict__ qkh, const bf16* __restrict__ qkl,
    const float* __restrict__ ba1, const float* __restrict__ ba2,
    const float* __restrict__ vsrc,
    bf16* __restrict__ ch, bf16* __restrict__ cl)
{
    extern __shared__ __align__(16) char sm[];
    const int tid = threadIdx.x;
    const int lane = tid & 31, warp = tid >> 5;
    const int px0 = blockIdx.x * 128;
    const int b   = blockIdx.y;
    const u32 smb = smem_u32(sm);

    const bf16* qkhb = qkh + (size_t)b * 64 * HW + px0;
    const bf16* qklb = qkl + (size_t)b * 64 * HW + px0;

    {
        const int r = tid >> 2;
        const int sb = (tid & 3) * 32;
        const size_t go = (size_t)r * 64 + (tid & 3) * 16;
        const u32 so = (u32)(r * 72) * 2 + sb;
        cpa16(smb + F2W1H + so, g_wa1h + go); cpa16(smb + F2W1H + so + 16, g_wa1h + go + 8);
        cpa16(smb + F2W1L + so, g_wa1l + go); cpa16(smb + F2W1L + so + 16, g_wa1l + go + 8);
        cpa16(smb + F2W2H + so, g_wa2h + go); cpa16(smb + F2W2H + so + 16, g_wa2h + go + 8);
        cpa16(smb + F2W2L + so, g_wa2l + go); cpa16(smb + F2W2L + so + 16, g_wa2l + go + 8);
    }
    const int bc = (tid & 15) * 8, br0 = tid >> 4;
    auto issueB = [&](int chunk) {
        const u32 base = smb + chunk * 2 * F2STG;
        #pragma unroll
        for (int i = 0; i < 2; i++) {
            const int brr = br0 + i * 16;
            const u32 d = base + (u32)(brr * F2PITCH + bc) * 2;
            const size_t o = (size_t)(chunk * 32 + brr) * HW + bc;
            cpa16(d, qkhb + o);
            cpa16(d + F2STG, qklb + o);
        }
        cp_commit();
    };
    issueB(0);
    issueB(1);

    const int grp = lane >> 3, lr = lane & 7;
    const int r8  = (grp & 1) * 8 + lr;
    const int kh8 = (grp >> 1) * 8;
    const int wn16 = warp * 16;
    const int r4 = lane >> 2, c2 = (lane & 3) * 2;

    float c[4][2][4];
    #pragma unroll
    for (int i = 0; i < 4; i++)
        #pragma unroll
        for (int j = 0; j < 2; j++)
            #pragma unroll
            for (int q = 0; q < 4; q++) c[i][j][q] = 0.f;

    for (int it = 0; it < 2; it++) {
        if (it == 0) cp_wait<1>(); else cp_wait<0>();
        __syncthreads();
        const u32 bHi = smb + it * 2 * F2STG, bLo = bHi + F2STG;
        #pragma unroll
        for (int ks = 0; ks < 2; ks++) {
            u32 bh[4], bl[4];
            const u32 off = (u32)((ks * 16 + r8) * F2PITCH + wn16 + kh8) * 2;
            ldm_x4t(bHi + off, bh[0], bh[1], bh[2], bh[3]);
            ldm_x4t(bLo + off, bl[0], bl[1], bl[2], bl[3]);
            #pragma unroll
            for (int mi = 0; mi < 4; mi++) {
                u32 ah[4], al[4];
                const u32 aoff = (u32)((mi * 16 + r8) * 72 + it * 32 + ks * 16 + kh8) * 2;
                ldm_x4(smb + F2W1H + aoff, ah[0], ah[1], ah[2], ah[3]);
                ldm_x4(smb + F2W1L + aoff, al[0], al[1], al[2], al[3]);
                #pragma unroll
                for (int nj = 0; nj < 2; nj++) {
                    mma_bf16(c[mi][nj], ah, bh[2 * nj], bh[2 * nj + 1]);
                    mma_bf16(c[mi][nj], ah, bl[2 * nj], bl[2 * nj + 1]);
                    mma_bf16(c[mi][nj], al, bh[2 * nj], bh[2 * nj + 1]);
                }
            }
        }
    }
    __syncthreads();

    #pragma unroll
    for (int mi = 0; mi < 4; mi++) {
        #pragma unroll
        for (int h = 0; h < 2; h++) {
            const int oc = mi * 16 + h * 8 + r4;
            const float bv = __ldg(&ba1[oc]);
            const u32 halfb = (oc & 32) ? 2u * F2STG : 0u;
            #pragma unroll
            for (int nj = 0; nj < 2; nj++) {
                float v0 = c[mi][nj][h * 2]     + bv;
                float v1 = c[mi][nj][h * 2 + 1] + bv;
                v0 = v0 / (1.f + __expf(-v0));
                v1 = v1 / (1.f + __expf(-v1));
                u32 hp, lp; split2(v0, v1, hp, lp);
                const u32 off = (u32)((oc & 31) * F2PITCH + wn16 + nj * 8 + c2) * 2;
                *reinterpret_cast<u32*>(sm + halfb + off)         = hp;
                *reinterpret_cast<u32*>(sm + halfb + F2STG + off) = lp;
            }
        }
    }
    __syncthreads();

    #pragma unroll
    for (int i = 0; i < 4; i++)
        #pragma unroll
        for (int j = 0; j < 2; j++)
            #pragma unroll
            for (int q = 0; q < 4; q++) c[i][j][q] = 0.f;

    #pragma unroll
    for (int it = 0; it < 2; it++) {
        const u32 bHi = smb + it * 2 * F2STG, bLo = bHi + F2STG;
        #pragma unroll
        for (int ks = 0; ks < 2; ks++) {
            u32 bh[4], bl[4];
            const u32 off = (u32)((ks * 16 + r8) * F2PITCH + wn16 + kh8) * 2;
            ldm_x4t(bHi + off, bh[0], bh[1], bh[2], bh[3]);
            ldm_x4t(bLo + off, bl[0], bl[1], bl[2], bl[3]);
            #pragma unroll
            for (int mi = 0; mi < 4; mi++) {
                u32 ah[4], al[4];
                const u32 aoff = (u32)((mi * 16 + r8) * 72 + it * 32 + ks * 16 + kh8) * 2;
                ldm_x4(smb + F2W2H + aoff, ah[0], ah[1], ah[2], ah[3]);
                ldm_x4(smb + F2W2L + aoff, al[0], al[1], al[2], al[3]);
                #pragma unroll
                for (int nj = 0; nj < 2; nj++) {
                    mma_bf16(c[mi][nj], ah, bh[2 * nj], bh[2 * nj + 1]);
                    mma_bf16(c[mi][nj], ah, bl[2 * nj], bl[2 * nj + 1]);
                    mma_bf16(c[mi][nj], al, bh[2 * nj], bh[2 * nj + 1]);
                }
            }
        }
    }

    #pragma unroll
    for (int mi = 0; mi < 4; mi++) {
        #pragma unroll
        for (int h = 0; h < 2; h++) {
            const int oc = mi * 16 + h * 8 + r4;
            const float bv = __ldg(&ba2[oc]);
            #pragma unroll
            for (int nj = 0; nj < 2; nj++) {
                const int px = px0 + wn16 + nj * 8 + c2;
                const float* vr = vsrc + ((size_t)b * 64 + oc) * HW + px;
                float v0 = tanhf((c[mi][nj][h * 2]     + bv) * 0.25f) * __ldg(vr);
                float v1 = tanhf((c[mi][nj][h * 2 + 1] + bv) * 0.25f) * __ldg(vr + 1);
                u32 hp, lp; split2(v0, v1, hp, lp);
                const size_t o = ((size_t)b * 128 + oc) * HW + px;
                *reinterpret_cast<u32*>(ch + o) = hp;
                *reinterpret_cast<u32*>(cl + o) = lp;
            }
        }
    }
}

// ---------------- weight prep ------------------------------------------------
__global__ void prep_weights(
    const float* __restrict__ Wqkv, const float* __restrict__ Wq,
    const float* __restrict__ Wa1, const float* __restrict__ Wa2,
    const float* __restrict__ Wproj,
    const float* __restrict__ bqkv, const float* __restrict__ bq)
{
    const int i = blockIdx.x * 256 + threadIdx.x;
    if (i < 32768) {
        float v = (i < 24576) ? Wqkv[i] : Wq[i - 24576];
        split1(v, g_w1h, g_w1l, i);
    } else if (i < 36864) {
        split1(Wa1[i - 32768], g_wa1h, g_wa1l, i - 32768);
    } else if (i < 40960) {
        split1(Wa2[i - 36864], g_wa2h, g_wa2l, i - 36864);
    } else if (i < 57344) {
        split1(Wproj[i - 40960], g_wph, g_wpl, i - 40960);
    } else if (i < 57600) {
        const int j = i - 57344;
        g_b1[j] = (j < 192) ? bqkv[j] : bq[j - 192];
    }
}

// ---------------- x -> hi/lo bf16 + 8x8 avgpool (one pass) -------------------
__global__ void __launch_bounds__(256) cvtpool(
    const float* __restrict__ x, bf16* __restrict__ xh, bf16* __restrict__ xl,
    float* __restrict__ xp)
{
    const int plane = blockIdx.x;
    const int t = threadIdx.x;
    const int wi = t >> 4, wj = t & 15;
    const float* sp = x + (size_t)plane * HW + (wi * 8) * WW + wj * 8;
    bf16* oh = xh + (size_t)plane * HW + (wi * 8) * WW + wj * 8;
    bf16* ol = xl + (size_t)plane * HW + (wi * 8) * WW + wj * 8;

    float s = 0.f;
    #pragma unroll
    for (int r = 0; r < 8; r++) {
        const float4 a = *reinterpret_cast<const float4*>(sp + r * WW);
        const float4 b = *reinterpret_cast<const float4*>(sp + r * WW + 4);
        s += a.x + a.y + a.z + a.w + b.x + b.y + b.z + b.w;
        u32 h0, l0, h1, l1, h2, l2, h3, l3;
        split2(a.x, a.y, h0, l0); split2(a.z, a.w, h1, l1);
        split2(b.x, b.y, h2, l2); split2(b.z, b.w, h3, l3);
        *reinterpret_cast<uint4*>(oh + r * WW) = make_uint4(h0, h1, h2, h3);
        *reinterpret_cast<uint4*>(ol + r * WW) = make_uint4(l0, l1, l2, l3);
    }
    xp[(size_t)plane * 256 + wi * 16 + wj] = s * (1.f / 64.f);
}

// ---------------- depthwise 3x3, smem-tiled rolling stencil -----------------
__global__ void __launch_bounds__(128) dwconv_qk(
    const float* __restrict__ qkv, const float* __restrict__ w,
    const float* __restrict__ bias,
    bf16* __restrict__ qkh, bf16* __restrict__ qkl,
    float* __restrict__ vout)
{
    const int z = blockIdx.z;
    const int b = z >> 7, t = z & 127;
    const int x = threadIdx.x;
    const int y0 = blockIdx.y * 16;

    __shared__ float s0[18][136];
    __shared__ float s1[18][136];

    if (t < 64) {
        const float* pq = qkv + ((size_t)b * 192 + t) * HW;
        const float* pk = qkv + ((size_t)b * 192 + 64 + t) * HW;
        #pragma unroll
        for (int r = 0; r < 18; r++) {
            const int yy = y0 - 1 + r;
            const bool ok = (yy >= 0) && (yy < HH);
            s0[r][x + 1] = ok ? __ldg(pq + yy * WW + x) : 0.f;
            s1[r][x + 1] = ok ? __ldg(pk + yy * WW + x) : 0.f;
        }
        if (x < 2) {
            const int col = x ? 129 : 0;
            #pragma unroll
            for (int r = 0; r < 18; r++) { s0[r][col] = 0.f; s1[r][col] = 0.f; }
        }
        __syncthreads();

        float wq[9], wk[9];
        #pragma unroll
        for (int i = 0; i < 9; i++) {
            wq[i] = __ldg(&w[t * 9 + i]);
            wk[i] = __ldg(&w[(64 + t) * 9 + i]);
        }
        const float bq = __ldg(&bias[t]);
        const float bk = __ldg(&bias[64 + t]);

        bf16* oh = qkh + ((size_t)b * 64 + t) * HW + (size_t)y0 * WW + x;
        bf16* ol = qkl + ((size_t)b * 64 + t) * HW + (size_t)y0 * WW + x;

        float Aq = 0.f, Bq = 0.f, Ak = 0.f, Bk = 0.f;
        #pragma unroll
        for (int r = 0; r < 18; r++) {
            const float lq = s0[r][x], cq = s0[r][x + 1], rq = s0[r][x + 2];
            const float h0q = wq[0]*lq + wq[1]*cq + wq[2]*rq;
            const float h1q = wq[3]*lq + wq[4]*cq + wq[5]*rq;
            const float h2q = wq[6]*lq + wq[7]*cq + wq[8]*rq;
            const float lk = s1[r][x], ck = s1[r][x + 1], rk = s1[r][x + 2];
            const float h0k = wk[0]*lk + wk[1]*ck + wk[2]*rk;
            const float h1k = wk[3]*lk + wk[4]*ck + wk[5]*rk;
            const float h2k = wk[6]*lk + wk[7]*ck + wk[8]*rk;
            Aq += h2q; Ak += h2k;
            if (r >= 2) {
                const int o = r - 2;
                const float prod = (Aq + bq) * (Ak + bk);
                const bf16 hv = __float2bfloat16(prod);
                oh[o * WW] = hv;
                ol[o * WW] = __float2bfloat16(prod - __bfloat162float(hv));
            }
            Aq = Bq + h1q; Bq = h0q;
            Ak = Bk + h1k; Bk = h0k;
        }
    } else {
        const int cv = t - 64;
        const float* pv = qkv + ((size_t)b * 192 + 128 + cv) * HW;
        #pragma unroll
        for (int r = 0; r < 18; r++) {
            const int yy = y0 - 1 + r;
            s0[r][x + 1] = (yy >= 0 && yy < HH) ? __ldg(pv + yy * WW + x) : 0.f;
        }
        if (x < 2) {
            const int col = x ? 129 : 0;
            #pragma unroll
            for (int r = 0; r < 18; r++) s0[r][col] = 0.f;
        }
        __syncthreads();

        float wv[9];
        #pragma unroll
        for (int i = 0; i < 9; i++) wv[i] = __ldg(&w[(128 + cv) * 9 + i]);
        const float bv = __ldg(&bias[128 + cv]);

        float* ov = vout + ((size_t)b * 64 + cv) * HW + (size_t)y0 * WW + x;
        float A = 0.f, Bv = 0.f;
        #pragma unroll
        for (int r = 0; r < 18; r++) {
            const float lv = s0[r][x], cvv = s0[r][x + 1], rv = s0[r][x + 2];
            const float h0 = wv[0]*lv + wv[1]*cvv + wv[2]*rv;
            const float h1 = wv[3]*lv + wv[4]*cvv + wv[5]*rv;
            const float h2 = wv[6]*lv + wv[7]*cvv + wv[8]*rv;
            A += h2;
            if (r >= 2) ov[(r - 2) * WW] = A + bv;
            A = Bv + h1; Bv = h0;
        }
    }
}

// ---------------- kv = Wkv @ xp + bkv (SIMT with smem W) ---------------------
__global__ void __launch_bounds__(256) kv_simt(
    const float* __restrict__ xp, const float* __restrict__ Wkv,
    const float* __restrict__ bkv, float* __restrict__ kvout)
{
    __shared__ float ws[32][128];
    const int oc0 = (blockIdx.x & 3) * 32;
    const int b   = blockIdx.x >> 2;
    const int tid = threadIdx.x;

    for (int i = tid; i < 32 * 128; i += 256)
        ws[i >> 7][i & 127] = __ldg(&Wkv[(oc0 + (i >> 7)) * 128 + (i & 127)]);
    __syncthreads();

    const float* xpb = xp + (size_t)b * 128 * 256 + tid;
    float xr[128];
    #pragma unroll 16
    for (int c = 0; c < 128; c++) xr[c] = __ldg(xpb + c * 256);

    #pragma unroll 4
    for (int o = 0; o < 32; o++) {
        float acc = __ldg(&bkv[oc0 + o]);
        #pragma unroll 16
        for (int c = 0; c < 128; c++) acc += ws[o][c] * xr[c];
        kvout[((size_t)b * 128 + oc0 + o) * 256 + tid] = acc;
    }
}

// ---------------- low-freq softmax attention (2 px/thread) -------------------
__global__ void __launch_bounds__(128) lowfreq_attn(
    const float* __restrict__ qg, const float* __restrict__ kv,
    bf16* __restrict__ ch, bf16* __restrict__ cl)
{
    const int b = blockIdx.z, h = blockIdx.y;
    const int p = blockIdx.x * 256 + threadIdx.x;

    __shared__ __align__(16) u64 ks2[256][8];
    __shared__ __align__(16) u64 vs2[256][8];

    const float* kvb = kv + (size_t)b * 128 * 256;
    for (int i = threadIdx.x; i < 2048; i += 128) {
        const int d2 = i >> 8, m = i & 255;
        ks2[m][d2] = pack2(kvb[(h * 16 + 2 * d2) * 256 + m],
                           kvb[(h * 16 + 2 * d2 + 1) * 256 + m]);
        vs2[m][d2] = pack2(kvb[(64 + h * 16 + 2 * d2) * 256 + m],
                           kvb[(64 + h * 16 + 2 * d2 + 1) * 256 + m]);
    }
    __syncthreads();

    u64 qa[8], qb[8];
    #pragma unroll
    for (int d2 = 0; d2 < 8; d2++) {
        const size_t base = (size_t)b * 64 * HW + (size_t)(h * 16 + 2 * d2) * HW + p;
        qa[d2] = pack2(0.25f * __ldg(&qg[base]),       0.25f * __ldg(&qg[base + HW]));
        qb[d2] = pack2(0.25f * __ldg(&qg[base + 128]), 0.25f * __ldg(&qg[base + HW + 128]));
    }

    float suma = 0.f, sumb = 0.f;
    u64 acca[8], accb[8];
    #pragma unroll
    for (int d2 = 0; d2 < 8; d2++) { acca[d2] = 0ull; accb[d2] = 0ull; }

    for (int m = 0; m < 256; m++) {
        u64 sa = 0ull, sb = 0ull;
        #pragma unroll
        for (int d2 = 0; d2 < 8; d2++) {
            const u64 kk = ks2[m][d2];
            sa = ffma2(qa[d2], kk, sa);
            sb = ffma2(qb[d2], kk, sb);
        }
        float a0, a1, b0, b1;
        unpack2(sa, a0, a1); unpack2(sb, b0, b1);
        const float ea = __expf(a0 + a1);
        const float eb = __expf(b0 + b1);
        suma += ea; sumb += eb;
        const u64 ea2 = pack2(ea, ea), eb2 = pack2(eb, eb);
        #pragma unroll
        for (int d2 = 0; d2 < 8; d2++) {
            const u64 vv = vs2[m][d2];
            acca[d2] = ffma2(ea2, vv, acca[d2]);
            accb[d2] = ffma2(eb2, vv, accb[d2]);
        }
    }

    const float inva = 1.f / suma, invb = 1.f / sumb;
    #pragma unroll
    for (int d2 = 0; d2 < 8; d2++) {
        float lo, hi;
        unpack2(acca[d2], lo, hi);
        const size_t base = ((size_t)b * 128 + 64 + h * 16 + 2 * d2) * HW + p;
        split1(lo * inva, ch, cl, base);
        split1(hi * inva, ch, cl, base + HW);
        unpack2(accb[d2], lo, hi);
        split1(lo * invb, ch, cl, base + 128);
        split1(hi * invb, ch, cl, base + HW + 128);
    }
}

// ---------------- launch -----------------------------------------------------
extern "C" void kernel_launch(void* const* d_in, const int* in_sizes, int n_in,
                              void* d_out, int out_size)
{
    const float* x     = (const float*)d_in[0];
    const float* Wqkv  = (const float*)d_in[1];
    const float* bqkv  = (const float*)d_in[2];
    const float* Wdw   = (const float*)d_in[3];
    const float* bdw   = (const float*)d_in[4];
    const float* Wa1   = (const float*)d_in[5];
    const float* ba1   = (const float*)d_in[6];
    const float* Wa2   = (const float*)d_in[7];
    const float* ba2   = (const float*)d_in[8];
    const float* Wq    = (const float*)d_in[9];
    const float* bq    = (const float*)d_in[10];
    const float* Wkv   = (const float*)d_in[11];
    const float* bkv   = (const float*)d_in[12];
    const float* Wproj = (const float*)d_in[13];
    const float* bproj = (const float*)d_in[14];
    float* out = (float*)d_out;

    float *qkv, *v, *qg, *kv, *xp, *b1;
    bf16 *xh, *xl, *qkh, *qkl, *ch, *cl;
    bf16 *w1h, *w1l, *wph, *wpl;
    cudaGetSymbolAddress((void**)&qkv, g_qkv);
    cudaGetSymbolAddress((void**)&v,   g_v);
    cudaGetSymbolAddress((void**)&qg,  g_qg);
    cudaGetSymbolAddress((void**)&kv,  g_kv);
    cudaGetSymbolAddress((void**)&xp,  g_xp);
    cudaGetSymbolAddress((void**)&b1,  g_b1);
    cudaGetSymbolAddress((void**)&xh,  g_xh);
    cudaGetSymbolAddress((void**)&xl,  g_xl);
    cudaGetSymbolAddress((void**)&qkh, g_qkh);
    cudaGetSymbolAddress((void**)&qkl, g_qkl);
    cudaGetSymbolAddress((void**)&ch,  g_ch);
    cudaGetSymbolAddress((void**)&cl,  g_cl);
    cudaGetSymbolAddress((void**)&w1h, g_w1h);
    cudaGetSymbolAddress((void**)&w1l, g_w1l);
    cudaGetSymbolAddress((void**)&wph, g_wph);
    cudaGetSymbolAddress((void**)&wpl, g_wpl);

    cudaFuncSetAttribute(gemm_bf16<true>,
                         cudaFuncAttributeMaxDynamicSharedMemorySize, SMEM_BYTES);
    cudaFuncSetAttribute(gemm_bf16<false>,
                         cudaFuncAttributeMaxDynamicSharedMemorySize, SMEM_BYTES);
    cudaFuncSetAttribute(fused_a1a2,
                         cudaFuncAttributeMaxDynamicSharedMemorySize, F2SMEM);

    static cudaStream_t s1 = nullptr;
    static cudaEvent_t eS = nullptr, e0 = nullptr, e1 = nullptr,
                       e2 = nullptr, e3 = nullptr;
    if (!s1) {
        cudaStreamCreateWithFlags(&s1, cudaStreamNonBlocking);
        cudaEventCreateWithFlags(&eS, cudaEventDisableTiming);
        cudaEventCreateWithFlags(&e0, cudaEventDisableTiming);
        cudaEventCreateWithFlags(&e1, cudaEventDisableTiming);
        cudaEventCreateWithFlags(&e2, cudaEventDisableTiming);
        cudaEventCreateWithFlags(&e3, cudaEventDisableTiming);
    }

    // fork s1 from the capturing stream BEFORE any s1 work (capture rule)
    cudaEventRecord(eS, 0);
    cudaStreamWaitEvent(s1, eS, 0);

    // 0) weight prep on side stream; x split/pool on main (concurrent)
    prep_weights<<<225, 256, 0, s1>>>(Wqkv, Wq, Wa1, Wa2, Wproj, bqkv, bq);
    cudaEventRecord(e0, s1);
    cvtpool<<<NB * 128, 256>>>(x, xh, xl, xp);
    cudaEventRecord(e1, 0);

    // 1) fused qkv+qg GEMM (main; needs weights + xh/xl)
    cudaStreamWaitEvent(0, e0, 0);
    gemm_bf16<true><<<dim3(4, HW / 256, NB), 256, SMEM_BYTES>>>(
        xh, xl, w1h, w1l, b1, 128, HW,
        qkv, 192 * HW, qg, 64 * HW, 192);
    cudaEventRecord(e2, 0);

    // side branch: kv then attention (overlaps dwconv + fused)
    cudaStreamWaitEvent(s1, e1, 0);
    kv_simt<<<NB * 4, 256, 0, s1>>>(xp, Wkv, bkv, kv);
    cudaStreamWaitEvent(s1, e2, 0);
    lowfreq_attn<<<dim3(HW / 256, 4, NB), 128, 0, s1>>>(qg, kv, ch, cl);
    cudaEventRecord(e3, s1);

    // 2) depthwise 3x3 with q*k fusion (main)
    dwconv_qk<<<dim3(1, 8, NB * 128), 128>>>(qkv, Wdw, bdw, qkh, qkl, v);

    // 3+4) fused a1 -> swish -> a2 -> tanh*v (main) -> cat planes [0,64)
    fused_a1a2<<<dim3(HW / 128, NB), 256, F2SMEM>>>(qkh, qkl, ba1, ba2, v, ch, cl);

    // join, then 5) out = Wproj @ cat
    cudaStreamWaitEvent(0, e3, 0);
    gemm_bf16<false><<<dim3(2, HW / 256, NB), 256, SMEM_BYTES>>>(
        ch, cl, wph, wpl, bproj, 128, HW,
        out, 128 * HW, nullptr, 0, 0);
}

// round 11
// speedup vs baseline: 1.0168x; 1.0168x over previous
#include <cuda_runtime.h>
#include <cuda_bf16.h>
#include <math.h>

#define HW 16384
#define HH 128
#define WW 128
#define NB 4

typedef unsigned long long u64;
typedef unsigned int u32;
typedef __nv_bfloat16 bf16;

// ---------------- f32x2 helpers (attention) ---------------------------------
__device__ __forceinline__ u64 pack2(float lo, float hi) {
    u64 r; asm("mov.b64 %0,{%1,%2};" : "=l"(r) : "f"(lo), "f"(hi)); return r;
}
__device__ __forceinline__ void unpack2(u64 v, float& lo, float& hi) {
    asm("mov.b64 {%0,%1},%2;" : "=f"(lo), "=f"(hi) : "l"(v));
}
__device__ __forceinline__ u64 ffma2(u64 a, u64 b, u64 c) {
    u64 r; asm("fma.rn.f32x2 %0,%1,%2,%3;" : "=l"(r) : "l"(a), "l"(b), "l"(c)); return r;
}

// ---------------- scratch ----------------------------------------------------
__device__ __align__(256) float g_qkv [NB * 192 * HW];
__device__ __align__(256) float g_v   [NB * 64  * HW];
__device__ __align__(256) float g_qg  [NB * 64  * HW];
__device__ __align__(256) float g_kv  [NB * 128 * 256];
__device__ __align__(256) float g_xp  [NB * 128 * 256];
__device__ __align__(256) bf16  g_xh  [NB * 128 * HW];
__device__ __align__(256) bf16  g_xl  [NB * 128 * HW];
__device__ __align__(256) bf16  g_qkh [NB * 64 * HW];
__device__ __align__(256) bf16  g_qkl [NB * 64 * HW];
__device__ __align__(256) bf16  g_ch  [NB * 128 * HW];
__device__ __align__(256) bf16  g_cl  [NB * 128 * HW];
__device__ __align__(256) bf16  g_w1h [256 * 128];
__device__ __align__(256) bf16  g_w1l [256 * 128];
__device__ __align__(256) bf16  g_wa1h[64 * 64];
__device__ __align__(256) bf16  g_wa1l[64 * 64];
__device__ __align__(256) bf16  g_wa2h[64 * 64];
__device__ __align__(256) bf16  g_wa2l[64 * 64];
__device__ __align__(256) bf16  g_wph [128 * 128];
__device__ __align__(256) bf16  g_wpl [128 * 128];
__device__ __align__(256) float g_b1  [256];

// ---------------- mma / cp.async helpers ------------------------------------
__device__ __forceinline__ u32 smem_u32(const void* p) {
    u32 a;
    asm("{ .reg .u64 t; cvta.to.shared.u64 t, %1; cvt.u32.u64 %0, t; }"
        : "=r"(a) : "l"(p));
    return a;
}
__device__ __forceinline__ void ldm_x4(u32 a, u32& r0, u32& r1, u32& r2, u32& r3) {
    asm volatile("ldmatrix.sync.aligned.m8n8.x4.shared.b16 {%0,%1,%2,%3},[%4];"
                 : "=r"(r0), "=r"(r1), "=r"(r2), "=r"(r3) : "r"(a));
}
__device__ __forceinline__ void ldm_x4t(u32 a, u32& r0, u32& r1, u32& r2, u32& r3) {
    asm volatile("ldmatrix.sync.aligned.m8n8.x4.trans.shared.b16 {%0,%1,%2,%3},[%4];"
                 : "=r"(r0), "=r"(r1), "=r"(r2), "=r"(r3) : "r"(a));
}
__device__ __forceinline__ void mma_bf16(float* c, const u32* a, u32 b0, u32 b1) {
    asm volatile(
        "mma.sync.aligned.m16n8k16.row.col.f32.bf16.bf16.f32 "
        "{%0,%1,%2,%3},{%4,%5,%6,%7},{%8,%9},{%0,%1,%2,%3};"
        : "+f"(c[0]), "+f"(c[1]), "+f"(c[2]), "+f"(c[3])
        : "r"(a[0]), "r"(a[1]), "r"(a[2]), "r"(a[3]), "r"(b0), "r"(b1));
}
__device__ __forceinline__ void cpa16(u32 d, const void* s) {
    asm volatile("cp.async.cg.shared.global [%0],[%1],16;" :: "r"(d), "l"(s));
}
__device__ __forceinline__ void cp_commit() {
    asm volatile("cp.async.commit_group;" ::: "memory");
}
template<int N> __device__ __forceinline__ void cp_wait() {
    asm volatile("cp.async.wait_group %0;" :: "n"(N) : "memory");
}
__device__ __forceinline__ void split2(float x0, float x1, u32& h, u32& l) {
    bf16 h0 = __float2bfloat16(x0);
    bf16 h1 = __float2bfloat16(x1);
    float r0 = x0 - __bfloat162float(h0);
    float r1 = x1 - __bfloat162float(h1);
    __nv_bfloat162 hp; hp.x = h0; hp.y = h1;
    __nv_bfloat162 lp; lp.x = __float2bfloat16(r0); lp.y = __float2bfloat16(r1);
    h = *reinterpret_cast<u32*>(&hp);
    l = *reinterpret_cast<u32*>(&lp);
}
__device__ __forceinline__ void split1(float x, bf16* hd, bf16* ld, size_t o) {
    bf16 h = __float2bfloat16(x);
    hd[o] = h;
    ld[o] = __float2bfloat16(x - __bfloat162float(h));
}

// ---------------- GEMM geometry ----------------------------------------------
#define APITCH 40
#define BPITCH 264
#define APB (64 * APITCH * 2)
#define BPB (32 * BPITCH * 2)
#define SMEM_BYTES (4 * APB + 4 * BPB)

// ---------------- generic bf16-split tensor-core GEMM -----------------------
// grid = (oc_tiles, px_tiles, batch): oc fastest so consecutive blocks share
// the same B (X) tile through L2.
template<bool DUAL>
__global__ void __launch_bounds__(256, 2) gemm_bf16(
    const bf16* __restrict__ Xh, const bf16* __restrict__ Xl,
    const bf16* __restrict__ Wh, const bf16* __restrict__ Wl,
    const float* __restrict__ bias, int IC, int NPIX,
    float* dstf, int dstf_stride,
    float* dstf2, int dst2_stride, int oc_split)
{
    extern __shared__ __align__(16) char sm[];
    const int tid = threadIdx.x;
    const int lane = tid & 31, warp = tid >> 5;
    const int oc0 = blockIdx.x * 64;
    const int px0 = blockIdx.y * 256;
    const int b   = blockIdx.z;
    const u32 smb = smem_u32(sm);

    const bf16* Xhb = Xh + (size_t)b * IC * NPIX;
    const bf16* Xlb = Xl + (size_t)b * IC * NPIX;

    const int ar = tid >> 2, ac = (tid & 3) * 8;
    const int bc = (tid & 31) * 8, br0 = tid >> 5;
    const int nk = IC >> 5;

    float c[4][4][4];
    #pragma unroll
    for (int i = 0; i < 4; i++)
        #pragma unroll
        for (int j = 0; j < 4; j++)
            #pragma unroll
            for (int q = 0; q < 4; q++) c[i][j][q] = 0.f;

    auto issue = [&](int it) {
        const int st = it & 1;
        const int k0 = it << 5;
        u32 aD = smb + st * 2 * APB + (u32)(ar * APITCH + ac) * 2;
        const size_t aO = (size_t)(oc0 + ar) * IC + k0 + ac;
        cpa16(aD, Wh + aO);
        cpa16(aD + APB, Wl + aO);
        const u32 bBase = smb + 4 * APB + st * 2 * BPB;
        #pragma unroll
        for (int i = 0; i < 4; i++) {
            const int brr = br0 + i * 8;
            u32 bD = bBase + (u32)(brr * BPITCH + bc) * 2;
            const size_t bO = (size_t)(k0 + brr) * NPIX + px0 + bc;
            cpa16(bD, Xhb + bO);
            cpa16(bD + BPB, Xlb + bO);
        }
        cp_commit();
    };

    issue(0);

    const int grp = lane >> 3, lr = lane & 7;
    const int r8  = (grp & 1) * 8 + lr;
    const int kh8 = (grp >> 1) * 8;
    const int wn32 = warp * 32;

    for (int it = 0; it < nk; it++) {
        if (it + 1 < nk) { issue(it + 1); cp_wait<1>(); }
        else             { cp_wait<0>(); }
        __syncthreads();
        const int st = it & 1;
        const u32 aHi = smb + st * 2 * APB, aLo = aHi + APB;
        const u32 bHi = smb + 4 * APB + st * 2 * BPB, bLo = bHi + BPB;
        #pragma unroll
        for (int ks = 0; ks < 2; ks++) {
            u32 bh[2][4], bl[2][4];
            #pragma unroll
            for (int g = 0; g < 2; g++) {
                const u32 off = (u32)((ks * 16 + r8) * BPITCH + wn32 + g * 16 + kh8) * 2;
                ldm_x4t(bHi + off, bh[g][0], bh[g][1], bh[g][2], bh[g][3]);
                ldm_x4t(bLo + off, bl[g][0], bl[g][1], bl[g][2], bl[g][3]);
            }
            #pragma unroll
            for (int mi = 0; mi < 4; mi++) {
                u32 ah[4], al[4];
                const u32 aoff = (u32)((mi * 16 + r8) * APITCH + ks * 16 + kh8) * 2;
                ldm_x4(aHi + aoff, ah[0], ah[1], ah[2], ah[3]);
                ldm_x4(aLo + aoff, al[0], al[1], al[2], al[3]);
                #pragma unroll
                for (int nj = 0; nj < 4; nj++) {
                    const int g = nj >> 1, s2 = nj & 1;
                    mma_bf16(c[mi][nj], ah, bh[g][2 * s2], bh[g][2 * s2 + 1]);
                    mma_bf16(c[mi][nj], ah, bl[g][2 * s2], bl[g][2 * s2 + 1]);
                    mma_bf16(c[mi][nj], al, bh[g][2 * s2], bh[g][2 * s2 + 1]);
                }
            }
        }
        __syncthreads();
    }

    // ---- epilogue
    const int r4 = lane >> 2, c2 = (lane & 3) * 2;
    #pragma unroll
    for (int mi = 0; mi < 4; mi++) {
        #pragma unroll
        for (int h = 0; h < 2; h++) {
            const int oc = oc0 + mi * 16 + h * 8 + r4;
            const float bv = bias[oc];
            #pragma unroll
            for (int nj = 0; nj < 4; nj++) {
                const int px = px0 + wn32 + nj * 8 + c2;
                const float v0 = c[mi][nj][h * 2]     + bv;
                const float v1 = c[mi][nj][h * 2 + 1] + bv;
                if (DUAL) {
                    if (oc < oc_split)
                        *reinterpret_cast<float2*>(dstf + (size_t)b * dstf_stride
                            + (size_t)oc * NPIX + px) = make_float2(v0, v1);
                    else
                        *reinterpret_cast<float2*>(dstf2 + (size_t)b * dst2_stride
                            + (size_t)(oc - oc_split) * NPIX + px) = make_float2(v0, v1);
                } else {
                    *reinterpret_cast<float2*>(dstf + (size_t)b * dstf_stride
                        + (size_t)oc * NPIX + px) = make_float2(v0, v1);
                }
            }
        }
    }
}

// ---------------- fused a1->swish->a2->tanh*v, 128-px tiles -----------------
#define F2PITCH 136
#define F2STG (32 * F2PITCH * 2)
#define F2W1H (4 * F2STG)
#define F2W1L (F2W1H + 64 * 72 * 2)
#define F2W2H (F2W1L + 64 * 72 * 2)
#define F2W2L (F2W2H + 64 * 72 * 2)
#define F2SMEM (F2W2L + 64 * 72 * 2)

__global__ void __launch_bounds__(256, 3) fused_a1a2(
    const bf16* __restrict__ qkh, const bf16* __restrict__ qkl,
    const float* __restrict__ ba1, const float* __restrict__ ba2,
    const float* __restrict__ vsrc,
    bf16* __restrict__ ch, bf16* __restrict__ cl)
{
    extern __shared__ __align__(16) char sm[];
    const int tid = threadIdx.x;
    const int lane = tid & 31, warp = tid >> 5;
    const int px0 = blockIdx.x * 128;
    const int b   = blockIdx.y;
    const u32 smb = smem_u32(sm);

    const bf16* qkhb = qkh + (size_t)b * 64 * HW + px0;
    const bf16* qklb = qkl + (size_t)b * 64 * HW + px0;

    {
        const int r = tid >> 2;
        const int sb = (tid & 3) * 32;
        const size_t go = (size_t)r * 64 + (tid & 3) * 16;
        const u32 so = (u32)(r * 72) * 2 + sb;
        cpa16(smb + F2W1H + so, g_wa1h + go); cpa16(smb + F2W1H + so + 16, g_wa1h + go + 8);
        cpa16(smb + F2W1L + so, g_wa1l + go); cpa16(smb + F2W1L + so + 16, g_wa1l + go + 8);
        cpa16(smb + F2W2H + so, g_wa2h + go); cpa16(smb + F2W2H + so + 16, g_wa2h + go + 8);
        cpa16(smb + F2W2L + so, g_wa2l + go); cpa16(smb + F2W2L + so + 16, g_wa2l + go + 8);
    }
    const int bc = (tid & 15) * 8, br0 = tid >> 4;
    auto issueB = [&](int chunk) {
        const u32 base = smb + chunk * 2 * F2STG;
        #pragma unroll
        for (int i = 0; i < 2; i++) {
            const int brr = br0 + i * 16;
            const u32 d = base + (u32)(brr * F2PITCH + bc) * 2;
            const size_t o = (size_t)(chunk * 32 + brr) * HW + bc;
            cpa16(d, qkhb + o);
            cpa16(d + F2STG, qklb + o);
        }
        cp_commit();
    };
    issueB(0);
    issueB(1);

    const int grp = lane >> 3, lr = lane & 7;
    const int r8  = (grp & 1) * 8 + lr;
    const int kh8 = (grp >> 1) * 8;
    const int wn16 = warp * 16;
    const int r4 = lane >> 2, c2 = (lane & 3) * 2;

    float c[4][2][4];
    #pragma unroll
    for (int i = 0; i < 4; i++)
        #pragma unroll
        for (int j = 0; j < 2; j++)
            #pragma unroll
            for (int q = 0; q < 4; q++) c[i][j][q] = 0.f;

    for (int it = 0; it < 2; it++) {
        if (it == 0) cp_wait<1>(); else cp_wait<0>();
        __syncthreads();
        const u32 bHi = smb + it * 2 * F2STG, bLo = bHi + F2STG;
        #pragma unroll
        for (int ks = 0; ks < 2; ks++) {
            u32 bh[4], bl[4];
            const u32 off = (u32)((ks * 16 + r8) * F2PITCH + wn16 + kh8) * 2;
            ldm_x4t(bHi + off, bh[0], bh[1], bh[2], bh[3]);
            ldm_x4t(bLo + off, bl[0], bl[1], bl[2], bl[3]);
            #pragma unroll
            for (int mi = 0; mi < 4; mi++) {
                u32 ah[4], al[4];
                const u32 aoff = (u32)((mi * 16 + r8) * 72 + it * 32 + ks * 16 + kh8) * 2;
                ldm_x4(smb + F2W1H + aoff, ah[0], ah[1], ah[2], ah[3]);
                ldm_x4(smb + F2W1L + aoff, al[0], al[1], al[2], al[3]);
                #pragma unroll
                for (int nj = 0; nj < 2; nj++) {
                    mma_bf16(c[mi][nj], ah, bh[2 * nj], bh[2 * nj + 1]);
                    mma_bf16(c[mi][nj], ah, bl[2 * nj], bl[2 * nj + 1]);
                    mma_bf16(c[mi][nj], al, bh[2 * nj], bh[2 * nj + 1]);
                }
            }
        }
    }
    __syncthreads();

    #pragma unroll
    for (int mi = 0; mi < 4; mi++) {
        #pragma unroll
        for (int h = 0; h < 2; h++) {
            const int oc = mi * 16 + h * 8 + r4;
            const float bv = __ldg(&ba1[oc]);
            const u32 halfb = (oc & 32) ? 2u * F2STG : 0u;
            #pragma unroll
            for (int nj = 0; nj < 2; nj++) {
                float v0 = c[mi][nj][h * 2]     + bv;
                float v1 = c[mi][nj][h * 2 + 1] + bv;
                v0 = v0 / (1.f + __expf(-v0));
                v1 = v1 / (1.f + __expf(-v1));
                u32 hp, lp; split2(v0, v1, hp, lp);
                const u32 off = (u32)((oc & 31) * F2PITCH + wn16 + nj * 8 + c2) * 2;
                *reinterpret_cast<u32*>(sm + halfb + off)         = hp;
                *reinterpret_cast<u32*>(sm + halfb + F2STG + off) = lp;
            }
        }
    }
    __syncthreads();

    #pragma unroll
    for (int i = 0; i < 4; i++)
        #pragma unroll
        for (int j = 0; j < 2; j++)
            #pragma unroll
            for (int q = 0; q < 4; q++) c[i][j][q] = 0.f;

    #pragma unroll
    for (int it = 0; it < 2; it++) {
        const u32 bHi = smb + it * 2 * F2STG, bLo = bHi + F2STG;
        #pragma unroll
        for (int ks = 0; ks < 2; ks++) {
            u32 bh[4], bl[4];
            const u32 off = (u32)((ks * 16 + r8) * F2PITCH + wn16 + kh8) * 2;
            ldm_x4t(bHi + off, bh[0], bh[1], bh[2], bh[3]);
            ldm_x4t(bLo + off, bl[0], bl[1], bl[2], bl[3]);
            #pragma unroll
            for (int mi = 0; mi < 4; mi++) {
                u32 ah[4], al[4];
                const u32 aoff = (u32)((mi * 16 + r8) * 72 + it * 32 + ks * 16 + kh8) * 2;
                ldm_x4(smb + F2W2H + aoff, ah[0], ah[1], ah[2], ah[3]);
                ldm_x4(smb + F2W2L + aoff, al[0], al[1], al[2], al[3]);
                #pragma unroll
                for (int nj = 0; nj < 2; nj++) {
                    mma_bf16(c[mi][nj], ah, bh[2 * nj], bh[2 * nj + 1]);
                    mma_bf16(c[mi][nj], ah, bl[2 * nj], bl[2 * nj + 1]);
                    mma_bf16(c[mi][nj], al, bh[2 * nj], bh[2 * nj + 1]);
                }
            }
        }
    }

    #pragma unroll
    for (int mi = 0; mi < 4; mi++) {
        #pragma unroll
        for (int h = 0; h < 2; h++) {
            const int oc = mi * 16 + h * 8 + r4;
            const float bv = __ldg(&ba2[oc]);
            #pragma unroll
            for (int nj = 0; nj < 2; nj++) {
                const int px = px0 + wn16 + nj * 8 + c2;
                const float* vr = vsrc + ((size_t)b * 64 + oc) * HW + px;
                float v0 = tanhf((c[mi][nj][h * 2]     + bv) * 0.25f) * __ldg(vr);
                float v1 = tanhf((c[mi][nj][h * 2 + 1] + bv) * 0.25f) * __ldg(vr + 1);
                u32 hp, lp; split2(v0, v1, hp, lp);
                const size_t o = ((size_t)b * 128 + oc) * HW + px;
                *reinterpret_cast<u32*>(ch + o) = hp;
                *reinterpret_cast<u32*>(cl + o) = lp;
            }
        }
    }
}

// ---------------- weight prep ------------------------------------------------
__global__ void prep_weights(
    const float* __restrict__ Wqkv, const float* __restrict__ Wq,
    const float* __restrict__ Wa1, const float* __restrict__ Wa2,
    const float* __restrict__ Wproj,
    const float* __restrict__ bqkv, const float* __restrict__ bq)
{
    const int i = blockIdx.x * 256 + threadIdx.x;
    if (i < 32768) {
        float v = (i < 24576) ? Wqkv[i] : Wq[i - 24576];
        split1(v, g_w1h, g_w1l, i);
    } else if (i < 36864) {
        split1(Wa1[i - 32768], g_wa1h, g_wa1l, i - 32768);
    } else if (i < 40960) {
        split1(Wa2[i - 36864], g_wa2h, g_wa2l, i - 36864);
    } else if (i < 57344) {
        split1(Wproj[i - 40960], g_wph, g_wpl, i - 40960);
    } else if (i < 57600) {
        const int j = i - 57344;
        g_b1[j] = (j < 192) ? bqkv[j] : bq[j - 192];
    }
}

// ---------------- x -> hi/lo bf16 + 8x8 avgpool (one pass) -------------------
__global__ void __launch_bounds__(256) cvtpool(
    const float* __restrict__ x, bf16* __restrict__ xh, bf16* __restrict__ xl,
    float* __restrict__ xp)
{
    const int plane = blockIdx.x;
    const int t = threadIdx.x;
    const int wi = t >> 4, wj = t & 15;
    const float* sp = x + (size_t)plane * HW + (wi * 8) * WW + wj * 8;
    bf16* oh = xh + (size_t)plane * HW + (wi * 8) * WW + wj * 8;
    bf16* ol = xl + (size_t)plane * HW + (wi * 8) * WW + wj * 8;

    float s = 0.f;
    #pragma unroll
    for (int r = 0; r < 8; r++) {
        const float4 a = *reinterpret_cast<const float4*>(sp + r * WW);
        const float4 b = *reinterpret_cast<const float4*>(sp + r * WW + 4);
        s += a.x + a.y + a.z + a.w + b.x + b.y + b.z + b.w;
        u32 h0, l0, h1, l1, h2, l2, h3, l3;
        split2(a.x, a.y, h0, l0); split2(a.z, a.w, h1, l1);
        split2(b.x, b.y, h2, l2); split2(b.z, b.w, h3, l3);
        *reinterpret_cast<uint4*>(oh + r * WW) = make_uint4(h0, h1, h2, h3);
        *reinterpret_cast<uint4*>(ol + r * WW) = make_uint4(l0, l1, l2, l3);
    }
    xp[(size_t)plane * 256 + wi * 16 + wj] = s * (1.f / 64.f);
}

// ---------------- depthwise 3x3, smem-tiled rolling stencil -----------------
__global__ void __launch_bounds__(128) dwconv_qk(
    const float* __restrict__ qkv, const float* __restrict__ w,
    const float* __restrict__ bias,
    bf16* __restrict__ qkh, bf16* __restrict__ qkl,
    float* __restrict__ vout)
{
    const int z = blockIdx.z;
    const int b = z >> 7, t = z & 127;
    const int x = threadIdx.x;
    const int y0 = blockIdx.y * 16;

    __shared__ float s0[18][136];
    __shared__ float s1[18][136];

    if (t < 64) {
        const float* pq = qkv + ((size_t)b * 192 + t) * HW;
        const float* pk = qkv + ((size_t)b * 192 + 64 + t) * HW;
        #pragma unroll
        for (int r = 0; r < 18; r++) {
            const int yy = y0 - 1 + r;
            const bool ok = (yy >= 0) && (yy < HH);
            s0[r][x + 1] = ok ? __ldg(pq + yy * WW + x) : 0.f;
            s1[r][x + 1] = ok ? __ldg(pk + yy * WW + x) : 0.f;
        }
        if (x < 2) {
            const int col = x ? 129 : 0;
            #pragma unroll
            for (int r = 0; r < 18; r++) { s0[r][col] = 0.f; s1[r][col] = 0.f; }
        }
        __syncthreads();

        float wq[9], wk[9];
        #pragma unroll
        for (int i = 0; i < 9; i++) {
            wq[i] = __ldg(&w[t * 9 + i]);
            wk[i] = __ldg(&w[(64 + t) * 9 + i]);
        }
        const float bq = __ldg(&bias[t]);
        const float bk = __ldg(&bias[64 + t]);

        bf16* oh = qkh + ((size_t)b * 64 + t) * HW + (size_t)y0 * WW + x;
        bf16* ol = qkl + ((size_t)b * 64 + t) * HW + (size_t)y0 * WW + x;

        float Aq = 0.f, Bq = 0.f, Ak = 0.f, Bk = 0.f;
        #pragma unroll
        for (int r = 0; r < 18; r++) {
            const float lq = s0[r][x], cq = s0[r][x + 1], rq = s0[r][x + 2];
            const float h0q = wq[0]*lq + wq[1]*cq + wq[2]*rq;
            const float h1q = wq[3]*lq + wq[4]*cq + wq[5]*rq;
            const float h2q = wq[6]*lq + wq[7]*cq + wq[8]*rq;
            const float lk = s1[r][x], ck = s1[r][x + 1], rk = s1[r][x + 2];
            const float h0k = wk[0]*lk + wk[1]*ck + wk[2]*rk;
            const float h1k = wk[3]*lk + wk[4]*ck + wk[5]*rk;
            const float h2k = wk[6]*lk + wk[7]*ck + wk[8]*rk;
            Aq += h2q; Ak += h2k;
            if (r >= 2) {
                const int o = r - 2;
                const float prod = (Aq + bq) * (Ak + bk);
                const bf16 hv = __float2bfloat16(prod);
                oh[o * WW] = hv;
                ol[o * WW] = __float2bfloat16(prod - __bfloat162float(hv));
            }
            Aq = Bq + h1q; Bq = h0q;
            Ak = Bk + h1k; Bk = h0k;
        }
    } else {
        const int cv = t - 64;
        const float* pv = qkv + ((size_t)b * 192 + 128 + cv) * HW;
        #pragma unroll
        for (int r = 0; r < 18; r++) {
            const int yy = y0 - 1 + r;
            s0[r][x + 1] = (yy >= 0 && yy < HH) ? __ldg(pv + yy * WW + x) : 0.f;
        }
        if (x < 2) {
            const int col = x ? 129 : 0;
            #pragma unroll
            for (int r = 0; r < 18; r++) s0[r][col] = 0.f;
        }
        __syncthreads();

        float wv[9];
        #pragma unroll
        for (int i = 0; i < 9; i++) wv[i] = __ldg(&w[(128 + cv) * 9 + i]);
        const float bv = __ldg(&bias[128 + cv]);

        float* ov = vout + ((size_t)b * 64 + cv) * HW + (size_t)y0 * WW + x;
        float A = 0.f, Bv = 0.f;
        #pragma unroll
        for (int r = 0; r < 18; r++) {
            const float lv = s0[r][x], cvv = s0[r][x + 1], rv = s0[r][x + 2];
            const float h0 = wv[0]*lv + wv[1]*cvv + wv[2]*rv;
            const float h1 = wv[3]*lv + wv[4]*cvv + wv[5]*rv;
            const float h2 = wv[6]*lv + wv[7]*cvv + wv[8]*rv;
            A += h2;
            if (r >= 2) ov[(r - 2) * WW] = A + bv;
            A = Bv + h1; Bv = h0;
        }
    }
}

// ---------------- kv = Wkv @ xp + bkv (SIMT, fp32) — R8 proven version ------
__global__ void __launch_bounds__(256) kv_simt(
    const float* __restrict__ xp, const float* __restrict__ Wkv,
    const float* __restrict__ bkv, float* __restrict__ kvout)
{
    const int idx = blockIdx.x * 256 + threadIdx.x;
    const int p  = idx & 255;
    const int oc = (idx >> 8) & 127;
    const int b  = idx >> 15;
    const float* xpb = xp + (size_t)b * 128 * 256 + p;
    const float* wr  = Wkv + oc * 128;
    float acc = __ldg(&bkv[oc]);
    #pragma unroll 8
    for (int c = 0; c < 128; c++)
        acc += __ldg(wr + c) * __ldg(xpb + c * 256);
    kvout[((size_t)b * 128 + oc) * 256 + p] = acc;
}

// ---------------- low-freq softmax attention (2 px/thread) -------------------
__global__ void __launch_bounds__(128) lowfreq_attn(
    const float* __restrict__ qg, const float* __restrict__ kv,
    bf16* __restrict__ ch, bf16* __restrict__ cl)
{
    const int b = blockIdx.z, h = blockIdx.y;
    const int p = blockIdx.x * 256 + threadIdx.x;

    __shared__ __align__(16) u64 ks2[256][8];
    __shared__ __align__(16) u64 vs2[256][8];

    const float* kvb = kv + (size_t)b * 128 * 256;
    for (int i = threadIdx.x; i < 2048; i += 128) {
        const int d2 = i >> 8, m = i & 255;
        ks2[m][d2] = pack2(kvb[(h * 16 + 2 * d2) * 256 + m],
                           kvb[(h * 16 + 2 * d2 + 1) * 256 + m]);
        vs2[m][d2] = pack2(kvb[(64 + h * 16 + 2 * d2) * 256 + m],
                           kvb[(64 + h * 16 + 2 * d2 + 1) * 256 + m]);
    }
    __syncthreads();

    u64 qa[8], qb[8];
    #pragma unroll
    for (int d2 = 0; d2 < 8; d2++) {
        const size_t base = (size_t)b * 64 * HW + (size_t)(h * 16 + 2 * d2) * HW + p;
        qa[d2] = pack2(0.25f * __ldg(&qg[base]),       0.25f * __ldg(&qg[base + HW]));
        qb[d2] = pack2(0.25f * __ldg(&qg[base + 128]), 0.25f * __ldg(&qg[base + HW + 128]));
    }

    float suma = 0.f, sumb = 0.f;
    u64 acca[8], accb[8];
    #pragma unroll
    for (int d2 = 0; d2 < 8; d2++) { acca[d2] = 0ull; accb[d2] = 0ull; }

    for (int m = 0; m < 256; m++) {
        u64 sa = 0ull, sb = 0ull;
        #pragma unroll
        for (int d2 = 0; d2 < 8; d2++) {
            const u64 kk = ks2[m][d2];
            sa = ffma2(qa[d2], kk, sa);
            sb = ffma2(qb[d2], kk, sb);
        }
        float a0, a1, b0, b1;
        unpack2(sa, a0, a1); unpack2(sb, b0, b1);
        const float ea = __expf(a0 + a1);
        const float eb = __expf(b0 + b1);
        suma += ea; sumb += eb;
        const u64 ea2 = pack2(ea, ea), eb2 = pack2(eb, eb);
        #pragma unroll
        for (int d2 = 0; d2 < 8; d2++) {
            const u64 vv = vs2[m][d2];
            acca[d2] = ffma2(ea2, vv, acca[d2]);
            accb[d2] = ffma2(eb2, vv, accb[d2]);
        }
    }

    const float inva = 1.f / suma, invb = 1.f / sumb;
    #pragma unroll
    for (int d2 = 0; d2 < 8; d2++) {
        float lo, hi;
        unpack2(acca[d2], lo, hi);
        const size_t base = ((size_t)b * 128 + 64 + h * 16 + 2 * d2) * HW + p;
        split1(lo * inva, ch, cl, base);
        split1(hi * inva, ch, cl, base + HW);
        unpack2(accb[d2], lo, hi);
        split1(lo * invb, ch, cl, base + 128);
        split1(hi * invb, ch, cl, base + HW + 128);
    }
}

// ---------------- launch -----------------------------------------------------
extern "C" void kernel_launch(void* const* d_in, const int* in_sizes, int n_in,
                              void* d_out, int out_size)
{
    const float* x     = (const float*)d_in[0];
    const float* Wqkv  = (const float*)d_in[1];
    const float* bqkv  = (const float*)d_in[2];
    const float* Wdw   = (const float*)d_in[3];
    const float* bdw   = (const float*)d_in[4];
    const float* Wa1   = (const float*)d_in[5];
    const float* ba1   = (const float*)d_in[6];
    const float* Wa2   = (const float*)d_in[7];
    const float* ba2   = (const float*)d_in[8];
    const float* Wq    = (const float*)d_in[9];
    const float* bq    = (const float*)d_in[10];
    const float* Wkv   = (const float*)d_in[11];
    const float* bkv   = (const float*)d_in[12];
    const float* Wproj = (const float*)d_in[13];
    const float* bproj = (const float*)d_in[14];
    float* out = (float*)d_out;

    float *qkv, *v, *qg, *kv, *xp, *b1;
    bf16 *xh, *xl, *qkh, *qkl, *ch, *cl;
    bf16 *w1h, *w1l, *wph, *wpl;
    cudaGetSymbolAddress((void**)&qkv, g_qkv);
    cudaGetSymbolAddress((void**)&v,   g_v);
    cudaGetSymbolAddress((void**)&qg,  g_qg);
    cudaGetSymbolAddress((void**)&kv,  g_kv);
    cudaGetSymbolAddress((void**)&xp,  g_xp);
    cudaGetSymbolAddress((void**)&b1,  g_b1);
    cudaGetSymbolAddress((void**)&xh,  g_xh);
    cudaGetSymbolAddress((void**)&xl,  g_xl);
    cudaGetSymbolAddress((void**)&qkh, g_qkh);
    cudaGetSymbolAddress((void**)&qkl, g_qkl);
    cudaGetSymbolAddress((void**)&ch,  g_ch);
    cudaGetSymbolAddress((void**)&cl,  g_cl);
    cudaGetSymbolAddress((void**)&w1h, g_w1h);
    cudaGetSymbolAddress((void**)&w1l, g_w1l);
    cudaGetSymbolAddress((void**)&wph, g_wph);
    cudaGetSymbolAddress((void**)&wpl, g_wpl);

    cudaFuncSetAttribute(gemm_bf16<true>,
                         cudaFuncAttributeMaxDynamicSharedMemorySize, SMEM_BYTES);
    cudaFuncSetAttribute(gemm_bf16<false>,
                         cudaFuncAttributeMaxDynamicSharedMemorySize, SMEM_BYTES);
    cudaFuncSetAttribute(fused_a1a2,
                         cudaFuncAttributeMaxDynamicSharedMemorySize, F2SMEM);

    static cudaStream_t s1 = nullptr;
    static cudaEvent_t eS = nullptr, e0 = nullptr, e1 = nullptr,
                       e2 = nullptr, e3 = nullptr;
    if (!s1) {
        cudaStreamCreateWithFlags(&s1, cudaStreamNonBlocking);
        cudaEventCreateWithFlags(&eS, cudaEventDisableTiming);
        cudaEventCreateWithFlags(&e0, cudaEventDisableTiming);
        cudaEventCreateWithFlags(&e1, cudaEventDisableTiming);
        cudaEventCreateWithFlags(&e2, cudaEventDisableTiming);
        cudaEventCreateWithFlags(&e3, cudaEventDisableTiming);
    }

    // fork s1 from the capturing stream BEFORE any s1 work (capture rule)
    cudaEventRecord(eS, 0);
    cudaStreamWaitEvent(s1, eS, 0);

    // 0) weight prep on side stream; x split/pool on main (concurrent)
    prep_weights<<<225, 256, 0, s1>>>(Wqkv, Wq, Wa1, Wa2, Wproj, bqkv, bq);
    cudaEventRecord(e0, s1);
    cvtpool<<<NB * 128, 256>>>(x, xh, xl, xp);
    cudaEventRecord(e1, 0);

    // 1) fused qkv+qg GEMM (main; needs weights + xh/xl)
    cudaStreamWaitEvent(0, e0, 0);
    gemm_bf16<true><<<dim3(4, HW / 256, NB), 256, SMEM_BYTES>>>(
        xh, xl, w1h, w1l, b1, 128, HW,
        qkv, 192 * HW, qg, 64 * HW, 192);
    cudaEventRecord(e2, 0);

    // side branch: kv then attention (overlaps dwconv + fused)
    cudaStreamWaitEvent(s1, e1, 0);
    kv_simt<<<NB * 128 * 256 / 256, 256, 0, s1>>>(xp, Wkv, bkv, kv);
    cudaStreamWaitEvent(s1, e2, 0);
    lowfreq_attn<<<dim3(HW / 256, 4, NB), 128, 0, s1>>>(qg, kv, ch, cl);
    cudaEventRecord(e3, s1);

    // 2) depthwise 3x3 with q*k fusion (main)
    dwconv_qk<<<dim3(1, 8, NB * 128), 128>>>(qkv, Wdw, bdw, qkh, qkl, v);

    // 3+4) fused a1 -> swish -> a2 -> tanh*v (main) -> cat planes [0,64)
    fused_a1a2<<<dim3(HW / 128, NB), 256, F2SMEM>>>(qkh, qkl, ba1, ba2, v, ch, cl);

    // join, then 5) out = Wproj @ cat
    cudaStreamWaitEvent(0, e3, 0);
    gemm_bf16<false><<<dim3(2, HW / 256, NB), 256, SMEM_BYTES>>>(
        ch, cl, wph, wpl, bproj, 128, HW,
        out, 128 * HW, nullptr, 0, 0);
}

// round 12
// speedup vs baseline: 1.0338x; 1.0167x over previous
#include <cuda_runtime.h>
#include <cuda_bf16.h>
#include <math.h>

#define HW 16384
#define HH 128
#define WW 128
#define NB 4

typedef unsigned long long u64;
typedef unsigned int u32;
typedef __nv_bfloat16 bf16;

// ---------------- f32x2 helpers (attention) ---------------------------------
__device__ __forceinline__ u64 pack2(float lo, float hi) {
    u64 r; asm("mov.b64 %0,{%1,%2};" : "=l"(r) : "f"(lo), "f"(hi)); return r;
}
__device__ __forceinline__ void unpack2(u64 v, float& lo, float& hi) {
    asm("mov.b64 {%0,%1},%2;" : "=f"(lo), "=f"(hi) : "l"(v));
}
__device__ __forceinline__ u64 ffma2(u64 a, u64 b, u64 c) {
    u64 r; asm("fma.rn.f32x2 %0,%1,%2,%3;" : "=l"(r) : "l"(a), "l"(b), "l"(c)); return r;
}

// ---------------- scratch ----------------------------------------------------
__device__ __align__(256) float g_qkv [NB * 192 * HW];
__device__ __align__(256) float g_v   [NB * 64  * HW];
__device__ __align__(256) float g_qg  [NB * 64  * HW];
__device__ __align__(256) float g_kv  [NB * 128 * 256];
__device__ __align__(256) float g_xp  [NB * 128 * 256];
__device__ __align__(256) bf16  g_xh  [NB * 128 * HW];
__device__ __align__(256) bf16  g_xl  [NB * 128 * HW];
__device__ __align__(256) bf16  g_qkh [NB * 64 * HW];
__device__ __align__(256) bf16  g_qkl [NB * 64 * HW];
__device__ __align__(256) bf16  g_ch  [NB * 128 * HW];
__device__ __align__(256) bf16  g_cl  [NB * 128 * HW];
__device__ __align__(256) bf16  g_w1h [256 * 128];
__device__ __align__(256) bf16  g_w1l [256 * 128];
__device__ __align__(256) bf16  g_wa1h[64 * 64];
__device__ __align__(256) bf16  g_wa1l[64 * 64];
__device__ __align__(256) bf16  g_wa2h[64 * 64];
__device__ __align__(256) bf16  g_wa2l[64 * 64];
__device__ __align__(256) bf16  g_wph [128 * 128];
__device__ __align__(256) bf16  g_wpl [128 * 128];
__device__ __align__(256) float g_b1  [256];

// ---------------- mma / cp.async helpers ------------------------------------
__device__ __forceinline__ u32 smem_u32(const void* p) {
    u32 a;
    asm("{ .reg .u64 t; cvta.to.shared.u64 t, %1; cvt.u32.u64 %0, t; }"
        : "=r"(a) : "l"(p));
    return a;
}
__device__ __forceinline__ void ldm_x4(u32 a, u32& r0, u32& r1, u32& r2, u32& r3) {
    asm volatile("ldmatrix.sync.aligned.m8n8.x4.shared.b16 {%0,%1,%2,%3},[%4];"
                 : "=r"(r0), "=r"(r1), "=r"(r2), "=r"(r3) : "r"(a));
}
__device__ __forceinline__ void ldm_x4t(u32 a, u32& r0, u32& r1, u32& r2, u32& r3) {
    asm volatile("ldmatrix.sync.aligned.m8n8.x4.trans.shared.b16 {%0,%1,%2,%3},[%4];"
                 : "=r"(r0), "=r"(r1), "=r"(r2), "=r"(r3) : "r"(a));
}
__device__ __forceinline__ void mma_bf16(float* c, const u32* a, u32 b0, u32 b1) {
    asm volatile(
        "mma.sync.aligned.m16n8k16.row.col.f32.bf16.bf16.f32 "
        "{%0,%1,%2,%3},{%4,%5,%6,%7},{%8,%9},{%0,%1,%2,%3};"
        : "+f"(c[0]), "+f"(c[1]), "+f"(c[2]), "+f"(c[3])
        : "r"(a[0]), "r"(a[1]), "r"(a[2]), "r"(a[3]), "r"(b0), "r"(b1));
}
__device__ __forceinline__ void cpa16(u32 d, const void* s) {
    asm volatile("cp.async.cg.shared.global [%0],[%1],16;" :: "r"(d), "l"(s));
}
__device__ __forceinline__ void cp_commit() {
    asm volatile("cp.async.commit_group;" ::: "memory");
}
template<int N> __device__ __forceinline__ void cp_wait() {
    asm volatile("cp.async.wait_group %0;" :: "n"(N) : "memory");
}
__device__ __forceinline__ void split2(float x0, float x1, u32& h, u32& l) {
    bf16 h0 = __float2bfloat16(x0);
    bf16 h1 = __float2bfloat16(x1);
    float r0 = x0 - __bfloat162float(h0);
    float r1 = x1 - __bfloat162float(h1);
    __nv_bfloat162 hp; hp.x = h0; hp.y = h1;
    __nv_bfloat162 lp; lp.x = __float2bfloat16(r0); lp.y = __float2bfloat16(r1);
    h = *reinterpret_cast<u32*>(&hp);
    l = *reinterpret_cast<u32*>(&lp);
}
__device__ __forceinline__ void split1(float x, bf16* hd, bf16* ld, size_t o) {
    bf16 h = __float2bfloat16(x);
    hd[o] = h;
    ld[o] = __float2bfloat16(x - __bfloat162float(h));
}

// ---------------- GEMM geometry ----------------------------------------------
#define APITCH 40
#define BPITCH 264
#define APB (64 * APITCH * 2)
#define BPB (32 * BPITCH * 2)
#define SMEM_BYTES (4 * APB + 4 * BPB)

// ---------------- generic bf16-split tensor-core GEMM -----------------------
// grid = (px_tiles, oc_tiles, batch) — R8-proven order (px fastest: streaming
// stores within an oc plane across the wave; X stays L2-resident regardless).
template<bool DUAL>
__global__ void __launch_bounds__(256, 2) gemm_bf16(
    const bf16* __restrict__ Xh, const bf16* __restrict__ Xl,
    const bf16* __restrict__ Wh, const bf16* __restrict__ Wl,
    const float* __restrict__ bias, int IC, int NPIX,
    float* dstf, int dstf_stride,
    float* dstf2, int dst2_stride, int oc_split)
{
    extern __shared__ __align__(16) char sm[];
    const int tid = threadIdx.x;
    const int lane = tid & 31, warp = tid >> 5;
    const int px0 = blockIdx.x * 256;
    const int oc0 = blockIdx.y * 64;
    const int b   = blockIdx.z;
    const u32 smb = smem_u32(sm);

    const bf16* Xhb = Xh + (size_t)b * IC * NPIX;
    const bf16* Xlb = Xl + (size_t)b * IC * NPIX;

    const int ar = tid >> 2, ac = (tid & 3) * 8;
    const int bc = (tid & 31) * 8, br0 = tid >> 5;
    const int nk = IC >> 5;

    float c[4][4][4];
    #pragma unroll
    for (int i = 0; i < 4; i++)
        #pragma unroll
        for (int j = 0; j < 4; j++)
            #pragma unroll
            for (int q = 0; q < 4; q++) c[i][j][q] = 0.f;

    auto issue = [&](int it) {
        const int st = it & 1;
        const int k0 = it << 5;
        u32 aD = smb + st * 2 * APB + (u32)(ar * APITCH + ac) * 2;
        const size_t aO = (size_t)(oc0 + ar) * IC + k0 + ac;
        cpa16(aD, Wh + aO);
        cpa16(aD + APB, Wl + aO);
        const u32 bBase = smb + 4 * APB + st * 2 * BPB;
        #pragma unroll
        for (int i = 0; i < 4; i++) {
            const int brr = br0 + i * 8;
            u32 bD = bBase + (u32)(brr * BPITCH + bc) * 2;
            const size_t bO = (size_t)(k0 + brr) * NPIX + px0 + bc;
            cpa16(bD, Xhb + bO);
            cpa16(bD + BPB, Xlb + bO);
        }
        cp_commit();
    };

    issue(0);

    const int grp = lane >> 3, lr = lane & 7;
    const int r8  = (grp & 1) * 8 + lr;
    const int kh8 = (grp >> 1) * 8;
    const int wn32 = warp * 32;

    for (int it = 0; it < nk; it++) {
        if (it + 1 < nk) { issue(it + 1); cp_wait<1>(); }
        else             { cp_wait<0>(); }
        __syncthreads();
        const int st = it & 1;
        const u32 aHi = smb + st * 2 * APB, aLo = aHi + APB;
        const u32 bHi = smb + 4 * APB + st * 2 * BPB, bLo = bHi + BPB;
        #pragma unroll
        for (int ks = 0; ks < 2; ks++) {
            u32 bh[2][4], bl[2][4];
            #pragma unroll
            for (int g = 0; g < 2; g++) {
                const u32 off = (u32)((ks * 16 + r8) * BPITCH + wn32 + g * 16 + kh8) * 2;
                ldm_x4t(bHi + off, bh[g][0], bh[g][1], bh[g][2], bh[g][3]);
                ldm_x4t(bLo + off, bl[g][0], bl[g][1], bl[g][2], bl[g][3]);
            }
            #pragma unroll
            for (int mi = 0; mi < 4; mi++) {
                u32 ah[4], al[4];
                const u32 aoff = (u32)((mi * 16 + r8) * APITCH + ks * 16 + kh8) * 2;
                ldm_x4(aHi + aoff, ah[0], ah[1], ah[2], ah[3]);
                ldm_x4(aLo + aoff, al[0], al[1], al[2], al[3]);
                #pragma unroll
                for (int nj = 0; nj < 4; nj++) {
                    const int g = nj >> 1, s2 = nj & 1;
                    mma_bf16(c[mi][nj], ah, bh[g][2 * s2], bh[g][2 * s2 + 1]);
                    mma_bf16(c[mi][nj], ah, bl[g][2 * s2], bl[g][2 * s2 + 1]);
                    mma_bf16(c[mi][nj], al, bh[g][2 * s2], bh[g][2 * s2 + 1]);
                }
            }
        }
        __syncthreads();
    }

    // ---- epilogue
    const int r4 = lane >> 2, c2 = (lane & 3) * 2;
    #pragma unroll
    for (int mi = 0; mi < 4; mi++) {
        #pragma unroll
        for (int h = 0; h < 2; h++) {
            const int oc = oc0 + mi * 16 + h * 8 + r4;
            const float bv = bias[oc];
            #pragma unroll
            for (int nj = 0; nj < 4; nj++) {
                const int px = px0 + wn32 + nj * 8 + c2;
                const float v0 = c[mi][nj][h * 2]     + bv;
                const float v1 = c[mi][nj][h * 2 + 1] + bv;
                if (DUAL) {
                    if (oc < oc_split)
                        *reinterpret_cast<float2*>(dstf + (size_t)b * dstf_stride
                            + (size_t)oc * NPIX + px) = make_float2(v0, v1);
                    else
                        *reinterpret_cast<float2*>(dstf2 + (size_t)b * dst2_stride
                            + (size_t)(oc - oc_split) * NPIX + px) = make_float2(v0, v1);
                } else {
                    *reinterpret_cast<float2*>(dstf + (size_t)b * dstf_stride
                        + (size_t)oc * NPIX + px) = make_float2(v0, v1);
                }
            }
        }
    }
}

// ---------------- fused a1->swish->a2->tanh*v, 128-px tiles -----------------
#define F2PITCH 136
#define F2STG (32 * F2PITCH * 2)
#define F2W1H (4 * F2STG)
#define F2W1L (F2W1H + 64 * 72 * 2)
#define F2W2H (F2W1L + 64 * 72 * 2)
#define F2W2L (F2W2H + 64 * 72 * 2)
#define F2SMEM (F2W2L + 64 * 72 * 2)

__global__ void __launch_bounds__(256, 3) fused_a1a2(
    const bf16* __restrict__ qkh, const bf16* __restrict__ qkl,
    const float* __restrict__ ba1, const float* __restrict__ ba2,
    const float* __restrict__ vsrc,
    bf16* __restrict__ ch, bf16* __restrict__ cl)
{
    extern __shared__ __align__(16) char sm[];
    const int tid = threadIdx.x;
    const int lane = tid & 31, warp = tid >> 5;
    const int px0 = blockIdx.x * 128;
    const int b   = blockIdx.y;
    const u32 smb = smem_u32(sm);

    const bf16* qkhb = qkh + (size_t)b * 64 * HW + px0;
    const bf16* qklb = qkl + (size_t)b * 64 * HW + px0;

    {
        const int r = tid >> 2;
        const int sb = (tid & 3) * 32;
        const size_t go = (size_t)r * 64 + (tid & 3) * 16;
        const u32 so = (u32)(r * 72) * 2 + sb;
        cpa16(smb + F2W1H + so, g_wa1h + go); cpa16(smb + F2W1H + so + 16, g_wa1h + go + 8);
        cpa16(smb + F2W1L + so, g_wa1l + go); cpa16(smb + F2W1L + so + 16, g_wa1l + go + 8);
        cpa16(smb + F2W2H + so, g_wa2h + go); cpa16(smb + F2W2H + so + 16, g_wa2h + go + 8);
        cpa16(smb + F2W2L + so, g_wa2l + go); cpa16(smb + F2W2L + so + 16, g_wa2l + go + 8);
    }
    const int bc = (tid & 15) * 8, br0 = tid >> 4;
    auto issueB = [&](int chunk) {
        const u32 base = smb + chunk * 2 * F2STG;
        #pragma unroll
        for (int i = 0; i < 2; i++) {
            const int brr = br0 + i * 16;
            const u32 d = base + (u32)(brr * F2PITCH + bc) * 2;
            const size_t o = (size_t)(chunk * 32 + brr) * HW + bc;
            cpa16(d, qkhb + o);
            cpa16(d + F2STG, qklb + o);
        }
        cp_commit();
    };
    issueB(0);
    issueB(1);

    const int grp = lane >> 3, lr = lane & 7;
    const int r8  = (grp & 1) * 8 + lr;
    const int kh8 = (grp >> 1) * 8;
    const int wn16 = warp * 16;
    const int r4 = lane >> 2, c2 = (lane & 3) * 2;

    float c[4][2][4];
    #pragma unroll
    for (int i = 0; i < 4; i++)
        #pragma unroll
        for (int j = 0; j < 2; j++)
            #pragma unroll
            for (int q = 0; q < 4; q++) c[i][j][q] = 0.f;

    for (int it = 0; it < 2; it++) {
        if (it == 0) cp_wait<1>(); else cp_wait<0>();
        __syncthreads();
        const u32 bHi = smb + it * 2 * F2STG, bLo = bHi + F2STG;
        #pragma unroll
        for (int ks = 0; ks < 2; ks++) {
            u32 bh[4], bl[4];
            const u32 off = (u32)((ks * 16 + r8) * F2PITCH + wn16 + kh8) * 2;
            ldm_x4t(bHi + off, bh[0], bh[1], bh[2], bh[3]);
            ldm_x4t(bLo + off, bl[0], bl[1], bl[2], bl[3]);
            #pragma unroll
            for (int mi = 0; mi < 4; mi++) {
                u32 ah[4], al[4];
                const u32 aoff = (u32)((mi * 16 + r8) * 72 + it * 32 + ks * 16 + kh8) * 2;
                ldm_x4(smb + F2W1H + aoff, ah[0], ah[1], ah[2], ah[3]);
                ldm_x4(smb + F2W1L + aoff, al[0], al[1], al[2], al[3]);
                #pragma unroll
                for (int nj = 0; nj < 2; nj++) {
                    mma_bf16(c[mi][nj], ah, bh[2 * nj], bh[2 * nj + 1]);
                    mma_bf16(c[mi][nj], ah, bl[2 * nj], bl[2 * nj + 1]);
                    mma_bf16(c[mi][nj], al, bh[2 * nj], bh[2 * nj + 1]);
                }
            }
        }
    }
    __syncthreads();

    #pragma unroll
    for (int mi = 0; mi < 4; mi++) {
        #pragma unroll
        for (int h = 0; h < 2; h++) {
            const int oc = mi * 16 + h * 8 + r4;
            const float bv = __ldg(&ba1[oc]);
            const u32 halfb = (oc & 32) ? 2u * F2STG : 0u;
            #pragma unroll
            for (int nj = 0; nj < 2; nj++) {
                float v0 = c[mi][nj][h * 2]     + bv;
                float v1 = c[mi][nj][h * 2 + 1] + bv;
                v0 = v0 / (1.f + __expf(-v0));
                v1 = v1 / (1.f + __expf(-v1));
                u32 hp, lp; split2(v0, v1, hp, lp);
                const u32 off = (u32)((oc & 31) * F2PITCH + wn16 + nj * 8 + c2) * 2;
                *reinterpret_cast<u32*>(sm + halfb + off)         = hp;
                *reinterpret_cast<u32*>(sm + halfb + F2STG + off) = lp;
            }
        }
    }
    __syncthreads();

    #pragma unroll
    for (int i = 0; i < 4; i++)
        #pragma unroll
        for (int j = 0; j < 2; j++)
            #pragma unroll
            for (int q = 0; q < 4; q++) c[i][j][q] = 0.f;

    #pragma unroll
    for (int it = 0; it < 2; it++) {
        const u32 bHi = smb + it * 2 * F2STG, bLo = bHi + F2STG;
        #pragma unroll
        for (int ks = 0; ks < 2; ks++) {
            u32 bh[4], bl[4];
            const u32 off = (u32)((ks * 16 + r8) * F2PITCH + wn16 + kh8) * 2;
            ldm_x4t(bHi + off, bh[0], bh[1], bh[2], bh[3]);
            ldm_x4t(bLo + off, bl[0], bl[1], bl[2], bl[3]);
            #pragma unroll
            for (int mi = 0; mi < 4; mi++) {
                u32 ah[4], al[4];
                const u32 aoff = (u32)((mi * 16 + r8) * 72 + it * 32 + ks * 16 + kh8) * 2;
                ldm_x4(smb + F2W2H + aoff, ah[0], ah[1], ah[2], ah[3]);
                ldm_x4(smb + F2W2L + aoff, al[0], al[1], al[2], al[3]);
                #pragma unroll
                for (int nj = 0; nj < 2; nj++) {
                    mma_bf16(c[mi][nj], ah, bh[2 * nj], bh[2 * nj + 1]);
                    mma_bf16(c[mi][nj], ah, bl[2 * nj], bl[2 * nj + 1]);
                    mma_bf16(c[mi][nj], al, bh[2 * nj], bh[2 * nj + 1]);
                }
            }
        }
    }

    #pragma unroll
    for (int mi = 0; mi < 4; mi++) {
        #pragma unroll
        for (int h = 0; h < 2; h++) {
            const int oc = mi * 16 + h * 8 + r4;
            const float bv = __ldg(&ba2[oc]);
            #pragma unroll
            for (int nj = 0; nj < 2; nj++) {
                const int px = px0 + wn16 + nj * 8 + c2;
                const float* vr = vsrc + ((size_t)b * 64 + oc) * HW + px;
                float v0 = tanhf((c[mi][nj][h * 2]     + bv) * 0.25f) * __ldg(vr);
                float v1 = tanhf((c[mi][nj][h * 2 + 1] + bv) * 0.25f) * __ldg(vr + 1);
                u32 hp, lp; split2(v0, v1, hp, lp);
                const size_t o = ((size_t)b * 128 + oc) * HW + px;
                *reinterpret_cast<u32*>(ch + o) = hp;
                *reinterpret_cast<u32*>(cl + o) = lp;
            }
        }
    }
}

// ---------------- weight prep ------------------------------------------------
__global__ void prep_weights(
    const float* __restrict__ Wqkv, const float* __restrict__ Wq,
    const float* __restrict__ Wa1, const float* __restrict__ Wa2,
    const float* __restrict__ Wproj,
    const float* __restrict__ bqkv, const float* __restrict__ bq)
{
    const int i = blockIdx.x * 256 + threadIdx.x;
    if (i < 32768) {
        float v = (i < 24576) ? Wqkv[i] : Wq[i - 24576];
        split1(v, g_w1h, g_w1l, i);
    } else if (i < 36864) {
        split1(Wa1[i - 32768], g_wa1h, g_wa1l, i - 32768);
    } else if (i < 40960) {
        split1(Wa2[i - 36864], g_wa2h, g_wa2l, i - 36864);
    } else if (i < 57344) {
        split1(Wproj[i - 40960], g_wph, g_wpl, i - 40960);
    } else if (i < 57600) {
        const int j = i - 57344;
        g_b1[j] = (j < 192) ? bqkv[j] : bq[j - 192];
    }
}

// ---------------- x -> hi/lo bf16 + 8x8 avgpool (one pass) -------------------
__global__ void __launch_bounds__(256) cvtpool(
    const float* __restrict__ x, bf16* __restrict__ xh, bf16* __restrict__ xl,
    float* __restrict__ xp)
{
    const int plane = blockIdx.x;
    const int t = threadIdx.x;
    const int wi = t >> 4, wj = t & 15;
    const float* sp = x + (size_t)plane * HW + (wi * 8) * WW + wj * 8;
    bf16* oh = xh + (size_t)plane * HW + (wi * 8) * WW + wj * 8;
    bf16* ol = xl + (size_t)plane * HW + (wi * 8) * WW + wj * 8;

    float s = 0.f;
    #pragma unroll
    for (int r = 0; r < 8; r++) {
        const float4 a = *reinterpret_cast<const float4*>(sp + r * WW);
        const float4 b = *reinterpret_cast<const float4*>(sp + r * WW + 4);
        s += a.x + a.y + a.z + a.w + b.x + b.y + b.z + b.w;
        u32 h0, l0, h1, l1, h2, l2, h3, l3;
        split2(a.x, a.y, h0, l0); split2(a.z, a.w, h1, l1);
        split2(b.x, b.y, h2, l2); split2(b.z, b.w, h3, l3);
        *reinterpret_cast<uint4*>(oh + r * WW) = make_uint4(h0, h1, h2, h3);
        *reinterpret_cast<uint4*>(ol + r * WW) = make_uint4(l0, l1, l2, l3);
    }
    xp[(size_t)plane * 256 + wi * 16 + wj] = s * (1.f / 64.f);
}

// ---------------- depthwise 3x3, smem-tiled rolling stencil -----------------
__global__ void __launch_bounds__(128) dwconv_qk(
    const float* __restrict__ qkv, const float* __restrict__ w,
    const float* __restrict__ bias,
    bf16* __restrict__ qkh, bf16* __restrict__ qkl,
    float* __restrict__ vout)
{
    const int z = blockIdx.z;
    const int b = z >> 7, t = z & 127;
    const int x = threadIdx.x;
    const int y0 = blockIdx.y * 16;

    __shared__ float s0[18][136];
    __shared__ float s1[18][136];

    if (t < 64) {
        const float* pq = qkv + ((size_t)b * 192 + t) * HW;
        const float* pk = qkv + ((size_t)b * 192 + 64 + t) * HW;
        #pragma unroll
        for (int r = 0; r < 18; r++) {
            const int yy = y0 - 1 + r;
            const bool ok = (yy >= 0) && (yy < HH);
            s0[r][x + 1] = ok ? __ldg(pq + yy * WW + x) : 0.f;
            s1[r][x + 1] = ok ? __ldg(pk + yy * WW + x) : 0.f;
        }
        if (x < 2) {
            const int col = x ? 129 : 0;
            #pragma unroll
            for (int r = 0; r < 18; r++) { s0[r][col] = 0.f; s1[r][col] = 0.f; }
        }
        __syncthreads();

        float wq[9], wk[9];
        #pragma unroll
        for (int i = 0; i < 9; i++) {
            wq[i] = __ldg(&w[t * 9 + i]);
            wk[i] = __ldg(&w[(64 + t) * 9 + i]);
        }
        const float bq = __ldg(&bias[t]);
        const float bk = __ldg(&bias[64 + t]);

        bf16* oh = qkh + ((size_t)b * 64 + t) * HW + (size_t)y0 * WW + x;
        bf16* ol = qkl + ((size_t)b * 64 + t) * HW + (size_t)y0 * WW + x;

        float Aq = 0.f, Bq = 0.f, Ak = 0.f, Bk = 0.f;
        #pragma unroll
        for (int r = 0; r < 18; r++) {
            const float lq = s0[r][x], cq = s0[r][x + 1], rq = s0[r][x + 2];
            const float h0q = wq[0]*lq + wq[1]*cq + wq[2]*rq;
            const float h1q = wq[3]*lq + wq[4]*cq + wq[5]*rq;
            const float h2q = wq[6]*lq + wq[7]*cq + wq[8]*rq;
            const float lk = s1[r][x], ck = s1[r][x + 1], rk = s1[r][x + 2];
            const float h0k = wk[0]*lk + wk[1]*ck + wk[2]*rk;
            const float h1k = wk[3]*lk + wk[4]*ck + wk[5]*rk;
            const float h2k = wk[6]*lk + wk[7]*ck + wk[8]*rk;
            Aq += h2q; Ak += h2k;
            if (r >= 2) {
                const int o = r - 2;
                const float prod = (Aq + bq) * (Ak + bk);
                const bf16 hv = __float2bfloat16(prod);
                oh[o * WW] = hv;
                ol[o * WW] = __float2bfloat16(prod - __bfloat162float(hv));
            }
            Aq = Bq + h1q; Bq = h0q;
            Ak = Bk + h1k; Bk = h0k;
        }
    } else {
        const int cv = t - 64;
        const float* pv = qkv + ((size_t)b * 192 + 128 + cv) * HW;
        #pragma unroll
        for (int r = 0; r < 18; r++) {
            const int yy = y0 - 1 + r;
            s0[r][x + 1] = (yy >= 0 && yy < HH) ? __ldg(pv + yy * WW + x) : 0.f;
        }
        if (x < 2) {
            const int col = x ? 129 : 0;
            #pragma unroll
            for (int r = 0; r < 18; r++) s0[r][col] = 0.f;
        }
        __syncthreads();

        float wv[9];
        #pragma unroll
        for (int i = 0; i < 9; i++) wv[i] = __ldg(&w[(128 + cv) * 9 + i]);
        const float bv = __ldg(&bias[128 + cv]);

        float* ov = vout + ((size_t)b * 64 + cv) * HW + (size_t)y0 * WW + x;
        float A = 0.f, Bv = 0.f;
        #pragma unroll
        for (int r = 0; r < 18; r++) {
            const float lv = s0[r][x], cvv = s0[r][x + 1], rv = s0[r][x + 2];
            const float h0 = wv[0]*lv + wv[1]*cvv + wv[2]*rv;
            const float h1 = wv[3]*lv + wv[4]*cvv + wv[5]*rv;
            const float h2 = wv[6]*lv + wv[7]*cvv + wv[8]*rv;
            A += h2;
            if (r >= 2) ov[(r - 2) * WW] = A + bv;
            A = Bv + h1; Bv = h0;
        }
    }
}

// ---------------- kv = Wkv @ xp + bkv (SIMT, fp32) — R8 proven version ------
__global__ void __launch_bounds__(256) kv_simt(
    const float* __restrict__ xp, const float* __restrict__ Wkv,
    const float* __restrict__ bkv, float* __restrict__ kvout)
{
    const int idx = blockIdx.x * 256 + threadIdx.x;
    const int p  = idx & 255;
    const int oc = (idx >> 8) & 127;
    const int b  = idx >> 15;
    const float* xpb = xp + (size_t)b * 128 * 256 + p;
    const float* wr  = Wkv + oc * 128;
    float acc = __ldg(&bkv[oc]);
    #pragma unroll 8
    for (int c = 0; c < 128; c++)
        acc += __ldg(wr + c) * __ldg(xpb + c * 256);
    kvout[((size_t)b * 128 + oc) * 256 + p] = acc;
}

// ---------------- low-freq softmax attention (2 px/thread) -------------------
__global__ void __launch_bounds__(128) lowfreq_attn(
    const float* __restrict__ qg, const float* __restrict__ kv,
    bf16* __restrict__ ch, bf16* __restrict__ cl)
{
    const int b = blockIdx.z, h = blockIdx.y;
    const int p = blockIdx.x * 256 + threadIdx.x;

    __shared__ __align__(16) u64 ks2[256][8];
    __shared__ __align__(16) u64 vs2[256][8];

    const float* kvb = kv + (size_t)b * 128 * 256;
    for (int i = threadIdx.x; i < 2048; i += 128) {
        const int d2 = i >> 8, m = i & 255;
        ks2[m][d2] = pack2(kvb[(h * 16 + 2 * d2) * 256 + m],
                           kvb[(h * 16 + 2 * d2 + 1) * 256 + m]);
        vs2[m][d2] = pack2(kvb[(64 + h * 16 + 2 * d2) * 256 + m],
                           kvb[(64 + h * 16 + 2 * d2 + 1) * 256 + m]);
    }
    __syncthreads();

    u64 qa[8], qb[8];
    #pragma unroll
    for (int d2 = 0; d2 < 8; d2++) {
        const size_t base = (size_t)b * 64 * HW + (size_t)(h * 16 + 2 * d2) * HW + p;
        qa[d2] = pack2(0.25f * __ldg(&qg[base]),       0.25f * __ldg(&qg[base + HW]));
        qb[d2] = pack2(0.25f * __ldg(&qg[base + 128]), 0.25f * __ldg(&qg[base + HW + 128]));
    }

    float suma = 0.f, sumb = 0.f;
    u64 acca[8], accb[8];
    #pragma unroll
    for (int d2 = 0; d2 < 8; d2++) { acca[d2] = 0ull; accb[d2] = 0ull; }

    for (int m = 0; m < 256; m++) {
        u64 sa = 0ull, sb = 0ull;
        #pragma unroll
        for (int d2 = 0; d2 < 8; d2++) {
            const u64 kk = ks2[m][d2];
            sa = ffma2(qa[d2], kk, sa);
            sb = ffma2(qb[d2], kk, sb);
        }
        float a0, a1, b0, b1;
        unpack2(sa, a0, a1); unpack2(sb, b0, b1);
        const float ea = __expf(a0 + a1);
        const float eb = __expf(b0 + b1);
        suma += ea; sumb += eb;
        const u64 ea2 = pack2(ea, ea), eb2 = pack2(eb, eb);
        #pragma unroll
        for (int d2 = 0; d2 < 8; d2++) {
            const u64 vv = vs2[m][d2];
            acca[d2] = ffma2(ea2, vv, acca[d2]);
            accb[d2] = ffma2(eb2, vv, accb[d2]);
        }
    }

    const float inva = 1.f / suma, invb = 1.f / sumb;
    #pragma unroll
    for (int d2 = 0; d2 < 8; d2++) {
        float lo, hi;
        unpack2(acca[d2], lo, hi);
        const size_t base = ((size_t)b * 128 + 64 + h * 16 + 2 * d2) * HW + p;
        split1(lo * inva, ch, cl, base);
        split1(hi * inva, ch, cl, base + HW);
        unpack2(accb[d2], lo, hi);
        split1(lo * invb, ch, cl, base + 128);
        split1(hi * invb, ch, cl, base + HW + 128);
    }
}

// ---------------- launch -----------------------------------------------------
extern "C" void kernel_launch(void* const* d_in, const int* in_sizes, int n_in,
                              void* d_out, int out_size)
{
    const float* x     = (const float*)d_in[0];
    const float* Wqkv  = (const float*)d_in[1];
    const float* bqkv  = (const float*)d_in[2];
    const float* Wdw   = (const float*)d_in[3];
    const float* bdw   = (const float*)d_in[4];
    const float* Wa1   = (const float*)d_in[5];
    const float* ba1   = (const float*)d_in[6];
    const float* Wa2   = (const float*)d_in[7];
    const float* ba2   = (const float*)d_in[8];
    const float* Wq    = (const float*)d_in[9];
    const float* bq    = (const float*)d_in[10];
    const float* Wkv   = (const float*)d_in[11];
    const float* bkv   = (const float*)d_in[12];
    const float* Wproj = (const float*)d_in[13];
    const float* bproj = (const float*)d_in[14];
    float* out = (float*)d_out;

    float *qkv, *v, *qg, *kv, *xp, *b1;
    bf16 *xh, *xl, *qkh, *qkl, *ch, *cl;
    bf16 *w1h, *w1l, *wph, *wpl;
    cudaGetSymbolAddress((void**)&qkv, g_qkv);
    cudaGetSymbolAddress((void**)&v,   g_v);
    cudaGetSymbolAddress((void**)&qg,  g_qg);
    cudaGetSymbolAddress((void**)&kv,  g_kv);
    cudaGetSymbolAddress((void**)&xp,  g_xp);
    cudaGetSymbolAddress((void**)&b1,  g_b1);
    cudaGetSymbolAddress((void**)&xh,  g_xh);
    cudaGetSymbolAddress((void**)&xl,  g_xl);
    cudaGetSymbolAddress((void**)&qkh, g_qkh);
    cudaGetSymbolAddress((void**)&qkl, g_qkl);
    cudaGetSymbolAddress((void**)&ch,  g_ch);
    cudaGetSymbolAddress((void**)&cl,  g_cl);
    cudaGetSymbolAddress((void**)&w1h, g_w1h);
    cudaGetSymbolAddress((void**)&w1l, g_w1l);
    cudaGetSymbolAddress((void**)&wph, g_wph);
    cudaGetSymbolAddress((void**)&wpl, g_wpl);

    cudaFuncSetAttribute(gemm_bf16<true>,
                         cudaFuncAttributeMaxDynamicSharedMemorySize, SMEM_BYTES);
    cudaFuncSetAttribute(gemm_bf16<false>,
                         cudaFuncAttributeMaxDynamicSharedMemorySize, SMEM_BYTES);
    cudaFuncSetAttribute(fused_a1a2,
                         cudaFuncAttributeMaxDynamicSharedMemorySize, F2SMEM);

    static cudaStream_t s1 = nullptr;
    static cudaEvent_t eS = nullptr, e0 = nullptr, e1 = nullptr,
                       e2 = nullptr, e3 = nullptr;
    if (!s1) {
        cudaStreamCreateWithFlags(&s1, cudaStreamNonBlocking);
        cudaEventCreateWithFlags(&eS, cudaEventDisableTiming);
        cudaEventCreateWithFlags(&e0, cudaEventDisableTiming);
        cudaEventCreateWithFlags(&e1, cudaEventDisableTiming);
        cudaEventCreateWithFlags(&e2, cudaEventDisableTiming);
        cudaEventCreateWithFlags(&e3, cudaEventDisableTiming);
    }

    // fork s1 from the capturing stream BEFORE any s1 work (capture rule)
    cudaEventRecord(eS, 0);
    cudaStreamWaitEvent(s1, eS, 0);

    // 0) weight prep on side stream; x split/pool on main (concurrent)
    prep_weights<<<225, 256, 0, s1>>>(Wqkv, Wq, Wa1, Wa2, Wproj, bqkv, bq);
    cudaEventRecord(e0, s1);
    cvtpool<<<NB * 128, 256>>>(x, xh, xl, xp);
    cudaEventRecord(e1, 0);

    // 1) fused qkv+qg GEMM (main; needs weights + xh/xl) — R8 grid order
    cudaStreamWaitEvent(0, e0, 0);
    gemm_bf16<true><<<dim3(HW / 256, 4, NB), 256, SMEM_BYTES>>>(
        xh, xl, w1h, w1l, b1, 128, HW,
        qkv, 192 * HW, qg, 64 * HW, 192);
    cudaEventRecord(e2, 0);

    // side branch: kv then attention (overlaps dwconv + fused)
    cudaStreamWaitEvent(s1, e1, 0);
    kv_simt<<<NB * 128 * 256 / 256, 256, 0, s1>>>(xp, Wkv, bkv, kv);
    cudaStreamWaitEvent(s1, e2, 0);
    lowfreq_attn<<<dim3(HW / 256, 4, NB), 128, 0, s1>>>(qg, kv, ch, cl);
    cudaEventRecord(e3, s1);

    // 2) depthwise 3x3 with q*k fusion (main)
    dwconv_qk<<<dim3(1, 8, NB * 128), 128>>>(qkv, Wdw, bdw, qkh, qkl, v);

    // 3+4) fused a1 -> swish -> a2 -> tanh*v (main) -> cat planes [0,64)
    fused_a1a2<<<dim3(HW / 128, NB), 256, F2SMEM>>>(qkh, qkl, ba1, ba2, v, ch, cl);

    // join, then 5) out = Wproj @ cat — R8 grid order
    cudaStreamWaitEvent(0, e3, 0);
    gemm_bf16<false><<<dim3(HW / 256, 2, NB), 256, SMEM_BYTES>>>(
        ch, cl, wph, wpl, bproj, 128, HW,
        out, 128 * HW, nullptr, 0, 0);
}

// round 13
// speedup vs baseline: 1.1172x; 1.0807x over previous
#include <cuda_runtime.h>
#include <cuda_bf16.h>
#include <math.h>

#define HW 16384
#define HH 128
#define WW 128
#define NB 4

typedef unsigned long long u64;
typedef unsigned int u32;
typedef __nv_bfloat16 bf16;

// ---------------- f32x2 helpers (attention) ---------------------------------
__device__ __forceinline__ u64 pack2(float lo, float hi) {
    u64 r; asm("mov.b64 %0,{%1,%2};" : "=l"(r) : "f"(lo), "f"(hi)); return r;
}
__device__ __forceinline__ void unpack2(u64 v, float& lo, float& hi) {
    asm("mov.b64 {%0,%1},%2;" : "=f"(lo), "=f"(hi) : "l"(v));
}
__device__ __forceinline__ u64 ffma2(u64 a, u64 b, u64 c) {
    u64 r; asm("fma.rn.f32x2 %0,%1,%2,%3;" : "=l"(r) : "l"(a), "l"(b), "l"(c)); return r;
}

// ---------------- scratch ----------------------------------------------------
__device__ __align__(256) float g_qkv [NB * 192 * HW];
__device__ __align__(256) float g_v   [NB * 64  * HW];
__device__ __align__(256) float g_qg  [NB * 64  * HW];
__device__ __align__(256) float g_kv  [NB * 128 * 256];
__device__ __align__(256) float g_xp  [NB * 128 * 256];
__device__ __align__(256) bf16  g_xh  [NB * 128 * HW];
__device__ __align__(256) bf16  g_xl  [NB * 128 * HW];
__device__ __align__(256) bf16  g_qkh [NB * 64 * HW];
__device__ __align__(256) bf16  g_qkl [NB * 64 * HW];
__device__ __align__(256) bf16  g_ch  [NB * 128 * HW];
__device__ __align__(256) bf16  g_cl  [NB * 128 * HW];
__device__ __align__(256) bf16  g_w1h [256 * 128];
__device__ __align__(256) bf16  g_w1l [256 * 128];
__device__ __align__(256) bf16  g_wa1h[64 * 64];
__device__ __align__(256) bf16  g_wa1l[64 * 64];
__device__ __align__(256) bf16  g_wa2h[64 * 64];
__device__ __align__(256) bf16  g_wa2l[64 * 64];
__device__ __align__(256) bf16  g_wph [128 * 128];
__device__ __align__(256) bf16  g_wpl [128 * 128];
__device__ __align__(256) float g_b1  [256];

// ---------------- mma / cp.async helpers ------------------------------------
__device__ __forceinline__ u32 smem_u32(const void* p) {
    u32 a;
    asm("{ .reg .u64 t; cvta.to.shared.u64 t, %1; cvt.u32.u64 %0, t; }"
        : "=r"(a) : "l"(p));
    return a;
}
__device__ __forceinline__ void ldm_x4(u32 a, u32& r0, u32& r1, u32& r2, u32& r3) {
    asm volatile("ldmatrix.sync.aligned.m8n8.x4.shared.b16 {%0,%1,%2,%3},[%4];"
                 : "=r"(r0), "=r"(r1), "=r"(r2), "=r"(r3) : "r"(a));
}
__device__ __forceinline__ void ldm_x4t(u32 a, u32& r0, u32& r1, u32& r2, u32& r3) {
    asm volatile("ldmatrix.sync.aligned.m8n8.x4.trans.shared.b16 {%0,%1,%2,%3},[%4];"
                 : "=r"(r0), "=r"(r1), "=r"(r2), "=r"(r3) : "r"(a));
}
__device__ __forceinline__ void mma_bf16(float* c, const u32* a, u32 b0, u32 b1) {
    asm volatile(
        "mma.sync.aligned.m16n8k16.row.col.f32.bf16.bf16.f32 "
        "{%0,%1,%2,%3},{%4,%5,%6,%7},{%8,%9},{%0,%1,%2,%3};"
        : "+f"(c[0]), "+f"(c[1]), "+f"(c[2]), "+f"(c[3])
        : "r"(a[0]), "r"(a[1]), "r"(a[2]), "r"(a[3]), "r"(b0), "r"(b1));
}
__device__ __forceinline__ void cpa16(u32 d, const void* s) {
    asm volatile("cp.async.cg.shared.global [%0],[%1],16;" :: "r"(d), "l"(s));
}
__device__ __forceinline__ void cp_commit() {
    asm volatile("cp.async.commit_group;" ::: "memory");
}
template<int N> __device__ __forceinline__ void cp_wait() {
    asm volatile("cp.async.wait_group %0;" :: "n"(N) : "memory");
}
__device__ __forceinline__ void split2(float x0, float x1, u32& h, u32& l) {
    bf16 h0 = __float2bfloat16(x0);
    bf16 h1 = __float2bfloat16(x1);
    float r0 = x0 - __bfloat162float(h0);
    float r1 = x1 - __bfloat162float(h1);
    __nv_bfloat162 hp; hp.x = h0; hp.y = h1;
    __nv_bfloat162 lp; lp.x = __float2bfloat16(r0); lp.y = __float2bfloat16(r1);
    h = *reinterpret_cast<u32*>(&hp);
    l = *reinterpret_cast<u32*>(&lp);
}
__device__ __forceinline__ void split1(float x, bf16* hd, bf16* ld, size_t o) {
    bf16 h = __float2bfloat16(x);
    hd[o] = h;
    ld[o] = __float2bfloat16(x - __bfloat162float(h));
}

// ---------------- GEMM geometry ----------------------------------------------
#define APITCH 40
#define BPITCH 264
#define APB (64 * APITCH * 2)
#define BPB (32 * BPITCH * 2)
#define SMEM_BYTES (4 * APB + 4 * BPB)

// ---------------- generic bf16-split tensor-core GEMM (R8-proven) -----------
template<bool DUAL>
__global__ void __launch_bounds__(256, 2) gemm_bf16(
    const bf16* __restrict__ Xh, const bf16* __restrict__ Xl,
    const bf16* __restrict__ Wh, const bf16* __restrict__ Wl,
    const float* __restrict__ bias, int IC, int NPIX,
    float* dstf, int dstf_stride,
    float* dstf2, int dst2_stride, int oc_split)
{
    extern __shared__ __align__(16) char sm[];
    const int tid = threadIdx.x;
    const int lane = tid & 31, warp = tid >> 5;
    const int px0 = blockIdx.x * 256;
    const int oc0 = blockIdx.y * 64;
    const int b   = blockIdx.z;
    const u32 smb = smem_u32(sm);

    const bf16* Xhb = Xh + (size_t)b * IC * NPIX;
    const bf16* Xlb = Xl + (size_t)b * IC * NPIX;

    const int ar = tid >> 2, ac = (tid & 3) * 8;
    const int bc = (tid & 31) * 8, br0 = tid >> 5;
    const int nk = IC >> 5;

    float c[4][4][4];
    #pragma unroll
    for (int i = 0; i < 4; i++)
        #pragma unroll
        for (int j = 0; j < 4; j++)
            #pragma unroll
            for (int q = 0; q < 4; q++) c[i][j][q] = 0.f;

    auto issue = [&](int it) {
        const int st = it & 1;
        const int k0 = it << 5;
        u32 aD = smb + st * 2 * APB + (u32)(ar * APITCH + ac) * 2;
        const size_t aO = (size_t)(oc0 + ar) * IC + k0 + ac;
        cpa16(aD, Wh + aO);
        cpa16(aD + APB, Wl + aO);
        const u32 bBase = smb + 4 * APB + st * 2 * BPB;
        #pragma unroll
        for (int i = 0; i < 4; i++) {
            const int brr = br0 + i * 8;
            u32 bD = bBase + (u32)(brr * BPITCH + bc) * 2;
            const size_t bO = (size_t)(k0 + brr) * NPIX + px0 + bc;
            cpa16(bD, Xhb + bO);
            cpa16(bD + BPB, Xlb + bO);
        }
        cp_commit();
    };

    issue(0);

    const int grp = lane >> 3, lr = lane & 7;
    const int r8  = (grp & 1) * 8 + lr;
    const int kh8 = (grp >> 1) * 8;
    const int wn32 = warp * 32;

    for (int it = 0; it < nk; it++) {
        if (it + 1 < nk) { issue(it + 1); cp_wait<1>(); }
        else             { cp_wait<0>(); }
        __syncthreads();
        const int st = it & 1;
        const u32 aHi = smb + st * 2 * APB, aLo = aHi + APB;
        const u32 bHi = smb + 4 * APB + st * 2 * BPB, bLo = bHi + BPB;
        #pragma unroll
        for (int ks = 0; ks < 2; ks++) {
            u32 bh[2][4], bl[2][4];
            #pragma unroll
            for (int g = 0; g < 2; g++) {
                const u32 off = (u32)((ks * 16 + r8) * BPITCH + wn32 + g * 16 + kh8) * 2;
                ldm_x4t(bHi + off, bh[g][0], bh[g][1], bh[g][2], bh[g][3]);
                ldm_x4t(bLo + off, bl[g][0], bl[g][1], bl[g][2], bl[g][3]);
            }
            #pragma unroll
            for (int mi = 0; mi < 4; mi++) {
                u32 ah[4], al[4];
                const u32 aoff = (u32)((mi * 16 + r8) * APITCH + ks * 16 + kh8) * 2;
                ldm_x4(aHi + aoff, ah[0], ah[1], ah[2], ah[3]);
                ldm_x4(aLo + aoff, al[0], al[1], al[2], al[3]);
                #pragma unroll
                for (int nj = 0; nj < 4; nj++) {
                    const int g = nj >> 1, s2 = nj & 1;
                    mma_bf16(c[mi][nj], ah, bh[g][2 * s2], bh[g][2 * s2 + 1]);
                    mma_bf16(c[mi][nj], ah, bl[g][2 * s2], bl[g][2 * s2 + 1]);
                    mma_bf16(c[mi][nj], al, bh[g][2 * s2], bh[g][2 * s2 + 1]);
                }
            }
        }
        __syncthreads();
    }

    // ---- epilogue
    const int r4 = lane >> 2, c2 = (lane & 3) * 2;
    #pragma unroll
    for (int mi = 0; mi < 4; mi++) {
        #pragma unroll
        for (int h = 0; h < 2; h++) {
            const int oc = oc0 + mi * 16 + h * 8 + r4;
            const float bv = bias[oc];
            #pragma unroll
            for (int nj = 0; nj < 4; nj++) {
                const int px = px0 + wn32 + nj * 8 + c2;
                const float v0 = c[mi][nj][h * 2]     + bv;
                const float v1 = c[mi][nj][h * 2 + 1] + bv;
                if (DUAL) {
                    if (oc < oc_split)
                        *reinterpret_cast<float2*>(dstf + (size_t)b * dstf_stride
                            + (size_t)oc * NPIX + px) = make_float2(v0, v1);
                    else
                        *reinterpret_cast<float2*>(dstf2 + (size_t)b * dst2_stride
                            + (size_t)(oc - oc_split) * NPIX + px) = make_float2(v0, v1);
                } else {
                    *reinterpret_cast<float2*>(dstf + (size_t)b * dstf_stride
                        + (size_t)oc * NPIX + px) = make_float2(v0, v1);
                }
            }
        }
    }
}

// ---------------- fused a1->swish->a2->tanh*v, 128-px tiles -----------------
#define F2PITCH 136
#define F2STG (32 * F2PITCH * 2)
#define F2W1H (4 * F2STG)
#define F2W1L (F2W1H + 64 * 72 * 2)
#define F2W2H (F2W1L + 64 * 72 * 2)
#define F2W2L (F2W2H + 64 * 72 * 2)
#define F2SMEM (F2W2L + 64 * 72 * 2)

__global__ void __launch_bounds__(256, 3) fused_a1a2(
    const bf16* __restrict__ qkh, const bf16* __restrict__ qkl,
    const float* __restrict__ ba1, const float* __restrict__ ba2,
    const float* __restrict__ vsrc,
    bf16* __restrict__ ch, bf16* __restrict__ cl)
{
    extern __shared__ __align__(16) char sm[];
    const int tid = threadIdx.x;
    const int lane = tid & 31, warp = tid >> 5;
    const int px0 = blockIdx.x * 128;
    const int b   = blockIdx.y;
    const u32 smb = smem_u32(sm);

    const bf16* qkhb = qkh + (size_t)b * 64 * HW + px0;
    const bf16* qklb = qkl + (size_t)b * 64 * HW + px0;

    {
        const int r = tid >> 2;
        const int sb = (tid & 3) * 32;
        const size_t go = (size_t)r * 64 + (tid & 3) * 16;
        const u32 so = (u32)(r * 72) * 2 + sb;
        cpa16(smb + F2W1H + so, g_wa1h + go); cpa16(smb + F2W1H + so + 16, g_wa1h + go + 8);
        cpa16(smb + F2W1L + so, g_wa1l + go); cpa16(smb + F2W1L + so + 16, g_wa1l + go + 8);
        cpa16(smb + F2W2H + so, g_wa2h + go); cpa16(smb + F2W2H + so + 16, g_wa2h + go + 8);
        cpa16(smb + F2W2L + so, g_wa2l + go); cpa16(smb + F2W2L + so + 16, g_wa2l + go + 8);
    }
    const int bc = (tid & 15) * 8, br0 = tid >> 4;
    auto issueB = [&](int chunk) {
        const u32 base = smb + chunk * 2 * F2STG;
        #pragma unroll
        for (int i = 0; i < 2; i++) {
            const int brr = br0 + i * 16;
            const u32 d = base + (u32)(brr * F2PITCH + bc) * 2;
            const size_t o = (size_t)(chunk * 32 + brr) * HW + bc;
            cpa16(d, qkhb + o);
            cpa16(d + F2STG, qklb + o);
        }
        cp_commit();
    };
    issueB(0);
    issueB(1);

    const int grp = lane >> 3, lr = lane & 7;
    const int r8  = (grp & 1) * 8 + lr;
    const int kh8 = (grp >> 1) * 8;
    const int wn16 = warp * 16;
    const int r4 = lane >> 2, c2 = (lane & 3) * 2;

    float c[4][2][4];
    #pragma unroll
    for (int i = 0; i < 4; i++)
        #pragma unroll
        for (int j = 0; j < 2; j++)
            #pragma unroll
            for (int q = 0; q < 4; q++) c[i][j][q] = 0.f;

    for (int it = 0; it < 2; it++) {
        if (it == 0) cp_wait<1>(); else cp_wait<0>();
        __syncthreads();
        const u32 bHi = smb + it * 2 * F2STG, bLo = bHi + F2STG;
        #pragma unroll
        for (int ks = 0; ks < 2; ks++) {
            u32 bh[4], bl[4];
            const u32 off = (u32)((ks * 16 + r8) * F2PITCH + wn16 + kh8) * 2;
            ldm_x4t(bHi + off, bh[0], bh[1], bh[2], bh[3]);
            ldm_x4t(bLo + off, bl[0], bl[1], bl[2], bl[3]);
            #pragma unroll
            for (int mi = 0; mi < 4; mi++) {
                u32 ah[4], al[4];
                const u32 aoff = (u32)((mi * 16 + r8) * 72 + it * 32 + ks * 16 + kh8) * 2;
                ldm_x4(smb + F2W1H + aoff, ah[0], ah[1], ah[2], ah[3]);
                ldm_x4(smb + F2W1L + aoff, al[0], al[1], al[2], al[3]);
                #pragma unroll
                for (int nj = 0; nj < 2; nj++) {
                    mma_bf16(c[mi][nj], ah, bh[2 * nj], bh[2 * nj + 1]);
                    mma_bf16(c[mi][nj], ah, bl[2 * nj], bl[2 * nj + 1]);
                    mma_bf16(c[mi][nj], al, bh[2 * nj], bh[2 * nj + 1]);
                }
            }
        }
    }
    __syncthreads();

    #pragma unroll
    for (int mi = 0; mi < 4; mi++) {
        #pragma unroll
        for (int h = 0; h < 2; h++) {
            const int oc = mi * 16 + h * 8 + r4;
            const float bv = __ldg(&ba1[oc]);
            const u32 halfb = (oc & 32) ? 2u * F2STG : 0u;
            #pragma unroll
            for (int nj = 0; nj < 2; nj++) {
                float v0 = c[mi][nj][h * 2]     + bv;
                float v1 = c[mi][nj][h * 2 + 1] + bv;
                v0 = v0 / (1.f + __expf(-v0));
                v1 = v1 / (1.f + __expf(-v1));
                u32 hp, lp; split2(v0, v1, hp, lp);
                const u32 off = (u32)((oc & 31) * F2PITCH + wn16 + nj * 8 + c2) * 2;
                *reinterpret_cast<u32*>(sm + halfb + off)         = hp;
                *reinterpret_cast<u32*>(sm + halfb + F2STG + off) = lp;
            }
        }
    }
    __syncthreads();

    #pragma unroll
    for (int i = 0; i < 4; i++)
        #pragma unroll
        for (int j = 0; j < 2; j++)
            #pragma unroll
            for (int q = 0; q < 4; q++) c[i][j][q] = 0.f;

    #pragma unroll
    for (int it = 0; it < 2; it++) {
        const u32 bHi = smb + it * 2 * F2STG, bLo = bHi + F2STG;
        #pragma unroll
        for (int ks = 0; ks < 2; ks++) {
            u32 bh[4], bl[4];
            const u32 off = (u32)((ks * 16 + r8) * F2PITCH + wn16 + kh8) * 2;
            ldm_x4t(bHi + off, bh[0], bh[1], bh[2], bh[3]);
            ldm_x4t(bLo + off, bl[0], bl[1], bl[2], bl[3]);
            #pragma unroll
            for (int mi = 0; mi < 4; mi++) {
                u32 ah[4], al[4];
                const u32 aoff = (u32)((mi * 16 + r8) * 72 + it * 32 + ks * 16 + kh8) * 2;
                ldm_x4(smb + F2W2H + aoff, ah[0], ah[1], ah[2], ah[3]);
                ldm_x4(smb + F2W2L + aoff, al[0], al[1], al[2], al[3]);
                #pragma unroll
                for (int nj = 0; nj < 2; nj++) {
                    mma_bf16(c[mi][nj], ah, bh[2 * nj], bh[2 * nj + 1]);
                    mma_bf16(c[mi][nj], ah, bl[2 * nj], bl[2 * nj + 1]);
                    mma_bf16(c[mi][nj], al, bh[2 * nj], bh[2 * nj + 1]);
                }
            }
        }
    }

    #pragma unroll
    for (int mi = 0; mi < 4; mi++) {
        #pragma unroll
        for (int h = 0; h < 2; h++) {
            const int oc = mi * 16 + h * 8 + r4;
            const float bv = __ldg(&ba2[oc]);
            #pragma unroll
            for (int nj = 0; nj < 2; nj++) {
                const int px = px0 + wn16 + nj * 8 + c2;
                const float* vr = vsrc + ((size_t)b * 64 + oc) * HW + px;
                float v0 = tanhf((c[mi][nj][h * 2]     + bv) * 0.25f) * __ldg(vr);
                float v1 = tanhf((c[mi][nj][h * 2 + 1] + bv) * 0.25f) * __ldg(vr + 1);
                u32 hp, lp; split2(v0, v1, hp, lp);
                const size_t o = ((size_t)b * 128 + oc) * HW + px;
                *reinterpret_cast<u32*>(ch + o) = hp;
                *reinterpret_cast<u32*>(cl + o) = lp;
            }
        }
    }
}

// ---------------- weight prep ------------------------------------------------
__global__ void prep_weights(
    const float* __restrict__ Wqkv, const float* __restrict__ Wq,
    const float* __restrict__ Wa1, const float* __restrict__ Wa2,
    const float* __restrict__ Wproj,
    const float* __restrict__ bqkv, const float* __restrict__ bq)
{
    const int i = blockIdx.x * 256 + threadIdx.x;
    if (i < 32768) {
        float v = (i < 24576) ? Wqkv[i] : Wq[i - 24576];
        split1(v, g_w1h, g_w1l, i);
    } else if (i < 36864) {
        split1(Wa1[i - 32768], g_wa1h, g_wa1l, i - 32768);
    } else if (i < 40960) {
        split1(Wa2[i - 36864], g_wa2h, g_wa2l, i - 36864);
    } else if (i < 57344) {
        split1(Wproj[i - 40960], g_wph, g_wpl, i - 40960);
    } else if (i < 57600) {
        const int j = i - 57344;
        g_b1[j] = (j < 192) ? bqkv[j] : bq[j - 192];
    }
}

// ---------------- x -> hi/lo bf16 + 8x8 avgpool (one pass) -------------------
__global__ void __launch_bounds__(256) cvtpool(
    const float* __restrict__ x, bf16* __restrict__ xh, bf16* __restrict__ xl,
    float* __restrict__ xp)
{
    const int plane = blockIdx.x;
    const int t = threadIdx.x;
    const int wi = t >> 4, wj = t & 15;
    const float* sp = x + (size_t)plane * HW + (wi * 8) * WW + wj * 8;
    bf16* oh = xh + (size_t)plane * HW + (wi * 8) * WW + wj * 8;
    bf16* ol = xl + (size_t)plane * HW + (wi * 8) * WW + wj * 8;

    float s = 0.f;
    #pragma unroll
    for (int r = 0; r < 8; r++) {
        const float4 a = *reinterpret_cast<const float4*>(sp + r * WW);
        const float4 b = *reinterpret_cast<const float4*>(sp + r * WW + 4);
        s += a.x + a.y + a.z + a.w + b.x + b.y + b.z + b.w;
        u32 h0, l0, h1, l1, h2, l2, h3, l3;
        split2(a.x, a.y, h0, l0); split2(a.z, a.w, h1, l1);
        split2(b.x, b.y, h2, l2); split2(b.z, b.w, h3, l3);
        *reinterpret_cast<uint4*>(oh + r * WW) = make_uint4(h0, h1, h2, h3);
        *reinterpret_cast<uint4*>(ol + r * WW) = make_uint4(l0, l1, l2, l3);
    }
    xp[(size_t)plane * 256 + wi * 16 + wj] = s * (1.f / 64.f);
}

// ---------------- depthwise 3x3, smem-tiled rolling stencil (32-row tiles) --
__global__ void __launch_bounds__(128) dwconv_qk(
    const float* __restrict__ qkv, const float* __restrict__ w,
    const float* __restrict__ bias,
    bf16* __restrict__ qkh, bf16* __restrict__ qkl,
    float* __restrict__ vout)
{
    const int z = blockIdx.z;
    const int b = z >> 7, t = z & 127;
    const int x = threadIdx.x;
    const int y0 = blockIdx.y * 32;

    __shared__ float s0[34][136];
    __shared__ float s1[34][136];

    if (t < 64) {
        const float* pq = qkv + ((size_t)b * 192 + t) * HW;
        const float* pk = qkv + ((size_t)b * 192 + 64 + t) * HW;
        #pragma unroll
        for (int r = 0; r < 34; r++) {
            const int yy = y0 - 1 + r;
            const bool ok = (yy >= 0) && (yy < HH);
            s0[r][x + 1] = ok ? __ldg(pq + yy * WW + x) : 0.f;
            s1[r][x + 1] = ok ? __ldg(pk + yy * WW + x) : 0.f;
        }
        if (x < 2) {
            const int col = x ? 129 : 0;
            #pragma unroll
            for (int r = 0; r < 34; r++) { s0[r][col] = 0.f; s1[r][col] = 0.f; }
        }
        __syncthreads();

        float wq[9], wk[9];
        #pragma unroll
        for (int i = 0; i < 9; i++) {
            wq[i] = __ldg(&w[t * 9 + i]);
            wk[i] = __ldg(&w[(64 + t) * 9 + i]);
        }
        const float bq = __ldg(&bias[t]);
        const float bk = __ldg(&bias[64 + t]);

        bf16* oh = qkh + ((size_t)b * 64 + t) * HW + (size_t)y0 * WW + x;
        bf16* ol = qkl + ((size_t)b * 64 + t) * HW + (size_t)y0 * WW + x;

        float Aq = 0.f, Bq = 0.f, Ak = 0.f, Bk = 0.f;
        #pragma unroll
        for (int r = 0; r < 34; r++) {
            const float lq = s0[r][x], cq = s0[r][x + 1], rq = s0[r][x + 2];
            const float h0q = wq[0]*lq + wq[1]*cq + wq[2]*rq;
            const float h1q = wq[3]*lq + wq[4]*cq + wq[5]*rq;
            const float h2q = wq[6]*lq + wq[7]*cq + wq[8]*rq;
            const float lk = s1[r][x], ck = s1[r][x + 1], rk = s1[r][x + 2];
            const float h0k = wk[0]*lk + wk[1]*ck + wk[2]*rk;
            const float h1k = wk[3]*lk + wk[4]*ck + wk[5]*rk;
            const float h2k = wk[6]*lk + wk[7]*ck + wk[8]*rk;
            Aq += h2q; Ak += h2k;
            if (r >= 2) {
                const int o = r - 2;
                const float prod = (Aq + bq) * (Ak + bk);
                const bf16 hv = __float2bfloat16(prod);
                oh[o * WW] = hv;
                ol[o * WW] = __float2bfloat16(prod - __bfloat162float(hv));
            }
            Aq = Bq + h1q; Bq = h0q;
            Ak = Bk + h1k; Bk = h0k;
        }
    } else {
        const int cv = t - 64;
        const float* pv = qkv + ((size_t)b * 192 + 128 + cv) * HW;
        #pragma unroll
        for (int r = 0; r < 34; r++) {
            const int yy = y0 - 1 + r;
            s0[r][x + 1] = (yy >= 0 && yy < HH) ? __ldg(pv + yy * WW + x) : 0.f;
        }
        if (x < 2) {
            const int col = x ? 129 : 0;
            #pragma unroll
            for (int r = 0; r < 34; r++) s0[r][col] = 0.f;
        }
        __syncthreads();

        float wv[9];
        #pragma unroll
        for (int i = 0; i < 9; i++) wv[i] = __ldg(&w[(128 + cv) * 9 + i]);
        const float bv = __ldg(&bias[128 + cv]);

        float* ov = vout + ((size_t)b * 64 + cv) * HW + (size_t)y0 * WW + x;
        float A = 0.f, Bv = 0.f;
        #pragma unroll
        for (int r = 0; r < 34; r++) {
            const float lv = s0[r][x], cvv = s0[r][x + 1], rv = s0[r][x + 2];
            const float h0 = wv[0]*lv + wv[1]*cvv + wv[2]*rv;
            const float h1 = wv[3]*lv + wv[4]*cvv + wv[5]*rv;
            const float h2 = wv[6]*lv + wv[7]*cvv + wv[8]*rv;
            A += h2;
            if (r >= 2) ov[(r - 2) * WW] = A + bv;
            A = Bv + h1; Bv = h0;
        }
    }
}

// ---------------- kv = Wkv @ xp + bkv (SIMT, fp32) — R8 proven version ------
__global__ void __launch_bounds__(256) kv_simt(
    const float* __restrict__ xp, const float* __restrict__ Wkv,
    const float* __restrict__ bkv, float* __restrict__ kvout)
{
    const int idx = blockIdx.x * 256 + threadIdx.x;
    const int p  = idx & 255;
    const int oc = (idx >> 8) & 127;
    const int b  = idx >> 15;
    const float* xpb = xp + (size_t)b * 128 * 256 + p;
    const float* wr  = Wkv + oc * 128;
    float acc = __ldg(&bkv[oc]);
    #pragma unroll 8
    for (int c = 0; c < 128; c++)
        acc += __ldg(wr + c) * __ldg(xpb + c * 256);
    kvout[((size_t)b * 128 + oc) * 256 + p] = acc;
}

// ---------------- low-freq softmax attention (2 px/thread) -------------------
__global__ void __launch_bounds__(128) lowfreq_attn(
    const float* __restrict__ qg, const float* __restrict__ kv,
    bf16* __restrict__ ch, bf16* __restrict__ cl)
{
    const int b = blockIdx.z, h = blockIdx.y;
    const int p = blockIdx.x * 256 + threadIdx.x;

    __shared__ __align__(16) u64 ks2[256][8];
    __shared__ __align__(16) u64 vs2[256][8];

    const float* kvb = kv + (size_t)b * 128 * 256;
    for (int i = threadIdx.x; i < 2048; i += 128) {
        const int d2 = i >> 8, m = i & 255;
        ks2[m][d2] = pack2(kvb[(h * 16 + 2 * d2) * 256 + m],
                           kvb[(h * 16 + 2 * d2 + 1) * 256 + m]);
        vs2[m][d2] = pack2(kvb[(64 + h * 16 + 2 * d2) * 256 + m],
                           kvb[(64 + h * 16 + 2 * d2 + 1) * 256 + m]);
    }
    __syncthreads();

    u64 qa[8], qb[8];
    #pragma unroll
    for (int d2 = 0; d2 < 8; d2++) {
        const size_t base = (size_t)b * 64 * HW + (size_t)(h * 16 + 2 * d2) * HW + p;
        qa[d2] = pack2(0.25f * __ldg(&qg[base]),       0.25f * __ldg(&qg[base + HW]));
        qb[d2] = pack2(0.25f * __ldg(&qg[base + 128]), 0.25f * __ldg(&qg[base + HW + 128]));
    }

    float suma = 0.f, sumb = 0.f;
    u64 acca[8], accb[8];
    #pragma unroll
    for (int d2 = 0; d2 < 8; d2++) { acca[d2] = 0ull; accb[d2] = 0ull; }

    for (int m = 0; m < 256; m++) {
        u64 sa = 0ull, sb = 0ull;
        #pragma unroll
        for (int d2 = 0; d2 < 8; d2++) {
            const u64 kk = ks2[m][d2];
            sa = ffma2(qa[d2], kk, sa);
            sb = ffma2(qb[d2], kk, sb);
        }
        float a0, a1, b0, b1;
        unpack2(sa, a0, a1); unpack2(sb, b0, b1);
        const float ea = __expf(a0 + a1);
        const float eb = __expf(b0 + b1);
        suma += ea; sumb += eb;
        const u64 ea2 = pack2(ea, ea), eb2 = pack2(eb, eb);
        #pragma unroll
        for (int d2 = 0; d2 < 8; d2++) {
            const u64 vv = vs2[m][d2];
            acca[d2] = ffma2(ea2, vv, acca[d2]);
            accb[d2] = ffma2(eb2, vv, accb[d2]);
        }
    }

    const float inva = 1.f / suma, invb = 1.f / sumb;
    #pragma unroll
    for (int d2 = 0; d2 < 8; d2++) {
        float lo, hi;
        unpack2(acca[d2], lo, hi);
        const size_t base = ((size_t)b * 128 + 64 + h * 16 + 2 * d2) * HW + p;
        split1(lo * inva, ch, cl, base);
        split1(hi * inva, ch, cl, base + HW);
        unpack2(accb[d2], lo, hi);
        split1(lo * invb, ch, cl, base + 128);
        split1(hi * invb, ch, cl, base + HW + 128);
    }
}

// ---------------- launch (R8 structure: prep on main stream) -----------------
extern "C" void kernel_launch(void* const* d_in, const int* in_sizes, int n_in,
                              void* d_out, int out_size)
{
    const float* x     = (const float*)d_in[0];
    const float* Wqkv  = (const float*)d_in[1];
    const float* bqkv  = (const float*)d_in[2];
    const float* Wdw   = (const float*)d_in[3];
    const float* bdw   = (const float*)d_in[4];
    const float* Wa1   = (const float*)d_in[5];
    const float* ba1   = (const float*)d_in[6];
    const float* Wa2   = (const float*)d_in[7];
    const float* ba2   = (const float*)d_in[8];
    const float* Wq    = (const float*)d_in[9];
    const float* bq    = (const float*)d_in[10];
    const float* Wkv   = (const float*)d_in[11];
    const float* bkv   = (const float*)d_in[12];
    const float* Wproj = (const float*)d_in[13];
    const float* bproj = (const float*)d_in[14];
    float* out = (float*)d_out;

    float *qkv, *v, *qg, *kv, *xp, *b1;
    bf16 *xh, *xl, *qkh, *qkl, *ch, *cl;
    bf16 *w1h, *w1l, *wph, *wpl;
    cudaGetSymbolAddress((void**)&qkv, g_qkv);
    cudaGetSymbolAddress((void**)&v,   g_v);
    cudaGetSymbolAddress((void**)&qg,  g_qg);
    cudaGetSymbolAddress((void**)&kv,  g_kv);
    cudaGetSymbolAddress((void**)&xp,  g_xp);
    cudaGetSymbolAddress((void**)&b1,  g_b1);
    cudaGetSymbolAddress((void**)&xh,  g_xh);
    cudaGetSymbolAddress((void**)&xl,  g_xl);
    cudaGetSymbolAddress((void**)&qkh, g_qkh);
    cudaGetSymbolAddress((void**)&qkl, g_qkl);
    cudaGetSymbolAddress((void**)&ch,  g_ch);
    cudaGetSymbolAddress((void**)&cl,  g_cl);
    cudaGetSymbolAddress((void**)&w1h, g_w1h);
    cudaGetSymbolAddress((void**)&w1l, g_w1l);
    cudaGetSymbolAddress((void**)&wph, g_wph);
    cudaGetSymbolAddress((void**)&wpl, g_wpl);

    cudaFuncSetAttribute(gemm_bf16<true>,
                         cudaFuncAttributeMaxDynamicSharedMemorySize, SMEM_BYTES);
    cudaFuncSetAttribute(gemm_bf16<false>,
                         cudaFuncAttributeMaxDynamicSharedMemorySize, SMEM_BYTES);
    cudaFuncSetAttribute(fused_a1a2,
                         cudaFuncAttributeMaxDynamicSharedMemorySize, F2SMEM);

    static cudaStream_t s1 = nullptr;
    static cudaEvent_t e1 = nullptr, e2 = nullptr, e3 = nullptr;
    if (!s1) {
        cudaStreamCreateWithFlags(&s1, cudaStreamNonBlocking);
        cudaEventCreateWithFlags(&e1, cudaEventDisableTiming);
        cudaEventCreateWithFlags(&e2, cudaEventDisableTiming);
        cudaEventCreateWithFlags(&e3, cudaEventDisableTiming);
    }

    // 0) weight prep + x split/pool, both on main stream (R8 structure)
    prep_weights<<<225, 256>>>(Wqkv, Wq, Wa1, Wa2, Wproj, bqkv, bq);
    cvtpool<<<NB * 128, 256>>>(x, xh, xl, xp);
    cudaEventRecord(e1, 0);

    // 1) fused qkv+qg GEMM (main)
    gemm_bf16<true><<<dim3(HW / 256, 4, NB), 256, SMEM_BYTES>>>(
        xh, xl, w1h, w1l, b1, 128, HW,
        qkv, 192 * HW, qg, 64 * HW, 192);
    cudaEventRecord(e2, 0);

    // side branch: kv then attention (overlaps dwconv + fused)
    cudaStreamWaitEvent(s1, e1, 0);
    kv_simt<<<NB * 128 * 256 / 256, 256, 0, s1>>>(xp, Wkv, bkv, kv);
    cudaStreamWaitEvent(s1, e2, 0);
    lowfreq_attn<<<dim3(HW / 256, 4, NB), 128, 0, s1>>>(qg, kv, ch, cl);
    cudaEventRecord(e3, s1);

    // 2) depthwise 3x3 with q*k fusion (main; 32-row tiles)
    dwconv_qk<<<dim3(1, 4, NB * 128), 128>>>(qkv, Wdw, bdw, qkh, qkl, v);

    // 3+4) fused a1 -> swish -> a2 -> tanh*v (main) -> cat planes [0,64)
    fused_a1a2<<<dim3(HW / 128, NB), 256, F2SMEM>>>(qkh, qkl, ba1, ba2, v, ch, cl);

    // join, then 5) out = Wproj @ cat
    cudaStreamWaitEvent(0, e3, 0);
    gemm_bf16<false><<<dim3(HW / 256, 2, NB), 256, SMEM_BYTES>>>(
        ch, cl, wph, wpl, bproj, 128, HW,
        out, 128 * HW, nullptr, 0, 0);
}

// round 14
// speedup vs baseline: 1.2053x; 1.0789x over previous
#include <cuda_runtime.h>
#include <cuda_fp16.h>
#include <math.h>

#define HW 16384
#define HH 128
#define WW 128
#define NB 4

typedef unsigned long long u64;
typedef unsigned int u32;
typedef __half h16;

// ---------------- f32x2 helpers (attention) ---------------------------------
__device__ __forceinline__ u64 pack2(float lo, float hi) {
    u64 r; asm("mov.b64 %0,{%1,%2};" : "=l"(r) : "f"(lo), "f"(hi)); return r;
}
__device__ __forceinline__ void unpack2(u64 v, float& lo, float& hi) {
    asm("mov.b64 {%0,%1},%2;" : "=f"(lo), "=f"(hi) : "l"(v));
}
__device__ __forceinline__ u64 ffma2(u64 a, u64 b, u64 c) {
    u64 r; asm("fma.rn.f32x2 %0,%1,%2,%3;" : "=l"(r) : "l"(a), "l"(b), "l"(c)); return r;
}

// ---------------- scratch ----------------------------------------------------
__device__ __align__(256) float g_qkv [NB * 192 * HW];
__device__ __align__(256) float g_v   [NB * 64  * HW];
__device__ __align__(256) float g_qg  [NB * 64  * HW];
__device__ __align__(256) float g_kv  [NB * 128 * 256];
__device__ __align__(256) float g_xp  [NB * 128 * 256];
__device__ __align__(256) h16   g_xh  [NB * 128 * HW];
__device__ __align__(256) h16   g_qkh [NB * 64 * HW];
__device__ __align__(256) h16   g_ch  [NB * 128 * HW];
__device__ __align__(256) h16   g_cl  [NB * 128 * HW];
__device__ __align__(256) h16   g_w1h [256 * 128];
__device__ __align__(256) h16   g_w1l [256 * 128];
__device__ __align__(256) h16   g_wa1h[64 * 64];
__device__ __align__(256) h16   g_wa1l[64 * 64];
__device__ __align__(256) h16   g_wa2h[64 * 64];
__device__ __align__(256) h16   g_wa2l[64 * 64];
__device__ __align__(256) h16   g_wph [128 * 128];
__device__ __align__(256) h16   g_wpl [128 * 128];
__device__ __align__(256) float g_b1  [256];

// ---------------- mma / cp.async helpers ------------------------------------
__device__ __forceinline__ u32 smem_u32(const void* p) {
    u32 a;
    asm("{ .reg .u64 t; cvta.to.shared.u64 t, %1; cvt.u32.u64 %0, t; }"
        : "=r"(a) : "l"(p));
    return a;
}
__device__ __forceinline__ void ldm_x4(u32 a, u32& r0, u32& r1, u32& r2, u32& r3) {
    asm volatile("ldmatrix.sync.aligned.m8n8.x4.shared.b16 {%0,%1,%2,%3},[%4];"
                 : "=r"(r0), "=r"(r1), "=r"(r2), "=r"(r3) : "r"(a));
}
__device__ __forceinline__ void ldm_x4t(u32 a, u32& r0, u32& r1, u32& r2, u32& r3) {
    asm volatile("ldmatrix.sync.aligned.m8n8.x4.trans.shared.b16 {%0,%1,%2,%3},[%4];"
                 : "=r"(r0), "=r"(r1), "=r"(r2), "=r"(r3) : "r"(a));
}
__device__ __forceinline__ void mma_f16(float* c, const u32* a, u32 b0, u32 b1) {
    asm volatile(
        "mma.sync.aligned.m16n8k16.row.col.f32.f16.f16.f32 "
        "{%0,%1,%2,%3},{%4,%5,%6,%7},{%8,%9},{%0,%1,%2,%3};"
        : "+f"(c[0]), "+f"(c[1]), "+f"(c[2]), "+f"(c[3])
        : "r"(a[0]), "r"(a[1]), "r"(a[2]), "r"(a[3]), "r"(b0), "r"(b1));
}
__device__ __forceinline__ void cpa16(u32 d, const void* s) {
    asm volatile("cp.async.cg.shared.global [%0],[%1],16;" :: "r"(d), "l"(s));
}
__device__ __forceinline__ void cp_commit() {
    asm volatile("cp.async.commit_group;" ::: "memory");
}
template<int N> __device__ __forceinline__ void cp_wait() {
    asm volatile("cp.async.wait_group %0;" :: "n"(N) : "memory");
}
__device__ __forceinline__ void split2h(float x0, float x1, u32& h, u32& l) {
    h16 h0 = __float2half(x0);
    h16 h1 = __float2half(x1);
    float r0 = x0 - __half2float(h0);
    float r1 = x1 - __half2float(h1);
    __half2 hp = __halves2half2(h0, h1);
    __half2 lp = __halves2half2(__float2half(r0), __float2half(r1));
    h = *reinterpret_cast<u32*>(&hp);
    l = *reinterpret_cast<u32*>(&lp);
}
__device__ __forceinline__ void split1h(float x, h16* hd, h16* ld, size_t o) {
    h16 h = __float2half(x);
    hd[o] = h;
    ld[o] = __float2half(x - __half2float(h));
}

// ---------------- GEMM geometry ----------------------------------------------
#define APITCH 40
#define BPITCH 264
#define APB (64 * APITCH * 2)
#define BPB (32 * BPITCH * 2)
#define SMEM_G1 (4 * APB + 2 * BPB)      // X single-plane
#define SMEM_PR (4 * APB + 4 * BPB)      // X split

// ---------------- fp16 tensor-core GEMM --------------------------------------
// W split (Wh+Wl); X single plane unless XSPLIT. grid = (px, oc, batch).
template<bool DUAL, bool XSPLIT>
__global__ void __launch_bounds__(256, 2) gemm_f16(
    const h16* __restrict__ Xh, const h16* __restrict__ Xl,
    const h16* __restrict__ Wh, const h16* __restrict__ Wl,
    const float* __restrict__ bias, int IC, int NPIX,
    float* dstf, int dstf_stride,
    float* dstf2, int dst2_stride, int oc_split)
{
    extern __shared__ __align__(16) char sm[];
    const int tid = threadIdx.x;
    const int lane = tid & 31, warp = tid >> 5;
    const int px0 = blockIdx.x * 256;
    const int oc0 = blockIdx.y * 64;
    const int b   = blockIdx.z;
    const u32 smb = smem_u32(sm);
    constexpr int BPL = XSPLIT ? 2 : 1;

    const h16* Xhb = Xh + (size_t)b * IC * NPIX;
    const h16* Xlb = XSPLIT ? (Xl + (size_t)b * IC * NPIX) : nullptr;

    const int ar = tid >> 2, ac = (tid & 3) * 8;
    const int bc = (tid & 31) * 8, br0 = tid >> 5;
    const int nk = IC >> 5;

    float c[4][4][4];
    #pragma unroll
    for (int i = 0; i < 4; i++)
        #pragma unroll
        for (int j = 0; j < 4; j++)
            #pragma unroll
            for (int q = 0; q < 4; q++) c[i][j][q] = 0.f;

    auto issue = [&](int it) {
        const int st = it & 1;
        const int k0 = it << 5;
        u32 aD = smb + st * 2 * APB + (u32)(ar * APITCH + ac) * 2;
        const size_t aO = (size_t)(oc0 + ar) * IC + k0 + ac;
        cpa16(aD, Wh + aO);
        cpa16(aD + APB, Wl + aO);
        const u32 bBase = smb + 4 * APB + st * BPL * BPB;
        #pragma unroll
        for (int i = 0; i < 4; i++) {
            const int brr = br0 + i * 8;
            u32 bD = bBase + (u32)(brr * BPITCH + bc) * 2;
            const size_t bO = (size_t)(k0 + brr) * NPIX + px0 + bc;
            cpa16(bD, Xhb + bO);
            if (XSPLIT) cpa16(bD + BPB, Xlb + bO);
        }
        cp_commit();
    };

    issue(0);

    const int grp = lane >> 3, lr = lane & 7;
    const int r8  = (grp & 1) * 8 + lr;
    const int kh8 = (grp >> 1) * 8;
    const int wn32 = warp * 32;

    for (int it = 0; it < nk; it++) {
        if (it + 1 < nk) { issue(it + 1); cp_wait<1>(); }
        else             { cp_wait<0>(); }
        __syncthreads();
        const int st = it & 1;
        const u32 aHi = smb + st * 2 * APB, aLo = aHi + APB;
        const u32 bHi = smb + 4 * APB + st * BPL * BPB, bLo = bHi + BPB;
        #pragma unroll
        for (int ks = 0; ks < 2; ks++) {
            u32 bh[2][4], bl[2][4];
            #pragma unroll
            for (int g = 0; g < 2; g++) {
                const u32 off = (u32)((ks * 16 + r8) * BPITCH + wn32 + g * 16 + kh8) * 2;
                ldm_x4t(bHi + off, bh[g][0], bh[g][1], bh[g][2], bh[g][3]);
                if (XSPLIT)
                    ldm_x4t(bLo + off, bl[g][0], bl[g][1], bl[g][2], bl[g][3]);
            }
            #pragma unroll
            for (int mi = 0; mi < 4; mi++) {
                u32 ah[4], al[4];
                const u32 aoff = (u32)((mi * 16 + r8) * APITCH + ks * 16 + kh8) * 2;
                ldm_x4(aHi + aoff, ah[0], ah[1], ah[2], ah[3]);
                ldm_x4(aLo + aoff, al[0], al[1], al[2], al[3]);
                #pragma unroll
                for (int nj = 0; nj < 4; nj++) {
                    const int g = nj >> 1, s2 = nj & 1;
                    mma_f16(c[mi][nj], ah, bh[g][2 * s2], bh[g][2 * s2 + 1]);
                    mma_f16(c[mi][nj], al, bh[g][2 * s2], bh[g][2 * s2 + 1]);
                    if (XSPLIT)
                        mma_f16(c[mi][nj], ah, bl[g][2 * s2], bl[g][2 * s2 + 1]);
                }
            }
        }
        __syncthreads();
    }

    // ---- epilogue
    const int r4 = lane >> 2, c2 = (lane & 3) * 2;
    #pragma unroll
    for (int mi = 0; mi < 4; mi++) {
        #pragma unroll
        for (int h = 0; h < 2; h++) {
            const int oc = oc0 + mi * 16 + h * 8 + r4;
            const float bv = bias[oc];
            #pragma unroll
            for (int nj = 0; nj < 4; nj++) {
                const int px = px0 + wn32 + nj * 8 + c2;
                const float v0 = c[mi][nj][h * 2]     + bv;
                const float v1 = c[mi][nj][h * 2 + 1] + bv;
                if (DUAL) {
                    if (oc < oc_split)
                        *reinterpret_cast<float2*>(dstf + (size_t)b * dstf_stride
                            + (size_t)oc * NPIX + px) = make_float2(v0, v1);
                    else
                        *reinterpret_cast<float2*>(dstf2 + (size_t)b * dst2_stride
                            + (size_t)(oc - oc_split) * NPIX + px) = make_float2(v0, v1);
                } else {
                    *reinterpret_cast<float2*>(dstf + (size_t)b * dstf_stride
                        + (size_t)oc * NPIX + px) = make_float2(v0, v1);
                }
            }
        }
    }
}

// ---------------- fused a1->swish->a2->tanh*v, 128-px tiles -----------------
// Phase1: qk single fp16 (2 products). Phase2: a split in smem (3 products).
#define F2PITCH 136
#define F2STG (32 * F2PITCH * 2)
#define F2W1H (4 * F2STG)
#define F2W1L (F2W1H + 64 * 72 * 2)
#define F2W2H (F2W1L + 64 * 72 * 2)
#define F2W2L (F2W2H + 64 * 72 * 2)
#define F2SMEM (F2W2L + 64 * 72 * 2)

__global__ void __launch_bounds__(256, 3) fused_a1a2(
    const h16* __restrict__ qkh,
    const float* __restrict__ ba1, const float* __restrict__ ba2,
    const float* __restrict__ vsrc,
    h16* __restrict__ ch, h16* __restrict__ cl)
{
    extern __shared__ __align__(16) char sm[];
    const int tid = threadIdx.x;
    const int lane = tid & 31, warp = tid >> 5;
    const int px0 = blockIdx.x * 128;
    const int b   = blockIdx.y;
    const u32 smb = smem_u32(sm);

    const h16* qkhb = qkh + (size_t)b * 64 * HW + px0;

    {
        const int r = tid >> 2;
        const int sb = (tid & 3) * 32;
        const size_t go = (size_t)r * 64 + (tid & 3) * 16;
        const u32 so = (u32)(r * 72) * 2 + sb;
        cpa16(smb + F2W1H + so, g_wa1h + go); cpa16(smb + F2W1H + so + 16, g_wa1h + go + 8);
        cpa16(smb + F2W1L + so, g_wa1l + go); cpa16(smb + F2W1L + so + 16, g_wa1l + go + 8);
        cpa16(smb + F2W2H + so, g_wa2h + go); cpa16(smb + F2W2H + so + 16, g_wa2h + go + 8);
        cpa16(smb + F2W2L + so, g_wa2l + go); cpa16(smb + F2W2L + so + 16, g_wa2l + go + 8);
    }
    const int bc = (tid & 15) * 8, br0 = tid >> 4;
    auto issueB = [&](int chunk) {
        const u32 base = smb + chunk * F2STG;      // single plane per chunk
        #pragma unroll
        for (int i = 0; i < 2; i++) {
            const int brr = br0 + i * 16;
            const u32 d = base + (u32)(brr * F2PITCH + bc) * 2;
            const size_t o = (size_t)(chunk * 32 + brr) * HW + bc;
            cpa16(d, qkhb + o);
        }
        cp_commit();
    };
    issueB(0);
    issueB(1);

    const int grp = lane >> 3, lr = lane & 7;
    const int r8  = (grp & 1) * 8 + lr;
    const int kh8 = (grp >> 1) * 8;
    const int wn16 = warp * 16;
    const int r4 = lane >> 2, c2 = (lane & 3) * 2;

    float c[4][2][4];
    #pragma unroll
    for (int i = 0; i < 4; i++)
        #pragma unroll
        for (int j = 0; j < 2; j++)
            #pragma unroll
            for (int q = 0; q < 4; q++) c[i][j][q] = 0.f;

    // ---- phase 1 (2 products: W1h*b + W1l*b)
    for (int it = 0; it < 2; it++) {
        if (it == 0) cp_wait<1>(); else cp_wait<0>();
        __syncthreads();
        const u32 bBase = smb + it * F2STG;
        #pragma unroll
        for (int ks = 0; ks < 2; ks++) {
            u32 bh[4];
            const u32 off = (u32)((ks * 16 + r8) * F2PITCH + wn16 + kh8) * 2;
            ldm_x4t(bBase + off, bh[0], bh[1], bh[2], bh[3]);
            #pragma unroll
            for (int mi = 0; mi < 4; mi++) {
                u32 ah[4], al[4];
                const u32 aoff = (u32)((mi * 16 + r8) * 72 + it * 32 + ks * 16 + kh8) * 2;
                ldm_x4(smb + F2W1H + aoff, ah[0], ah[1], ah[2], ah[3]);
                ldm_x4(smb + F2W1L + aoff, al[0], al[1], al[2], al[3]);
                #pragma unroll
                for (int nj = 0; nj < 2; nj++) {
                    mma_f16(c[mi][nj], ah, bh[2 * nj], bh[2 * nj + 1]);
                    mma_f16(c[mi][nj], al, bh[2 * nj], bh[2 * nj + 1]);
                }
            }
        }
    }
    __syncthreads();

    // ---- swish + split a into smem (overwrites qk region; safe after sync)
    #pragma unroll
    for (int mi = 0; mi < 4; mi++) {
        #pragma unroll
        for (int h = 0; h < 2; h++) {
            const int oc = mi * 16 + h * 8 + r4;
            const float bv = __ldg(&ba1[oc]);
            const u32 halfb = (oc & 32) ? 2u * F2STG : 0u;
            #pragma unroll
            for (int nj = 0; nj < 2; nj++) {
                float v0 = c[mi][nj][h * 2]     + bv;
                float v1 = c[mi][nj][h * 2 + 1] + bv;
                v0 = v0 / (1.f + __expf(-v0));
                v1 = v1 / (1.f + __expf(-v1));
                u32 hp, lp; split2h(v0, v1, hp, lp);
                const u32 off = (u32)((oc & 31) * F2PITCH + wn16 + nj * 8 + c2) * 2;
                *reinterpret_cast<u32*>(sm + halfb + off)         = hp;
                *reinterpret_cast<u32*>(sm + halfb + F2STG + off) = lp;
            }
        }
    }
    __syncthreads();

    // ---- phase 2 (3 products, a split)
    #pragma unroll
    for (int i = 0; i < 4; i++)
        #pragma unroll
        for (int j = 0; j < 2; j++)
            #pragma unroll
            for (int q = 0; q < 4; q++) c[i][j][q] = 0.f;

    #pragma unroll
    for (int it = 0; it < 2; it++) {
        const u32 bHi = smb + it * 2 * F2STG, bLo = bHi + F2STG;
        #pragma unroll
        for (int ks = 0; ks < 2; ks++) {
            u32 bh[4], bl[4];
            const u32 off = (u32)((ks * 16 + r8) * F2PITCH + wn16 + kh8) * 2;
            ldm_x4t(bHi + off, bh[0], bh[1], bh[2], bh[3]);
            ldm_x4t(bLo + off, bl[0], bl[1], bl[2], bl[3]);
            #pragma unroll
            for (int mi = 0; mi < 4; mi++) {
                u32 ah[4], al[4];
                const u32 aoff = (u32)((mi * 16 + r8) * 72 + it * 32 + ks * 16 + kh8) * 2;
                ldm_x4(smb + F2W2H + aoff, ah[0], ah[1], ah[2], ah[3]);
                ldm_x4(smb + F2W2L + aoff, al[0], al[1], al[2], al[3]);
                #pragma unroll
                for (int nj = 0; nj < 2; nj++) {
                    mma_f16(c[mi][nj], ah, bh[2 * nj], bh[2 * nj + 1]);
                    mma_f16(c[mi][nj], ah, bl[2 * nj], bl[2 * nj + 1]);
                    mma_f16(c[mi][nj], al, bh[2 * nj], bh[2 * nj + 1]);
                }
            }
        }
    }

    #pragma unroll
    for (int mi = 0; mi < 4; mi++) {
        #pragma unroll
        for (int h = 0; h < 2; h++) {
            const int oc = mi * 16 + h * 8 + r4;
            const float bv = __ldg(&ba2[oc]);
            #pragma unroll
            for (int nj = 0; nj < 2; nj++) {
                const int px = px0 + wn16 + nj * 8 + c2;
                const float* vr = vsrc + ((size_t)b * 64 + oc) * HW + px;
                float v0 = tanhf((c[mi][nj][h * 2]     + bv) * 0.25f) * __ldg(vr);
                float v1 = tanhf((c[mi][nj][h * 2 + 1] + bv) * 0.25f) * __ldg(vr + 1);
                u32 hp, lp; split2h(v0, v1, hp, lp);
                const size_t o = ((size_t)b * 128 + oc) * HW + px;
                *reinterpret_cast<u32*>(ch + o) = hp;
                *reinterpret_cast<u32*>(cl + o) = lp;
            }
        }
    }
}

// ---------------- weight prep ------------------------------------------------
__device__ __forceinline__ void wsplit(float x, h16* hd, h16* ld, size_t o) {
    h16 h = __float2half(x);
    hd[o] = h;
    ld[o] = __float2half(x - __half2float(h));
}

__global__ void prep_weights(
    const float* __restrict__ Wqkv, const float* __restrict__ Wq,
    const float* __restrict__ Wa1, const float* __restrict__ Wa2,
    const float* __restrict__ Wproj,
    const float* __restrict__ bqkv, const float* __restrict__ bq)
{
    const int i = blockIdx.x * 256 + threadIdx.x;
    if (i < 32768) {
        float v = (i < 24576) ? Wqkv[i] : Wq[i - 24576];
        wsplit(v, g_w1h, g_w1l, i);
    } else if (i < 36864) {
        wsplit(Wa1[i - 32768], g_wa1h, g_wa1l, i - 32768);
    } else if (i < 40960) {
        wsplit(Wa2[i - 36864], g_wa2h, g_wa2l, i - 36864);
    } else if (i < 57344) {
        wsplit(Wproj[i - 40960], g_wph, g_wpl, i - 40960);
    } else if (i < 57600) {
        const int j = i - 57344;
        g_b1[j] = (j < 192) ? bqkv[j] : bq[j - 192];
    }
}

// ---------------- x -> fp16 + 8x8 avgpool (one pass) --------------------------
__global__ void __launch_bounds__(256) cvtpool(
    const float* __restrict__ x, h16* __restrict__ xh, float* __restrict__ xp)
{
    const int plane = blockIdx.x;
    const int t = threadIdx.x;
    const int wi = t >> 4, wj = t & 15;
    const float* sp = x + (size_t)plane * HW + (wi * 8) * WW + wj * 8;
    h16* oh = xh + (size_t)plane * HW + (wi * 8) * WW + wj * 8;

    float s = 0.f;
    #pragma unroll
    for (int r = 0; r < 8; r++) {
        const float4 a = *reinterpret_cast<const float4*>(sp + r * WW);
        const float4 b = *reinterpret_cast<const float4*>(sp + r * WW + 4);
        s += a.x + a.y + a.z + a.w + b.x + b.y + b.z + b.w;
        __half2 p0 = __floats2half2_rn(a.x, a.y);
        __half2 p1 = __floats2half2_rn(a.z, a.w);
        __half2 p2 = __floats2half2_rn(b.x, b.y);
        __half2 p3 = __floats2half2_rn(b.z, b.w);
        *reinterpret_cast<uint4*>(oh + r * WW) =
            make_uint4(*reinterpret_cast<u32*>(&p0), *reinterpret_cast<u32*>(&p1),
                       *reinterpret_cast<u32*>(&p2), *reinterpret_cast<u32*>(&p3));
    }
    xp[(size_t)plane * 256 + wi * 16 + wj] = s * (1.f / 64.f);
}

// ---------------- depthwise 3x3, smem-tiled rolling stencil (32-row tiles) --
__global__ void __launch_bounds__(128) dwconv_qk(
    const float* __restrict__ qkv, const float* __restrict__ w,
    const float* __restrict__ bias,
    h16* __restrict__ qkh, float* __restrict__ vout)
{
    const int z = blockIdx.z;
    const int b = z >> 7, t = z & 127;
    const int x = threadIdx.x;
    const int y0 = blockIdx.y * 32;

    __shared__ float s0[34][136];
    __shared__ float s1[34][136];

    if (t < 64) {
        const float* pq = qkv + ((size_t)b * 192 + t) * HW;
        const float* pk = qkv + ((size_t)b * 192 + 64 + t) * HW;
        #pragma unroll
        for (int r = 0; r < 34; r++) {
            const int yy = y0 - 1 + r;
            const bool ok = (yy >= 0) && (yy < HH);
            s0[r][x + 1] = ok ? __ldg(pq + yy * WW + x) : 0.f;
            s1[r][x + 1] = ok ? __ldg(pk + yy * WW + x) : 0.f;
        }
        if (x < 2) {
            const int col = x ? 129 : 0;
            #pragma unroll
            for (int r = 0; r < 34; r++) { s0[r][col] = 0.f; s1[r][col] = 0.f; }
        }
        __syncthreads();

        float wq[9], wk[9];
        #pragma unroll
        for (int i = 0; i < 9; i++) {
            wq[i] = __ldg(&w[t * 9 + i]);
            wk[i] = __ldg(&w[(64 + t) * 9 + i]);
        }
        const float bq = __ldg(&bias[t]);
        const float bk = __ldg(&bias[64 + t]);

        h16* oh = qkh + ((size_t)b * 64 + t) * HW + (size_t)y0 * WW + x;

        float Aq = 0.f, Bq = 0.f, Ak = 0.f, Bk = 0.f;
        #pragma unroll
        for (int r = 0; r < 34; r++) {
            const float lq = s0[r][x], cq = s0[r][x + 1], rq = s0[r][x + 2];
            const float h0q = wq[0]*lq + wq[1]*cq + wq[2]*rq;
            const float h1q = wq[3]*lq + wq[4]*cq + wq[5]*rq;
            const float h2q = wq[6]*lq + wq[7]*cq + wq[8]*rq;
            const float lk = s1[r][x], ck = s1[r][x + 1], rk = s1[r][x + 2];
            const float h0k = wk[0]*lk + wk[1]*ck + wk[2]*rk;
            const float h1k = wk[3]*lk + wk[4]*ck + wk[5]*rk;
            const float h2k = wk[6]*lk + wk[7]*ck + wk[8]*rk;
            Aq += h2q; Ak += h2k;
            if (r >= 2) {
                const float prod = (Aq + bq) * (Ak + bk);
                oh[(r - 2) * WW] = __float2half(prod);
            }
            Aq = Bq + h1q; Bq = h0q;
            Ak = Bk + h1k; Bk = h0k;
        }
    } else {
        const int cv = t - 64;
        const float* pv = qkv + ((size_t)b * 192 + 128 + cv) * HW;
        #pragma unroll
        for (int r = 0; r < 34; r++) {
            const int yy = y0 - 1 + r;
            s0[r][x + 1] = (yy >= 0 && yy < HH) ? __ldg(pv + yy * WW + x) : 0.f;
        }
        if (x < 2) {
            const int col = x ? 129 : 0;
            #pragma unroll
            for (int r = 0; r < 34; r++) s0[r][col] = 0.f;
        }
        __syncthreads();

        float wv[9];
        #pragma unroll
        for (int i = 0; i < 9; i++) wv[i] = __ldg(&w[(128 + cv) * 9 + i]);
        const float bv = __ldg(&bias[128 + cv]);

        float* ov = vout + ((size_t)b * 64 + cv) * HW + (size_t)y0 * WW + x;
        float A = 0.f, Bv = 0.f;
        #pragma unroll
        for (int r = 0; r < 34; r++) {
            const float lv = s0[r][x], cvv = s0[r][x + 1], rv = s0[r][x + 2];
            const float h0 = wv[0]*lv + wv[1]*cvv + wv[2]*rv;
            const float h1 = wv[3]*lv + wv[4]*cvv + wv[5]*rv;
            const float h2 = wv[6]*lv + wv[7]*cvv + wv[8]*rv;
            A += h2;
            if (r >= 2) ov[(r - 2) * WW] = A + bv;
            A = Bv + h1; Bv = h0;
        }
    }
}

// ---------------- kv = Wkv @ xp + bkv (SIMT, fp32) ---------------------------
__global__ void __launch_bounds__(256) kv_simt(
    const float* __restrict__ xp, const float* __restrict__ Wkv,
    const float* __restrict__ bkv, float* __restrict__ kvout)
{
    const int idx = blockIdx.x * 256 + threadIdx.x;
    const int p  = idx & 255;
    const int oc = (idx >> 8) & 127;
    const int b  = idx >> 15;
    const float* xpb = xp + (size_t)b * 128 * 256 + p;
    const float* wr  = Wkv + oc * 128;
    float acc = __ldg(&bkv[oc]);
    #pragma unroll 8
    for (int c = 0; c < 128; c++)
        acc += __ldg(wr + c) * __ldg(xpb + c * 256);
    kvout[((size_t)b * 128 + oc) * 256 + p] = acc;
}

// ---------------- low-freq softmax attention (2 px/thread) -------------------
__global__ void __launch_bounds__(128) lowfreq_attn(
    const float* __restrict__ qg, const float* __restrict__ kv,
    h16* __restrict__ ch, h16* __restrict__ cl)
{
    const int b = blockIdx.z, h = blockIdx.y;
    const int p = blockIdx.x * 256 + threadIdx.x;

    __shared__ __align__(16) u64 ks2[256][8];
    __shared__ __align__(16) u64 vs2[256][8];

    const float* kvb = kv + (size_t)b * 128 * 256;
    for (int i = threadIdx.x; i < 2048; i += 128) {
        const int d2 = i >> 8, m = i & 255;
        ks2[m][d2] = pack2(kvb[(h * 16 + 2 * d2) * 256 + m],
                           kvb[(h * 16 + 2 * d2 + 1) * 256 + m]);
        vs2[m][d2] = pack2(kvb[(64 + h * 16 + 2 * d2) * 256 + m],
                           kvb[(64 + h * 16 + 2 * d2 + 1) * 256 + m]);
    }
    __syncthreads();

    u64 qa[8], qb[8];
    #pragma unroll
    for (int d2 = 0; d2 < 8; d2++) {
        const size_t base = (size_t)b * 64 * HW + (size_t)(h * 16 + 2 * d2) * HW + p;
        qa[d2] = pack2(0.25f * __ldg(&qg[base]),       0.25f * __ldg(&qg[base + HW]));
        qb[d2] = pack2(0.25f * __ldg(&qg[base + 128]), 0.25f * __ldg(&qg[base + HW + 128]));
    }

    float suma = 0.f, sumb = 0.f;
    u64 acca[8], accb[8];
    #pragma unroll
    for (int d2 = 0; d2 < 8; d2++) { acca[d2] = 0ull; accb[d2] = 0ull; }

    for (int m = 0; m < 256; m++) {
        u64 sa = 0ull, sb = 0ull;
        #pragma unroll
        for (int d2 = 0; d2 < 8; d2++) {
            const u64 kk = ks2[m][d2];
            sa = ffma2(qa[d2], kk, sa);
            sb = ffma2(qb[d2], kk, sb);
        }
        float a0, a1, b0, b1;
        unpack2(sa, a0, a1); unpack2(sb, b0, b1);
        const float ea = __expf(a0 + a1);
        const float eb = __expf(b0 + b1);
        suma += ea; sumb += eb;
        const u64 ea2 = pack2(ea, ea), eb2 = pack2(eb, eb);
        #pragma unroll
        for (int d2 = 0; d2 < 8; d2++) {
            const u64 vv = vs2[m][d2];
            acca[d2] = ffma2(ea2, vv, acca[d2]);
            accb[d2] = ffma2(eb2, vv, accb[d2]);
        }
    }

    const float inva = 1.f / suma, invb = 1.f / sumb;
    #pragma unroll
    for (int d2 = 0; d2 < 8; d2++) {
        float lo, hi;
        unpack2(acca[d2], lo, hi);
        const size_t base = ((size_t)b * 128 + 64 + h * 16 + 2 * d2) * HW + p;
        split1h(lo * inva, ch, cl, base);
        split1h(hi * inva, ch, cl, base + HW);
        unpack2(accb[d2], lo, hi);
        split1h(lo * invb, ch, cl, base + 128);
        split1h(hi * invb, ch, cl, base + HW + 128);
    }
}

// ---------------- launch (R13-proven structure) ------------------------------
extern "C" void kernel_launch(void* const* d_in, const int* in_sizes, int n_in,
                              void* d_out, int out_size)
{
    const float* x     = (const float*)d_in[0];
    const float* Wqkv  = (const float*)d_in[1];
    const float* bqkv  = (const float*)d_in[2];
    const float* Wdw   = (const float*)d_in[3];
    const float* bdw   = (const float*)d_in[4];
    const float* Wa1   = (const float*)d_in[5];
    const float* ba1   = (const float*)d_in[6];
    const float* Wa2   = (const float*)d_in[7];
    const float* ba2   = (const float*)d_in[8];
    const float* Wq    = (const float*)d_in[9];
    const float* bq    = (const float*)d_in[10];
    const float* Wkv   = (const float*)d_in[11];
    const float* bkv   = (const float*)d_in[12];
    const float* Wproj = (const float*)d_in[13];
    const float* bproj = (const float*)d_in[14];
    float* out = (float*)d_out;

    float *qkv, *v, *qg, *kv, *xp, *b1;
    h16 *xh, *qkh, *ch, *cl;
    h16 *w1h, *w1l, *wph, *wpl;
    cudaGetSymbolAddress((void**)&qkv, g_qkv);
    cudaGetSymbolAddress((void**)&v,   g_v);
    cudaGetSymbolAddress((void**)&qg,  g_qg);
    cudaGetSymbolAddress((void**)&kv,  g_kv);
    cudaGetSymbolAddress((void**)&xp,  g_xp);
    cudaGetSymbolAddress((void**)&b1,  g_b1);
    cudaGetSymbolAddress((void**)&xh,  g_xh);
    cudaGetSymbolAddress((void**)&qkh, g_qkh);
    cudaGetSymbolAddress((void**)&ch,  g_ch);
    cudaGetSymbolAddress((void**)&cl,  g_cl);
    cudaGetSymbolAddress((void**)&w1h, g_w1h);
    cudaGetSymbolAddress((void**)&w1l, g_w1l);
    cudaGetSymbolAddress((void**)&wph, g_wph);
    cudaGetSymbolAddress((void**)&wpl, g_wpl);

    cudaFuncSetAttribute(gemm_f16<true, false>,
                         cudaFuncAttributeMaxDynamicSharedMemorySize, SMEM_G1);
    cudaFuncSetAttribute(gemm_f16<false, true>,
                         cudaFuncAttributeMaxDynamicSharedMemorySize, SMEM_PR);
    cudaFuncSetAttribute(fused_a1a2,
                         cudaFuncAttributeMaxDynamicSharedMemorySize, F2SMEM);

    static cudaStream_t s1 = nullptr;
    static cudaEvent_t e1 = nullptr, e2 = nullptr, e3 = nullptr;
    if (!s1) {
        cudaStreamCreateWithFlags(&s1, cudaStreamNonBlocking);
        cudaEventCreateWithFlags(&e1, cudaEventDisableTiming);
        cudaEventCreateWithFlags(&e2, cudaEventDisableTiming);
        cudaEventCreateWithFlags(&e3, cudaEventDisableTiming);
    }

    // 0) weight prep + x cvt/pool (main stream)
    prep_weights<<<225, 256>>>(Wqkv, Wq, Wa1, Wa2, Wproj, bqkv, bq);
    cvtpool<<<NB * 128, 256>>>(x, xh, xp);
    cudaEventRecord(e1, 0);

    // 1) fused qkv+qg GEMM (X single fp16, W split)
    gemm_f16<true, false><<<dim3(HW / 256, 4, NB), 256, SMEM_G1>>>(
        xh, nullptr, w1h, w1l, b1, 128, HW,
        qkv, 192 * HW, qg, 64 * HW, 192);
    cudaEventRecord(e2, 0);

    // side branch: kv then attention (overlaps dwconv + fused)
    cudaStreamWaitEvent(s1, e1, 0);
    kv_simt<<<NB * 128 * 256 / 256, 256, 0, s1>>>(xp, Wkv, bkv, kv);
    cudaStreamWaitEvent(s1, e2, 0);
    lowfreq_attn<<<dim3(HW / 256, 4, NB), 128, 0, s1>>>(qg, kv, ch, cl);
    cudaEventRecord(e3, s1);

    // 2) depthwise 3x3 with q*k fusion (32-row tiles)
    dwconv_qk<<<dim3(1, 4, NB * 128), 128>>>(qkv, Wdw, bdw, qkh, v);

    // 3+4) fused a1 -> swish -> a2 -> tanh*v -> cat planes [0,64)
    fused_a1a2<<<dim3(HW / 128, NB), 256, F2SMEM>>>(qkh, ba1, ba2, v, ch, cl);

    // join, then 5) out = Wproj @ cat (cat split fp16)
    cudaStreamWaitEvent(0, e3, 0);
    gemm_f16<false, true><<<dim3(HW / 256, 2, NB), 256, SMEM_PR>>>(
        ch, cl, wph, wpl, bproj, 128, HW,
        out, 128 * HW, nullptr, 0, 0);
}

// round 15
// speedup vs baseline: 1.3003x; 1.0788x over previous
#include <cuda_runtime.h>
#include <cuda_fp16.h>
#include <math.h>

#define HW 16384
#define HH 128
#define WW 128
#define NB 4

typedef unsigned long long u64;
typedef unsigned int u32;
typedef __half h16;

// ---------------- f32x2 helpers (attention) ---------------------------------
__device__ __forceinline__ u64 pack2(float lo, float hi) {
    u64 r; asm("mov.b64 %0,{%1,%2};" : "=l"(r) : "f"(lo), "f"(hi)); return r;
}
__device__ __forceinline__ void unpack2(u64 v, float& lo, float& hi) {
    asm("mov.b64 {%0,%1},%2;" : "=f"(lo), "=f"(hi) : "l"(v));
}
__device__ __forceinline__ u64 ffma2(u64 a, u64 b, u64 c) {
    u64 r; asm("fma.rn.f32x2 %0,%1,%2,%3;" : "=l"(r) : "l"(a), "l"(b), "l"(c)); return r;
}

// ---------------- scratch ----------------------------------------------------
__device__ __align__(256) float g_qkv [NB * 192 * HW];
__device__ __align__(256) float g_v   [NB * 64  * HW];
__device__ __align__(256) float g_qg  [NB * 64  * HW];
__device__ __align__(256) float g_kv  [NB * 128 * 256];
__device__ __align__(256) float g_xp  [NB * 128 * 256];
__device__ __align__(256) h16   g_xh  [NB * 128 * HW];
__device__ __align__(256) h16   g_qkh [NB * 64 * HW];
__device__ __align__(256) h16   g_ch  [NB * 128 * HW];
__device__ __align__(256) h16   g_w1h [256 * 128];
__device__ __align__(256) h16   g_wa1h[64 * 64];
__device__ __align__(256) h16   g_wa2h[64 * 64];
__device__ __align__(256) h16   g_wa2l[64 * 64];
__device__ __align__(256) h16   g_wph [128 * 128];
__device__ __align__(256) h16   g_wpl [128 * 128];
__device__ __align__(256) float g_b1  [256];

// ---------------- mma / cp.async helpers ------------------------------------
__device__ __forceinline__ u32 smem_u32(const void* p) {
    u32 a;
    asm("{ .reg .u64 t; cvta.to.shared.u64 t, %1; cvt.u32.u64 %0, t; }"
        : "=r"(a) : "l"(p));
    return a;
}
__device__ __forceinline__ void ldm_x4(u32 a, u32& r0, u32& r1, u32& r2, u32& r3) {
    asm volatile("ldmatrix.sync.aligned.m8n8.x4.shared.b16 {%0,%1,%2,%3},[%4];"
                 : "=r"(r0), "=r"(r1), "=r"(r2), "=r"(r3) : "r"(a));
}
__device__ __forceinline__ void ldm_x4t(u32 a, u32& r0, u32& r1, u32& r2, u32& r3) {
    asm volatile("ldmatrix.sync.aligned.m8n8.x4.trans.shared.b16 {%0,%1,%2,%3},[%4];"
                 : "=r"(r0), "=r"(r1), "=r"(r2), "=r"(r3) : "r"(a));
}
__device__ __forceinline__ void mma_f16(float* c, const u32* a, u32 b0, u32 b1) {
    asm volatile(
        "mma.sync.aligned.m16n8k16.row.col.f32.f16.f16.f32 "
        "{%0,%1,%2,%3},{%4,%5,%6,%7},{%8,%9},{%0,%1,%2,%3};"
        : "+f"(c[0]), "+f"(c[1]), "+f"(c[2]), "+f"(c[3])
        : "r"(a[0]), "r"(a[1]), "r"(a[2]), "r"(a[3]), "r"(b0), "r"(b1));
}
__device__ __forceinline__ void cpa16(u32 d, const void* s) {
    asm volatile("cp.async.cg.shared.global [%0],[%1],16;" :: "r"(d), "l"(s));
}
__device__ __forceinline__ void cp_commit() {
    asm volatile("cp.async.commit_group;" ::: "memory");
}
template<int N> __device__ __forceinline__ void cp_wait() {
    asm volatile("cp.async.wait_group %0;" :: "n"(N) : "memory");
}
__device__ __forceinline__ void split2h(float x0, float x1, u32& h, u32& l) {
    h16 h0 = __float2half(x0);
    h16 h1 = __float2half(x1);
    float r0 = x0 - __half2float(h0);
    float r1 = x1 - __half2float(h1);
    __half2 hp = __halves2half2(h0, h1);
    __half2 lp = __halves2half2(__float2half(r0), __float2half(r1));
    h = *reinterpret_cast<u32*>(&hp);
    l = *reinterpret_cast<u32*>(&lp);
}

// ---------------- GEMM geometry ----------------------------------------------
#define APITCH 40
#define BPITCH 264
#define APB (64 * APITCH * 2)
#define BPB (32 * BPITCH * 2)
#define SMEM_G1 (2 * APB + 2 * BPB)      // W single, X single
#define SMEM_PR (4 * APB + 2 * BPB)      // W split,  X single

// ---------------- fp16 tensor-core GEMM --------------------------------------
// grid = (px, oc, batch).  Products: h*h always; +Wl*h if WSPLIT.
template<bool DUAL, bool WSPLIT>
__global__ void __launch_bounds__(256, 2) gemm_f16(
    const h16* __restrict__ Xh,
    const h16* __restrict__ Wh, const h16* __restrict__ Wl,
    const float* __restrict__ bias, int IC, int NPIX,
    float* dstf, int dstf_stride,
    float* dstf2, int dst2_stride, int oc_split)
{
    extern __shared__ __align__(16) char sm[];
    const int tid = threadIdx.x;
    const int lane = tid & 31, warp = tid >> 5;
    const int px0 = blockIdx.x * 256;
    const int oc0 = blockIdx.y * 64;
    const int b   = blockIdx.z;
    const u32 smb = smem_u32(sm);
    constexpr int APL = WSPLIT ? 2 : 1;

    const h16* Xhb = Xh + (size_t)b * IC * NPIX;

    const int ar = tid >> 2, ac = (tid & 3) * 8;
    const int bc = (tid & 31) * 8, br0 = tid >> 5;
    const int nk = IC >> 5;

    float c[4][4][4];
    #pragma unroll
    for (int i = 0; i < 4; i++)
        #pragma unroll
        for (int j = 0; j < 4; j++)
            #pragma unroll
            for (int q = 0; q < 4; q++) c[i][j][q] = 0.f;

    auto issue = [&](int it) {
        const int st = it & 1;
        const int k0 = it << 5;
        u32 aD = smb + st * APL * APB + (u32)(ar * APITCH + ac) * 2;
        const size_t aO = (size_t)(oc0 + ar) * IC + k0 + ac;
        cpa16(aD, Wh + aO);
        if (WSPLIT) cpa16(aD + APB, Wl + aO);
        const u32 bBase = smb + 2 * APL * APB + st * BPB;
        #pragma unroll
        for (int i = 0; i < 4; i++) {
            const int brr = br0 + i * 8;
            u32 bD = bBase + (u32)(brr * BPITCH + bc) * 2;
            const size_t bO = (size_t)(k0 + brr) * NPIX + px0 + bc;
            cpa16(bD, Xhb + bO);
        }
        cp_commit();
    };

    issue(0);

    const int grp = lane >> 3, lr = lane & 7;
    const int r8  = (grp & 1) * 8 + lr;
    const int kh8 = (grp >> 1) * 8;
    const int wn32 = warp * 32;

    for (int it = 0; it < nk; it++) {
        if (it + 1 < nk) { issue(it + 1); cp_wait<1>(); }
        else             { cp_wait<0>(); }
        __syncthreads();
        const int st = it & 1;
        const u32 aHi = smb + st * APL * APB, aLo = aHi + APB;
        const u32 bHi = smb + 2 * APL * APB + st * BPB;
        #pragma unroll
        for (int ks = 0; ks < 2; ks++) {
            u32 bh[2][4];
            #pragma unroll
            for (int g = 0; g < 2; g++) {
                const u32 off = (u32)((ks * 16 + r8) * BPITCH + wn32 + g * 16 + kh8) * 2;
                ldm_x4t(bHi + off, bh[g][0], bh[g][1], bh[g][2], bh[g][3]);
            }
            #pragma unroll
            for (int mi = 0; mi < 4; mi++) {
                u32 ah[4], al[4];
                const u32 aoff = (u32)((mi * 16 + r8) * APITCH + ks * 16 + kh8) * 2;
                ldm_x4(aHi + aoff, ah[0], ah[1], ah[2], ah[3]);
                if (WSPLIT) ldm_x4(aLo + aoff, al[0], al[1], al[2], al[3]);
                #pragma unroll
                for (int nj = 0; nj < 4; nj++) {
                    const int g = nj >> 1, s2 = nj & 1;
                    mma_f16(c[mi][nj], ah, bh[g][2 * s2], bh[g][2 * s2 + 1]);
                    if (WSPLIT)
                        mma_f16(c[mi][nj], al, bh[g][2 * s2], bh[g][2 * s2 + 1]);
                }
            }
        }
        __syncthreads();
    }

    // ---- epilogue
    const int r4 = lane >> 2, c2 = (lane & 3) * 2;
    #pragma unroll
    for (int mi = 0; mi < 4; mi++) {
        #pragma unroll
        for (int h = 0; h < 2; h++) {
            const int oc = oc0 + mi * 16 + h * 8 + r4;
            const float bv = bias[oc];
            #pragma unroll
            for (int nj = 0; nj < 4; nj++) {
                const int px = px0 + wn32 + nj * 8 + c2;
                const float v0 = c[mi][nj][h * 2]     + bv;
                const float v1 = c[mi][nj][h * 2 + 1] + bv;
                if (DUAL) {
                    if (oc < oc_split)
                        *reinterpret_cast<float2*>(dstf + (size_t)b * dstf_stride
                            + (size_t)oc * NPIX + px) = make_float2(v0, v1);
                    else
                        *reinterpret_cast<float2*>(dstf2 + (size_t)b * dst2_stride
                            + (size_t)(oc - oc_split) * NPIX + px) = make_float2(v0, v1);
                } else {
                    *reinterpret_cast<float2*>(dstf + (size_t)b * dstf_stride
                        + (size_t)oc * NPIX + px) = make_float2(v0, v1);
                }
            }
        }
    }
}

// ---------------- fused a1->swish->a2->tanh*v, 128-px tiles -----------------
// Phase1: Wa1 single x qk single (1 product). Phase2: Wa2 split + a split (3).
#define F2PITCH 136
#define F2STG (32 * F2PITCH * 2)
#define F2W1H (4 * F2STG)
#define F2W2H (F2W1H + 64 * 72 * 2)
#define F2W2L (F2W2H + 64 * 72 * 2)
#define F2SMEM (F2W2L + 64 * 72 * 2)

__global__ void __launch_bounds__(256, 3) fused_a1a2(
    const h16* __restrict__ qkh,
    const float* __restrict__ ba1, const float* __restrict__ ba2,
    const float* __restrict__ vsrc,
    h16* __restrict__ ch)
{
    extern __shared__ __align__(16) char sm[];
    const int tid = threadIdx.x;
    const int lane = tid & 31, warp = tid >> 5;
    const int px0 = blockIdx.x * 128;
    const int b   = blockIdx.y;
    const u32 smb = smem_u32(sm);

    const h16* qkhb = qkh + (size_t)b * 64 * HW + px0;

    {
        const int r = tid >> 2;
        const int sb = (tid & 3) * 32;
        const size_t go = (size_t)r * 64 + (tid & 3) * 16;
        const u32 so = (u32)(r * 72) * 2 + sb;
        cpa16(smb + F2W1H + so, g_wa1h + go); cpa16(smb + F2W1H + so + 16, g_wa1h + go + 8);
        cpa16(smb + F2W2H + so, g_wa2h + go); cpa16(smb + F2W2H + so + 16, g_wa2h + go + 8);
        cpa16(smb + F2W2L + so, g_wa2l + go); cpa16(smb + F2W2L + so + 16, g_wa2l + go + 8);
    }
    const int bc = (tid & 15) * 8, br0 = tid >> 4;
    auto issueB = [&](int chunk) {
        const u32 base = smb + chunk * F2STG;
        #pragma unroll
        for (int i = 0; i < 2; i++) {
            const int brr = br0 + i * 16;
            const u32 d = base + (u32)(brr * F2PITCH + bc) * 2;
            const size_t o = (size_t)(chunk * 32 + brr) * HW + bc;
            cpa16(d, qkhb + o);
        }
        cp_commit();
    };
    issueB(0);
    issueB(1);

    const int grp = lane >> 3, lr = lane & 7;
    const int r8  = (grp & 1) * 8 + lr;
    const int kh8 = (grp >> 1) * 8;
    const int wn16 = warp * 16;
    const int r4 = lane >> 2, c2 = (lane & 3) * 2;

    float c[4][2][4];
    #pragma unroll
    for (int i = 0; i < 4; i++)
        #pragma unroll
        for (int j = 0; j < 2; j++)
            #pragma unroll
            for (int q = 0; q < 4; q++) c[i][j][q] = 0.f;

    // ---- phase 1 (1 product)
    for (int it = 0; it < 2; it++) {
        if (it == 0) cp_wait<1>(); else cp_wait<0>();
        __syncthreads();
        const u32 bBase = smb + it * F2STG;
        #pragma unroll
        for (int ks = 0; ks < 2; ks++) {
            u32 bh[4];
            const u32 off = (u32)((ks * 16 + r8) * F2PITCH + wn16 + kh8) * 2;
            ldm_x4t(bBase + off, bh[0], bh[1], bh[2], bh[3]);
            #pragma unroll
            for (int mi = 0; mi < 4; mi++) {
                u32 ah[4];
                const u32 aoff = (u32)((mi * 16 + r8) * 72 + it * 32 + ks * 16 + kh8) * 2;
                ldm_x4(smb + F2W1H + aoff, ah[0], ah[1], ah[2], ah[3]);
                #pragma unroll
                for (int nj = 0; nj < 2; nj++)
                    mma_f16(c[mi][nj], ah, bh[2 * nj], bh[2 * nj + 1]);
            }
        }
    }
    __syncthreads();

    // ---- swish + split a into smem
    #pragma unroll
    for (int mi = 0; mi < 4; mi++) {
        #pragma unroll
        for (int h = 0; h < 2; h++) {
            const int oc = mi * 16 + h * 8 + r4;
            const float bv = __ldg(&ba1[oc]);
            const u32 halfb = (oc & 32) ? 2u * F2STG : 0u;
            #pragma unroll
            for (int nj = 0; nj < 2; nj++) {
                float v0 = c[mi][nj][h * 2]     + bv;
                float v1 = c[mi][nj][h * 2 + 1] + bv;
                v0 = v0 / (1.f + __expf(-v0));
                v1 = v1 / (1.f + __expf(-v1));
                u32 hp, lp; split2h(v0, v1, hp, lp);
                const u32 off = (u32)((oc & 31) * F2PITCH + wn16 + nj * 8 + c2) * 2;
                *reinterpret_cast<u32*>(sm + halfb + off)         = hp;
                *reinterpret_cast<u32*>(sm + halfb + F2STG + off) = lp;
            }
        }
    }
    __syncthreads();

    // ---- phase 2 (3 products, a split)
    #pragma unroll
    for (int i = 0; i < 4; i++)
        #pragma unroll
        for (int j = 0; j < 2; j++)
            #pragma unroll
            for (int q = 0; q < 4; q++) c[i][j][q] = 0.f;

    #pragma unroll
    for (int it = 0; it < 2; it++) {
        const u32 bHi = smb + it * 2 * F2STG, bLo = bHi + F2STG;
        #pragma unroll
        for (int ks = 0; ks < 2; ks++) {
            u32 bh[4], bl[4];
            const u32 off = (u32)((ks * 16 + r8) * F2PITCH + wn16 + kh8) * 2;
            ldm_x4t(bHi + off, bh[0], bh[1], bh[2], bh[3]);
            ldm_x4t(bLo + off, bl[0], bl[1], bl[2], bl[3]);
            #pragma unroll
            for (int mi = 0; mi < 4; mi++) {
                u32 ah[4], al[4];
                const u32 aoff = (u32)((mi * 16 + r8) * 72 + it * 32 + ks * 16 + kh8) * 2;
                ldm_x4(smb + F2W2H + aoff, ah[0], ah[1], ah[2], ah[3]);
                ldm_x4(smb + F2W2L + aoff, al[0], al[1], al[2], al[3]);
                #pragma unroll
                for (int nj = 0; nj < 2; nj++) {
                    mma_f16(c[mi][nj], ah, bh[2 * nj], bh[2 * nj + 1]);
                    mma_f16(c[mi][nj], ah, bl[2 * nj], bl[2 * nj + 1]);
                    mma_f16(c[mi][nj], al, bh[2 * nj], bh[2 * nj + 1]);
                }
            }
        }
    }

    #pragma unroll
    for (int mi = 0; mi < 4; mi++) {
        #pragma unroll
        for (int h = 0; h < 2; h++) {
            const int oc = mi * 16 + h * 8 + r4;
            const float bv = __ldg(&ba2[oc]);
            #pragma unroll
            for (int nj = 0; nj < 2; nj++) {
                const int px = px0 + wn16 + nj * 8 + c2;
                const float* vr = vsrc + ((size_t)b * 64 + oc) * HW + px;
                float v0 = tanhf((c[mi][nj][h * 2]     + bv) * 0.25f) * __ldg(vr);
                float v1 = tanhf((c[mi][nj][h * 2 + 1] + bv) * 0.25f) * __ldg(vr + 1);
                __half2 hp = __floats2half2_rn(v0, v1);
                const size_t o = ((size_t)b * 128 + oc) * HW + px;
                *reinterpret_cast<u32*>(ch + o) = *reinterpret_cast<u32*>(&hp);
            }
        }
    }
}

// ---------------- weight prep ------------------------------------------------
__device__ __forceinline__ void wsplit(float x, h16* hd, h16* ld, size_t o) {
    h16 h = __float2half(x);
    hd[o] = h;
    ld[o] = __float2half(x - __half2float(h));
}

__global__ void prep_weights(
    const float* __restrict__ Wqkv, const float* __restrict__ Wq,
    const float* __restrict__ Wa1, const float* __restrict__ Wa2,
    const float* __restrict__ Wproj,
    const float* __restrict__ bqkv, const float* __restrict__ bq)
{
    const int i = blockIdx.x * 256 + threadIdx.x;
    if (i < 32768) {
        float v = (i < 24576) ? Wqkv[i] : Wq[i - 24576];
        g_w1h[i] = __float2half(v);
    } else if (i < 36864) {
        g_wa1h[i - 32768] = __float2half(Wa1[i - 32768]);
    } else if (i < 40960) {
        wsplit(Wa2[i - 36864], g_wa2h, g_wa2l, i - 36864);
    } else if (i < 57344) {
        wsplit(Wproj[i - 40960], g_wph, g_wpl, i - 40960);
    } else if (i < 57600) {
        const int j = i - 57344;
        g_b1[j] = (j < 192) ? bqkv[j] : bq[j - 192];
    }
}

// ---------------- x -> fp16 + 8x8 avgpool (one pass) --------------------------
__global__ void __launch_bounds__(256) cvtpool(
    const float* __restrict__ x, h16* __restrict__ xh, float* __restrict__ xp)
{
    const int plane = blockIdx.x;
    const int t = threadIdx.x;
    const int wi = t >> 4, wj = t & 15;
    const float* sp = x + (size_t)plane * HW + (wi * 8) * WW + wj * 8;
    h16* oh = xh + (size_t)plane * HW + (wi * 8) * WW + wj * 8;

    float s = 0.f;
    #pragma unroll
    for (int r = 0; r < 8; r++) {
        const float4 a = *reinterpret_cast<const float4*>(sp + r * WW);
        const float4 b = *reinterpret_cast<const float4*>(sp + r * WW + 4);
        s += a.x + a.y + a.z + a.w + b.x + b.y + b.z + b.w;
        __half2 p0 = __floats2half2_rn(a.x, a.y);
        __half2 p1 = __floats2half2_rn(a.z, a.w);
        __half2 p2 = __floats2half2_rn(b.x, b.y);
        __half2 p3 = __floats2half2_rn(b.z, b.w);
        *reinterpret_cast<uint4*>(oh + r * WW) =
            make_uint4(*reinterpret_cast<u32*>(&p0), *reinterpret_cast<u32*>(&p1),
                       *reinterpret_cast<u32*>(&p2), *reinterpret_cast<u32*>(&p3));
    }
    xp[(size_t)plane * 256 + wi * 16 + wj] = s * (1.f / 64.f);
}

// ---------------- depthwise 3x3, smem-tiled rolling stencil (32-row tiles) --
__global__ void __launch_bounds__(128) dwconv_qk(
    const float* __restrict__ qkv, const float* __restrict__ w,
    const float* __restrict__ bias,
    h16* __restrict__ qkh, float* __restrict__ vout)
{
    const int z = blockIdx.z;
    const int b = z >> 7, t = z & 127;
    const int x = threadIdx.x;
    const int y0 = blockIdx.y * 32;

    __shared__ float s0[34][136];
    __shared__ float s1[34][136];

    if (t < 64) {
        const float* pq = qkv + ((size_t)b * 192 + t) * HW;
        const float* pk = qkv + ((size_t)b * 192 + 64 + t) * HW;
        #pragma unroll
        for (int r = 0; r < 34; r++) {
            const int yy = y0 - 1 + r;
            const bool ok = (yy >= 0) && (yy < HH);
            s0[r][x + 1] = ok ? __ldg(pq + yy * WW + x) : 0.f;
            s1[r][x + 1] = ok ? __ldg(pk + yy * WW + x) : 0.f;
        }
        if (x < 2) {
            const int col = x ? 129 : 0;
            #pragma unroll
            for (int r = 0; r < 34; r++) { s0[r][col] = 0.f; s1[r][col] = 0.f; }
        }
        __syncthreads();

        float wq[9], wk[9];
        #pragma unroll
        for (int i = 0; i < 9; i++) {
            wq[i] = __ldg(&w[t * 9 + i]);
            wk[i] = __ldg(&w[(64 + t) * 9 + i]);
        }
        const float bq = __ldg(&bias[t]);
        const float bk = __ldg(&bias[64 + t]);

        h16* oh = qkh + ((size_t)b * 64 + t) * HW + (size_t)y0 * WW + x;

        float Aq = 0.f, Bq = 0.f, Ak = 0.f, Bk = 0.f;
        #pragma unroll
        for (int r = 0; r < 34; r++) {
            const float lq = s0[r][x], cq = s0[r][x + 1], rq = s0[r][x + 2];
            const float h0q = wq[0]*lq + wq[1]*cq + wq[2]*rq;
            const float h1q = wq[3]*lq + wq[4]*cq + wq[5]*rq;
            const float h2q = wq[6]*lq + wq[7]*cq + wq[8]*rq;
            const float lk = s1[r][x], ck = s1[r][x + 1], rk = s1[r][x + 2];
            const float h0k = wk[0]*lk + wk[1]*ck + wk[2]*rk;
            const float h1k = wk[3]*lk + wk[4]*ck + wk[5]*rk;
            const float h2k = wk[6]*lk + wk[7]*ck + wk[8]*rk;
            Aq += h2q; Ak += h2k;
            if (r >= 2) {
                const float prod = (Aq + bq) * (Ak + bk);
                oh[(r - 2) * WW] = __float2half(prod);
            }
            Aq = Bq + h1q; Bq = h0q;
            Ak = Bk + h1k; Bk = h0k;
        }
    } else {
        const int cv = t - 64;
        const float* pv = qkv + ((size_t)b * 192 + 128 + cv) * HW;
        #pragma unroll
        for (int r = 0; r < 34; r++) {
            const int yy = y0 - 1 + r;
            s0[r][x + 1] = (yy >= 0 && yy < HH) ? __ldg(pv + yy * WW + x) : 0.f;
        }
        if (x < 2) {
            const int col = x ? 129 : 0;
            #pragma unroll
            for (int r = 0; r < 34; r++) s0[r][col] = 0.f;
        }
        __syncthreads();

        float wv[9];
        #pragma unroll
        for (int i = 0; i < 9; i++) wv[i] = __ldg(&w[(128 + cv) * 9 + i]);
        const float bv = __ldg(&bias[128 + cv]);

        float* ov = vout + ((size_t)b * 64 + cv) * HW + (size_t)y0 * WW + x;
        float A = 0.f, Bv = 0.f;
        #pragma unroll
        for (int r = 0; r < 34; r++) {
            const float lv = s0[r][x], cvv = s0[r][x + 1], rv = s0[r][x + 2];
            const float h0 = wv[0]*lv + wv[1]*cvv + wv[2]*rv;
            const float h1 = wv[3]*lv + wv[4]*cvv + wv[5]*rv;
            const float h2 = wv[6]*lv + wv[7]*cvv + wv[8]*rv;
            A += h2;
            if (r >= 2) ov[(r - 2) * WW] = A + bv;
            A = Bv + h1; Bv = h0;
        }
    }
}

// ---------------- kv = Wkv @ xp + bkv (SIMT, fp32) ---------------------------
__global__ void __launch_bounds__(256) kv_simt(
    const float* __restrict__ xp, const float* __restrict__ Wkv,
    const float* __restrict__ bkv, float* __restrict__ kvout)
{
    const int idx = blockIdx.x * 256 + threadIdx.x;
    const int p  = idx & 255;
    const int oc = (idx >> 8) & 127;
    const int b  = idx >> 15;
    const float* xpb = xp + (size_t)b * 128 * 256 + p;
    const float* wr  = Wkv + oc * 128;
    float acc = __ldg(&bkv[oc]);
    #pragma unroll 8
    for (int c = 0; c < 128; c++)
        acc += __ldg(wr + c) * __ldg(xpb + c * 256);
    kvout[((size_t)b * 128 + oc) * 256 + p] = acc;
}

// ---------------- low-freq softmax attention (2 px/thread) -------------------
__global__ void __launch_bounds__(128) lowfreq_attn(
    const float* __restrict__ qg, const float* __restrict__ kv,
    h16* __restrict__ ch)
{
    const int b = blockIdx.z, h = blockIdx.y;
    const int p = blockIdx.x * 256 + threadIdx.x;

    __shared__ __align__(16) u64 ks2[256][8];
    __shared__ __align__(16) u64 vs2[256][8];

    const float* kvb = kv + (size_t)b * 128 * 256;
    for (int i = threadIdx.x; i < 2048; i += 128) {
        const int d2 = i >> 8, m = i & 255;
        ks2[m][d2] = pack2(kvb[(h * 16 + 2 * d2) * 256 + m],
                           kvb[(h * 16 + 2 * d2 + 1) * 256 + m]);
        vs2[m][d2] = pack2(kvb[(64 + h * 16 + 2 * d2) * 256 + m],
                           kvb[(64 + h * 16 + 2 * d2 + 1) * 256 + m]);
    }
    __syncthreads();

    u64 qa[8], qb[8];
    #pragma unroll
    for (int d2 = 0; d2 < 8; d2++) {
        const size_t base = (size_t)b * 64 * HW + (size_t)(h * 16 + 2 * d2) * HW + p;
        qa[d2] = pack2(0.25f * __ldg(&qg[base]),       0.25f * __ldg(&qg[base + HW]));
        qb[d2] = pack2(0.25f * __ldg(&qg[base + 128]), 0.25f * __ldg(&qg[base + HW + 128]));
    }

    float suma = 0.f, sumb = 0.f;
    u64 acca[8], accb[8];
    #pragma unroll
    for (int d2 = 0; d2 < 8; d2++) { acca[d2] = 0ull; accb[d2] = 0ull; }

    for (int m = 0; m < 256; m++) {
        u64 sa = 0ull, sb = 0ull;
        #pragma unroll
        for (int d2 = 0; d2 < 8; d2++) {
            const u64 kk = ks2[m][d2];
            sa = ffma2(qa[d2], kk, sa);
            sb = ffma2(qb[d2], kk, sb);
        }
        float a0, a1, b0, b1;
        unpack2(sa, a0, a1); unpack2(sb, b0, b1);
        const float ea = __expf(a0 + a1);
        const float eb = __expf(b0 + b1);
        suma += ea; sumb += eb;
        const u64 ea2 = pack2(ea, ea), eb2 = pack2(eb, eb);
        #pragma unroll
        for (int d2 = 0; d2 < 8; d2++) {
            const u64 vv = vs2[m][d2];
            acca[d2] = ffma2(ea2, vv, acca[d2]);
            accb[d2] = ffma2(eb2, vv, accb[d2]);
        }
    }

    const float inva = 1.f / suma, invb = 1.f / sumb;
    #pragma unroll
    for (int d2 = 0; d2 < 8; d2++) {
        float lo, hi;
        unpack2(acca[d2], lo, hi);
        const size_t base = ((size_t)b * 128 + 64 + h * 16 + 2 * d2) * HW + p;
        ch[base]      = __float2half(lo * inva);
        ch[base + HW] = __float2half(hi * inva);
        unpack2(accb[d2], lo, hi);
        ch[base + 128]      = __float2half(lo * invb);
        ch[base + HW + 128] = __float2half(hi * invb);
    }
}

// ---------------- launch (R13-proven structure) ------------------------------
extern "C" void kernel_launch(void* const* d_in, const int* in_sizes, int n_in,
                              void* d_out, int out_size)
{
    const float* x     = (const float*)d_in[0];
    const float* Wqkv  = (const float*)d_in[1];
    const float* bqkv  = (const float*)d_in[2];
    const float* Wdw   = (const float*)d_in[3];
    const float* bdw   = (const float*)d_in[4];
    const float* Wa1   = (const float*)d_in[5];
    const float* ba1   = (const float*)d_in[6];
    const float* Wa2   = (const float*)d_in[7];
    const float* ba2   = (const float*)d_in[8];
    const float* Wq    = (const float*)d_in[9];
    const float* bq    = (const float*)d_in[10];
    const float* Wkv   = (const float*)d_in[11];
    const float* bkv   = (const float*)d_in[12];
    const float* Wproj = (const float*)d_in[13];
    const float* bproj = (const float*)d_in[14];
    float* out = (float*)d_out;

    float *qkv, *v, *qg, *kv, *xp, *b1;
    h16 *xh, *qkh, *ch;
    h16 *w1h, *wph, *wpl;
    cudaGetSymbolAddress((void**)&qkv, g_qkv);
    cudaGetSymbolAddress((void**)&v,   g_v);
    cudaGetSymbolAddress((void**)&qg,  g_qg);
    cudaGetSymbolAddress((void**)&kv,  g_kv);
    cudaGetSymbolAddress((void**)&xp,  g_xp);
    cudaGetSymbolAddress((void**)&b1,  g_b1);
    cudaGetSymbolAddress((void**)&xh,  g_xh);
    cudaGetSymbolAddress((void**)&qkh, g_qkh);
    cudaGetSymbolAddress((void**)&ch,  g_ch);
    cudaGetSymbolAddress((void**)&w1h, g_w1h);
    cudaGetSymbolAddress((void**)&wph, g_wph);
    cudaGetSymbolAddress((void**)&wpl, g_wpl);

    cudaFuncSetAttribute(gemm_f16<true, false>,
                         cudaFuncAttributeMaxDynamicSharedMemorySize, SMEM_G1);
    cudaFuncSetAttribute(gemm_f16<false, true>,
                         cudaFuncAttributeMaxDynamicSharedMemorySize, SMEM_PR);
    cudaFuncSetAttribute(fused_a1a2,
                         cudaFuncAttributeMaxDynamicSharedMemorySize, F2SMEM);

    static cudaStream_t s1 = nullptr;
    static cudaEvent_t e1 = nullptr, e2 = nullptr, e3 = nullptr;
    if (!s1) {
        cudaStreamCreateWithFlags(&s1, cudaStreamNonBlocking);
        cudaEventCreateWithFlags(&e1, cudaEventDisableTiming);
        cudaEventCreateWithFlags(&e2, cudaEventDisableTiming);
        cudaEventCreateWithFlags(&e3, cudaEventDisableTiming);
    }

    // 0) weight prep + x cvt/pool (main stream)
    prep_weights<<<225, 256>>>(Wqkv, Wq, Wa1, Wa2, Wproj, bqkv, bq);
    cvtpool<<<NB * 128, 256>>>(x, xh, xp);
    cudaEventRecord(e1, 0);

    // 1) fused qkv+qg GEMM (all-single fp16: 1 MMA/tile)
    gemm_f16<true, false><<<dim3(HW / 256, 4, NB), 256, SMEM_G1>>>(
        xh, w1h, nullptr, b1, 128, HW,
        qkv, 192 * HW, qg, 64 * HW, 192);
    cudaEventRecord(e2, 0);

    // side branch: kv then attention (overlaps dwconv + fused)
    cudaStreamWaitEvent(s1, e1, 0);
    kv_simt<<<NB * 128 * 256 / 256, 256, 0, s1>>>(xp, Wkv, bkv, kv);
    cudaStreamWaitEvent(s1, e2, 0);
    lowfreq_attn<<<dim3(HW / 256, 4, NB), 128, 0, s1>>>(qg, kv, ch);
    cudaEventRecord(e3, s1);

    // 2) depthwise 3x3 with q*k fusion (32-row tiles)
    dwconv_qk<<<dim3(1, 4, NB * 128), 128>>>(qkv, Wdw, bdw, qkh, v);

    // 3+4) fused a1 -> swish -> a2 -> tanh*v -> cat planes [0,64)
    fused_a1a2<<<dim3(HW / 128, NB), 256, F2SMEM>>>(qkh, ba1, ba2, v, ch);

    // join, then 5) out = Wproj @ cat (W split, cat single: 2 MMAs/tile)
    cudaStreamWaitEvent(0, e3, 0);
    gemm_f16<false, true><<<dim3(HW / 256, 2, NB), 256, SMEM_PR>>>(
        ch, wph, wpl, bproj, 128, HW,
        out, 128 * HW, nullptr, 0, 0);
}

// round 16
// speedup vs baseline: 1.3431x; 1.0330x over previous
#include <cuda_runtime.h>
#include <cuda_fp16.h>
#include <math.h>

#define HW 16384
#define HH 128
#define WW 128
#define NB 4

typedef unsigned long long u64;
typedef unsigned int u32;
typedef __half h16;

// ---------------- f32x2 helpers (attention) ---------------------------------
__device__ __forceinline__ u64 pack2(float lo, float hi) {
    u64 r; asm("mov.b64 %0,{%1,%2};" : "=l"(r) : "f"(lo), "f"(hi)); return r;
}
__device__ __forceinline__ void unpack2(u64 v, float& lo, float& hi) {
    asm("mov.b64 {%0,%1},%2;" : "=f"(lo), "=f"(hi) : "l"(v));
}
__device__ __forceinline__ u64 ffma2(u64 a, u64 b, u64 c) {
    u64 r; asm("fma.rn.f32x2 %0,%1,%2,%3;" : "=l"(r) : "l"(a), "l"(b), "l"(c)); return r;
}

// ---------------- scratch ----------------------------------------------------
__device__ __align__(256) float g_qkv [NB * 192 * HW];
__device__ __align__(256) float g_v   [NB * 64  * HW];
__device__ __align__(256) float g_qg  [NB * 64  * HW];
__device__ __align__(256) float g_kv  [NB * 128 * 256];
__device__ __align__(256) float g_xp  [NB * 128 * 256];
__device__ __align__(256) h16   g_xh  [NB * 128 * HW];
__device__ __align__(256) h16   g_qkh [NB * 64 * HW];
__device__ __align__(256) h16   g_ch  [NB * 128 * HW];
__device__ __align__(256) h16   g_w1h [256 * 128];
__device__ __align__(256) h16   g_wa1h[64 * 64];
__device__ __align__(256) h16   g_wa2h[64 * 64];
__device__ __align__(256) h16   g_wa2l[64 * 64];
__device__ __align__(256) h16   g_wph [128 * 128];
__device__ __align__(256) float g_b1  [256];

// ---------------- mma / cp.async helpers ------------------------------------
__device__ __forceinline__ u32 smem_u32(const void* p) {
    u32 a;
    asm("{ .reg .u64 t; cvta.to.shared.u64 t, %1; cvt.u32.u64 %0, t; }"
        : "=r"(a) : "l"(p));
    return a;
}
__device__ __forceinline__ void ldm_x4(u32 a, u32& r0, u32& r1, u32& r2, u32& r3) {
    asm volatile("ldmatrix.sync.aligned.m8n8.x4.shared.b16 {%0,%1,%2,%3},[%4];"
                 : "=r"(r0), "=r"(r1), "=r"(r2), "=r"(r3) : "r"(a));
}
__device__ __forceinline__ void ldm_x4t(u32 a, u32& r0, u32& r1, u32& r2, u32& r3) {
    asm volatile("ldmatrix.sync.aligned.m8n8.x4.trans.shared.b16 {%0,%1,%2,%3},[%4];"
                 : "=r"(r0), "=r"(r1), "=r"(r2), "=r"(r3) : "r"(a));
}
__device__ __forceinline__ void mma_f16(float* c, const u32* a, u32 b0, u32 b1) {
    asm volatile(
        "mma.sync.aligned.m16n8k16.row.col.f32.f16.f16.f32 "
        "{%0,%1,%2,%3},{%4,%5,%6,%7},{%8,%9},{%0,%1,%2,%3};"
        : "+f"(c[0]), "+f"(c[1]), "+f"(c[2]), "+f"(c[3])
        : "r"(a[0]), "r"(a[1]), "r"(a[2]), "r"(a[3]), "r"(b0), "r"(b1));
}
__device__ __forceinline__ void cpa16(u32 d, const void* s) {
    asm volatile("cp.async.cg.shared.global [%0],[%1],16;" :: "r"(d), "l"(s));
}
__device__ __forceinline__ void cp_commit() {
    asm volatile("cp.async.commit_group;" ::: "memory");
}
template<int N> __device__ __forceinline__ void cp_wait() {
    asm volatile("cp.async.wait_group %0;" :: "n"(N) : "memory");
}
__device__ __forceinline__ void split2h(float x0, float x1, u32& h, u32& l) {
    h16 h0 = __float2half(x0);
    h16 h1 = __float2half(x1);
    float r0 = x0 - __half2float(h0);
    float r1 = x1 - __half2float(h1);
    __half2 hp = __halves2half2(h0, h1);
    __half2 lp = __halves2half2(__float2half(r0), __float2half(r1));
    h = *reinterpret_cast<u32*>(&hp);
    l = *reinterpret_cast<u32*>(&lp);
}

// ---------------- GEMM geometry ----------------------------------------------
#define APITCH 40
#define BPITCH 264
#define APB (64 * APITCH * 2)
#define BPB (32 * BPITCH * 2)
#define SSTR (APB + BPB)
#define SMEM_G (3 * SSTR)                 // 3-stage ring, W single, X single

// ---------------- fp16 tensor-core GEMM (3-stage cp.async ring) --------------
// grid = (px, oc, batch).  Single product h*h.
template<bool DUAL>
__global__ void __launch_bounds__(256, 2) gemm_f16(
    const h16* __restrict__ Xh, const h16* __restrict__ Wh,
    const float* __restrict__ bias, int IC, int NPIX,
    float* dstf, int dstf_stride,
    float* dstf2, int dst2_stride, int oc_split)
{
    extern __shared__ __align__(16) char sm[];
    const int tid = threadIdx.x;
    const int lane = tid & 31, warp = tid >> 5;
    const int px0 = blockIdx.x * 256;
    const int oc0 = blockIdx.y * 64;
    const int b   = blockIdx.z;
    const u32 smb = smem_u32(sm);

    const h16* Xhb = Xh + (size_t)b * IC * NPIX;

    const int ar = tid >> 2, ac = (tid & 3) * 8;
    const int bc = (tid & 31) * 8, br0 = tid >> 5;
    const int nk = IC >> 5;

    float c[4][4][4];
    #pragma unroll
    for (int i = 0; i < 4; i++)
        #pragma unroll
        for (int j = 0; j < 4; j++)
            #pragma unroll
            for (int q = 0; q < 4; q++) c[i][j][q] = 0.f;

    auto issue = [&](int it) {
        const u32 base = smb + (u32)(it % 3) * SSTR;
        const int k0 = it << 5;
        const size_t aO = (size_t)(oc0 + ar) * IC + k0 + ac;
        cpa16(base + (u32)(ar * APITCH + ac) * 2, Wh + aO);
        #pragma unroll
        for (int i = 0; i < 4; i++) {
            const int brr = br0 + i * 8;
            const size_t bO = (size_t)(k0 + brr) * NPIX + px0 + bc;
            cpa16(base + APB + (u32)(brr * BPITCH + bc) * 2, Xhb + bO);
        }
        cp_commit();
    };

    issue(0);
    issue(1);

    const int grp = lane >> 3, lr = lane & 7;
    const int r8  = (grp & 1) * 8 + lr;
    const int kh8 = (grp >> 1) * 8;
    const int wn32 = warp * 32;

    for (int it = 0; it < nk; it++) {
        if (it + 2 < nk)      { issue(it + 2); cp_wait<2>(); }
        else if (it + 1 < nk) { cp_wait<1>(); }
        else                  { cp_wait<0>(); }
        __syncthreads();
        const u32 aHi = smb + (u32)(it % 3) * SSTR;
        const u32 bHi = aHi + APB;
        #pragma unroll
        for (int ks = 0; ks < 2; ks++) {
            u32 bh[2][4];
            #pragma unroll
            for (int g = 0; g < 2; g++) {
                const u32 off = (u32)((ks * 16 + r8) * BPITCH + wn32 + g * 16 + kh8) * 2;
                ldm_x4t(bHi + off, bh[g][0], bh[g][1], bh[g][2], bh[g][3]);
            }
            #pragma unroll
            for (int mi = 0; mi < 4; mi++) {
                u32 ah[4];
                const u32 aoff = (u32)((mi * 16 + r8) * APITCH + ks * 16 + kh8) * 2;
                ldm_x4(aHi + aoff, ah[0], ah[1], ah[2], ah[3]);
                #pragma unroll
                for (int nj = 0; nj < 4; nj++) {
                    const int g = nj >> 1, s2 = nj & 1;
                    mma_f16(c[mi][nj], ah, bh[g][2 * s2], bh[g][2 * s2 + 1]);
                }
            }
        }
        __syncthreads();
    }

    // ---- epilogue
    const int r4 = lane >> 2, c2 = (lane & 3) * 2;
    #pragma unroll
    for (int mi = 0; mi < 4; mi++) {
        #pragma unroll
        for (int h = 0; h < 2; h++) {
            const int oc = oc0 + mi * 16 + h * 8 + r4;
            const float bv = bias[oc];
            #pragma unroll
            for (int nj = 0; nj < 4; nj++) {
                const int px = px0 + wn32 + nj * 8 + c2;
                const float v0 = c[mi][nj][h * 2]     + bv;
                const float v1 = c[mi][nj][h * 2 + 1] + bv;
                if (DUAL) {
                    if (oc < oc_split)
                        *reinterpret_cast<float2*>(dstf + (size_t)b * dstf_stride
                            + (size_t)oc * NPIX + px) = make_float2(v0, v1);
                    else
                        *reinterpret_cast<float2*>(dstf2 + (size_t)b * dst2_stride
                            + (size_t)(oc - oc_split) * NPIX + px) = make_float2(v0, v1);
                } else {
                    *reinterpret_cast<float2*>(dstf + (size_t)b * dstf_stride
                        + (size_t)oc * NPIX + px) = make_float2(v0, v1);
                }
            }
        }
    }
}

// ---------------- fused a1->swish->a2->tanh*v, 128-px tiles -----------------
#define F2PITCH 136
#define F2STG (32 * F2PITCH * 2)
#define F2W1H (4 * F2STG)
#define F2W2H (F2W1H + 64 * 72 * 2)
#define F2W2L (F2W2H + 64 * 72 * 2)
#define F2SMEM (F2W2L + 64 * 72 * 2)

__global__ void __launch_bounds__(256, 3) fused_a1a2(
    const h16* __restrict__ qkh,
    const float* __restrict__ ba1, const float* __restrict__ ba2,
    const float* __restrict__ vsrc,
    h16* __restrict__ ch)
{
    extern __shared__ __align__(16) char sm[];
    const int tid = threadIdx.x;
    const int lane = tid & 31, warp = tid >> 5;
    const int px0 = blockIdx.x * 128;
    const int b   = blockIdx.y;
    const u32 smb = smem_u32(sm);

    const h16* qkhb = qkh + (size_t)b * 64 * HW + px0;

    {
        const int r = tid >> 2;
        const int sb = (tid & 3) * 32;
        const size_t go = (size_t)r * 64 + (tid & 3) * 16;
        const u32 so = (u32)(r * 72) * 2 + sb;
        cpa16(smb + F2W1H + so, g_wa1h + go); cpa16(smb + F2W1H + so + 16, g_wa1h + go + 8);
        cpa16(smb + F2W2H + so, g_wa2h + go); cpa16(smb + F2W2H + so + 16, g_wa2h + go + 8);
        cpa16(smb + F2W2L + so, g_wa2l + go); cpa16(smb + F2W2L + so + 16, g_wa2l + go + 8);
    }
    const int bc = (tid & 15) * 8, br0 = tid >> 4;
    auto issueB = [&](int chunk) {
        const u32 base = smb + chunk * F2STG;
        #pragma unroll
        for (int i = 0; i < 2; i++) {
            const int brr = br0 + i * 16;
            const u32 d = base + (u32)(brr * F2PITCH + bc) * 2;
            const size_t o = (size_t)(chunk * 32 + brr) * HW + bc;
            cpa16(d, qkhb + o);
        }
        cp_commit();
    };
    issueB(0);
    issueB(1);

    const int grp = lane >> 3, lr = lane & 7;
    const int r8  = (grp & 1) * 8 + lr;
    const int kh8 = (grp >> 1) * 8;
    const int wn16 = warp * 16;
    const int r4 = lane >> 2, c2 = (lane & 3) * 2;

    float c[4][2][4];
    #pragma unroll
    for (int i = 0; i < 4; i++)
        #pragma unroll
        for (int j = 0; j < 2; j++)
            #pragma unroll
            for (int q = 0; q < 4; q++) c[i][j][q] = 0.f;

    // ---- phase 1 (1 product)
    for (int it = 0; it < 2; it++) {
        if (it == 0) cp_wait<1>(); else cp_wait<0>();
        __syncthreads();
        const u32 bBase = smb + it * F2STG;
        #pragma unroll
        for (int ks = 0; ks < 2; ks++) {
            u32 bh[4];
            const u32 off = (u32)((ks * 16 + r8) * F2PITCH + wn16 + kh8) * 2;
            ldm_x4t(bBase + off, bh[0], bh[1], bh[2], bh[3]);
            #pragma unroll
            for (int mi = 0; mi < 4; mi++) {
                u32 ah[4];
                const u32 aoff = (u32)((mi * 16 + r8) * 72 + it * 32 + ks * 16 + kh8) * 2;
                ldm_x4(smb + F2W1H + aoff, ah[0], ah[1], ah[2], ah[3]);
                #pragma unroll
                for (int nj = 0; nj < 2; nj++)
                    mma_f16(c[mi][nj], ah, bh[2 * nj], bh[2 * nj + 1]);
            }
        }
    }
    __syncthreads();

    // ---- swish + split a into smem
    #pragma unroll
    for (int mi = 0; mi < 4; mi++) {
        #pragma unroll
        for (int h = 0; h < 2; h++) {
            const int oc = mi * 16 + h * 8 + r4;
            const float bv = __ldg(&ba1[oc]);
            const u32 halfb = (oc & 32) ? 2u * F2STG : 0u;
            #pragma unroll
            for (int nj = 0; nj < 2; nj++) {
                float v0 = c[mi][nj][h * 2]     + bv;
                float v1 = c[mi][nj][h * 2 + 1] + bv;
                v0 = v0 / (1.f + __expf(-v0));
                v1 = v1 / (1.f + __expf(-v1));
                u32 hp, lp; split2h(v0, v1, hp, lp);
                const u32 off = (u32)((oc & 31) * F2PITCH + wn16 + nj * 8 + c2) * 2;
                *reinterpret_cast<u32*>(sm + halfb + off)         = hp;
                *reinterpret_cast<u32*>(sm + halfb + F2STG + off) = lp;
            }
        }
    }
    __syncthreads();

    // ---- phase 2 (3 products, a split)
    #pragma unroll
    for (int i = 0; i < 4; i++)
        #pragma unroll
        for (int j = 0; j < 2; j++)
            #pragma unroll
            for (int q = 0; q < 4; q++) c[i][j][q] = 0.f;

    #pragma unroll
    for (int it = 0; it < 2; it++) {
        const u32 bHi = smb + it * 2 * F2STG, bLo = bHi + F2STG;
        #pragma unroll
        for (int ks = 0; ks < 2; ks++) {
            u32 bh[4], bl[4];
            const u32 off = (u32)((ks * 16 + r8) * F2PITCH + wn16 + kh8) * 2;
            ldm_x4t(bHi + off, bh[0], bh[1], bh[2], bh[3]);
            ldm_x4t(bLo + off, bl[0], bl[1], bl[2], bl[3]);
            #pragma unroll
            for (int mi = 0; mi < 4; mi++) {
                u32 ah[4], al[4];
                const u32 aoff = (u32)((mi * 16 + r8) * 72 + it * 32 + ks * 16 + kh8) * 2;
                ldm_x4(smb + F2W2H + aoff, ah[0], ah[1], ah[2], ah[3]);
                ldm_x4(smb + F2W2L + aoff, al[0], al[1], al[2], al[3]);
                #pragma unroll
                for (int nj = 0; nj < 2; nj++) {
                    mma_f16(c[mi][nj], ah, bh[2 * nj], bh[2 * nj + 1]);
                    mma_f16(c[mi][nj], ah, bl[2 * nj], bl[2 * nj + 1]);
                    mma_f16(c[mi][nj], al, bh[2 * nj], bh[2 * nj + 1]);
                }
            }
        }
    }

    #pragma unroll
    for (int mi = 0; mi < 4; mi++) {
        #pragma unroll
        for (int h = 0; h < 2; h++) {
            const int oc = mi * 16 + h * 8 + r4;
            const float bv = __ldg(&ba2[oc]);
            #pragma unroll
            for (int nj = 0; nj < 2; nj++) {
                const int px = px0 + wn16 + nj * 8 + c2;
                const float* vr = vsrc + ((size_t)b * 64 + oc) * HW + px;
                float v0 = tanhf((c[mi][nj][h * 2]     + bv) * 0.25f) * __ldg(vr);
                float v1 = tanhf((c[mi][nj][h * 2 + 1] + bv) * 0.25f) * __ldg(vr + 1);
                __half2 hp = __floats2half2_rn(v0, v1);
                const size_t o = ((size_t)b * 128 + oc) * HW + px;
                *reinterpret_cast<u32*>(ch + o) = *reinterpret_cast<u32*>(&hp);
            }
        }
    }
}

// ---------------- x cvt/pool + weight prep, one kernel -----------------------
__device__ __forceinline__ void wsplit(float x, h16* hd, h16* ld, size_t o) {
    h16 h = __float2half(x);
    hd[o] = h;
    ld[o] = __float2half(x - __half2float(h));
}

__global__ void __launch_bounds__(256) cvt_prep(
    const float* __restrict__ x, h16* __restrict__ xh, float* __restrict__ xp,
    const float* __restrict__ Wqkv, const float* __restrict__ Wq,
    const float* __restrict__ Wa1, const float* __restrict__ Wa2,
    const float* __restrict__ Wproj,
    const float* __restrict__ bqkv, const float* __restrict__ bq)
{
    const int blk = blockIdx.x;
    if (blk < NB * 128) {
        const int plane = blk;
        const int t = threadIdx.x;
        const int wi = t >> 4, wj = t & 15;
        const float* sp = x + (size_t)plane * HW + (wi * 8) * WW + wj * 8;
        h16* oh = xh + (size_t)plane * HW + (wi * 8) * WW + wj * 8;

        float s = 0.f;
        #pragma unroll
        for (int r = 0; r < 8; r++) {
            const float4 a = *reinterpret_cast<const float4*>(sp + r * WW);
            const float4 b = *reinterpret_cast<const float4*>(sp + r * WW + 4);
            s += a.x + a.y + a.z + a.w + b.x + b.y + b.z + b.w;
            __half2 p0 = __floats2half2_rn(a.x, a.y);
            __half2 p1 = __floats2half2_rn(a.z, a.w);
            __half2 p2 = __floats2half2_rn(b.x, b.y);
            __half2 p3 = __floats2half2_rn(b.z, b.w);
            *reinterpret_cast<uint4*>(oh + r * WW) =
                make_uint4(*reinterpret_cast<u32*>(&p0), *reinterpret_cast<u32*>(&p1),
                           *reinterpret_cast<u32*>(&p2), *reinterpret_cast<u32*>(&p3));
        }
        xp[(size_t)plane * 256 + wi * 16 + wj] = s * (1.f / 64.f);
    } else {
        const int i = (blk - NB * 128) * 256 + threadIdx.x;
        if (i < 32768) {
            float v = (i < 24576) ? Wqkv[i] : Wq[i - 24576];
            g_w1h[i] = __float2half(v);
        } else if (i < 36864) {
            g_wa1h[i - 32768] = __float2half(Wa1[i - 32768]);
        } else if (i < 40960) {
            wsplit(Wa2[i - 36864], g_wa2h, g_wa2l, i - 36864);
        } else if (i < 57344) {
            g_wph[i - 40960] = __float2half(Wproj[i - 40960]);
        } else if (i < 57600) {
            const int j = i - 57344;
            g_b1[j] = (j < 192) ? bqkv[j] : bq[j - 192];
        }
    }
}

// ---------------- depthwise 3x3, smem-tiled rolling stencil (32-row tiles) --
__global__ void __launch_bounds__(128) dwconv_qk(
    const float* __restrict__ qkv, const float* __restrict__ w,
    const float* __restrict__ bias,
    h16* __restrict__ qkh, float* __restrict__ vout)
{
    const int z = blockIdx.z;
    const int b = z >> 7, t = z & 127;
    const int x = threadIdx.x;
    const int y0 = blockIdx.y * 32;

    __shared__ float s0[34][136];
    __shared__ float s1[34][136];

    if (t < 64) {
        const float* pq = qkv + ((size_t)b * 192 + t) * HW;
        const float* pk = qkv + ((size_t)b * 192 + 64 + t) * HW;
        #pragma unroll
        for (int r = 0; r < 34; r++) {
            const int yy = y0 - 1 + r;
            const bool ok = (yy >= 0) && (yy < HH);
            s0[r][x + 1] = ok ? __ldg(pq + yy * WW + x) : 0.f;
            s1[r][x + 1] = ok ? __ldg(pk + yy * WW + x) : 0.f;
        }
        if (x < 2) {
            const int col = x ? 129 : 0;
            #pragma unroll
            for (int r = 0; r < 34; r++) { s0[r][col] = 0.f; s1[r][col] = 0.f; }
        }
        __syncthreads();

        float wq[9], wk[9];
        #pragma unroll
        for (int i = 0; i < 9; i++) {
            wq[i] = __ldg(&w[t * 9 + i]);
            wk[i] = __ldg(&w[(64 + t) * 9 + i]);
        }
        const float bq = __ldg(&bias[t]);
        const float bk = __ldg(&bias[64 + t]);

        h16* oh = qkh + ((size_t)b * 64 + t) * HW + (size_t)y0 * WW + x;

        float Aq = 0.f, Bq = 0.f, Ak = 0.f, Bk = 0.f;
        #pragma unroll
        for (int r = 0; r < 34; r++) {
            const float lq = s0[r][x], cq = s0[r][x + 1], rq = s0[r][x + 2];
            const float h0q = wq[0]*lq + wq[1]*cq + wq[2]*rq;
            const float h1q = wq[3]*lq + wq[4]*cq + wq[5]*rq;
            const float h2q = wq[6]*lq + wq[7]*cq + wq[8]*rq;
            const float lk = s1[r][x], ck = s1[r][x + 1], rk = s1[r][x + 2];
            const float h0k = wk[0]*lk + wk[1]*ck + wk[2]*rk;
            const float h1k = wk[3]*lk + wk[4]*ck + wk[5]*rk;
            const float h2k = wk[6]*lk + wk[7]*ck + wk[8]*rk;
            Aq += h2q; Ak += h2k;
            if (r >= 2) {
                const float prod = (Aq + bq) * (Ak + bk);
                oh[(r - 2) * WW] = __float2half(prod);
            }
            Aq = Bq + h1q; Bq = h0q;
            Ak = Bk + h1k; Bk = h0k;
        }
    } else {
        const int cv = t - 64;
        const float* pv = qkv + ((size_t)b * 192 + 128 + cv) * HW;
        #pragma unroll
        for (int r = 0; r < 34; r++) {
            const int yy = y0 - 1 + r;
            s0[r][x + 1] = (yy >= 0 && yy < HH) ? __ldg(pv + yy * WW + x) : 0.f;
        }
        if (x < 2) {
            const int col = x ? 129 : 0;
            #pragma unroll
            for (int r = 0; r < 34; r++) s0[r][col] = 0.f;
        }
        __syncthreads();

        float wv[9];
        #pragma unroll
        for (int i = 0; i < 9; i++) wv[i] = __ldg(&w[(128 + cv) * 9 + i]);
        const float bv = __ldg(&bias[128 + cv]);

        float* ov = vout + ((size_t)b * 64 + cv) * HW + (size_t)y0 * WW + x;
        float A = 0.f, Bv = 0.f;
        #pragma unroll
        for (int r = 0; r < 34; r++) {
            const float lv = s0[r][x], cvv = s0[r][x + 1], rv = s0[r][x + 2];
            const float h0 = wv[0]*lv + wv[1]*cvv + wv[2]*rv;
            const float h1 = wv[3]*lv + wv[4]*cvv + wv[5]*rv;
            const float h2 = wv[6]*lv + wv[7]*cvv + wv[8]*rv;
            A += h2;
            if (r >= 2) ov[(r - 2) * WW] = A + bv;
            A = Bv + h1; Bv = h0;
        }
    }
}

// ---------------- kv = Wkv @ xp + bkv (SIMT, fp32) ---------------------------
__global__ void __launch_bounds__(256) kv_simt(
    const float* __restrict__ xp, const float* __restrict__ Wkv,
    const float* __restrict__ bkv, float* __restrict__ kvout)
{
    const int idx = blockIdx.x * 256 + threadIdx.x;
    const int p  = idx & 255;
    const int oc = (idx >> 8) & 127;
    const int b  = idx >> 15;
    const float* xpb = xp + (size_t)b * 128 * 256 + p;
    const float* wr  = Wkv + oc * 128;
    float acc = __ldg(&bkv[oc]);
    #pragma unroll 8
    for (int c = 0; c < 128; c++)
        acc += __ldg(wr + c) * __ldg(xpb + c * 256);
    kvout[((size_t)b * 128 + oc) * 256 + p] = acc;
}

// ---------------- low-freq softmax attention (2 px/thread) -------------------
__global__ void __launch_bounds__(128) lowfreq_attn(
    const float* __restrict__ qg, const float* __restrict__ kv,
    h16* __restrict__ ch)
{
    const int b = blockIdx.z, h = blockIdx.y;
    const int p = blockIdx.x * 256 + threadIdx.x;

    __shared__ __align__(16) u64 ks2[256][8];
    __shared__ __align__(16) u64 vs2[256][8];

    const float* kvb = kv + (size_t)b * 128 * 256;
    for (int i = threadIdx.x; i < 2048; i += 128) {
        const int d2 = i >> 8, m = i & 255;
        ks2[m][d2] = pack2(kvb[(h * 16 + 2 * d2) * 256 + m],
                           kvb[(h * 16 + 2 * d2 + 1) * 256 + m]);
        vs2[m][d2] = pack2(kvb[(64 + h * 16 + 2 * d2) * 256 + m],
                           kvb[(64 + h * 16 + 2 * d2 + 1) * 256 + m]);
    }
    __syncthreads();

    u64 qa[8], qb[8];
    #pragma unroll
    for (int d2 = 0; d2 < 8; d2++) {
        const size_t base = (size_t)b * 64 * HW + (size_t)(h * 16 + 2 * d2) * HW + p;
        qa[d2] = pack2(0.25f * __ldg(&qg[base]),       0.25f * __ldg(&qg[base + HW]));
        qb[d2] = pack2(0.25f * __ldg(&qg[base + 128]), 0.25f * __ldg(&qg[base + HW + 128]));
    }

    float suma = 0.f, sumb = 0.f;
    u64 acca[8], accb[8];
    #pragma unroll
    for (int d2 = 0; d2 < 8; d2++) { acca[d2] = 0ull; accb[d2] = 0ull; }

    for (int m = 0; m < 256; m++) {
        u64 sa = 0ull, sb = 0ull;
        #pragma unroll
        for (int d2 = 0; d2 < 8; d2++) {
            const u64 kk = ks2[m][d2];
            sa = ffma2(qa[d2], kk, sa);
            sb = ffma2(qb[d2], kk, sb);
        }
        float a0, a1, b0, b1;
        unpack2(sa, a0, a1); unpack2(sb, b0, b1);
        const float ea = __expf(a0 + a1);
        const float eb = __expf(b0 + b1);
        suma += ea; sumb += eb;
        const u64 ea2 = pack2(ea, ea), eb2 = pack2(eb, eb);
        #pragma unroll
        for (int d2 = 0; d2 < 8; d2++) {
            const u64 vv = vs2[m][d2];
            acca[d2] = ffma2(ea2, vv, acca[d2]);
            accb[d2] = ffma2(eb2, vv, accb[d2]);
        }
    }

    const float inva = 1.f / suma, invb = 1.f / sumb;
    #pragma unroll
    for (int d2 = 0; d2 < 8; d2++) {
        float lo, hi;
        unpack2(acca[d2], lo, hi);
        const size_t base = ((size_t)b * 128 + 64 + h * 16 + 2 * d2) * HW + p;
        ch[base]      = __float2half(lo * inva);
        ch[base + HW] = __float2half(hi * inva);
        unpack2(accb[d2], lo, hi);
        ch[base + 128]      = __float2half(lo * invb);
        ch[base + HW + 128] = __float2half(hi * invb);
    }
}

// ---------------- launch -----------------------------------------------------
extern "C" void kernel_launch(void* const* d_in, const int* in_sizes, int n_in,
                              void* d_out, int out_size)
{
    const float* x     = (const float*)d_in[0];
    const float* Wqkv  = (const float*)d_in[1];
    const float* bqkv  = (const float*)d_in[2];
    const float* Wdw   = (const float*)d_in[3];
    const float* bdw   = (const float*)d_in[4];
    const float* Wa1   = (const float*)d_in[5];
    const float* ba1   = (const float*)d_in[6];
    const float* Wa2   = (const float*)d_in[7];
    const float* ba2   = (const float*)d_in[8];
    const float* Wq    = (const float*)d_in[9];
    const float* bq    = (const float*)d_in[10];
    const float* Wkv   = (const float*)d_in[11];
    const float* bkv   = (const float*)d_in[12];
    const float* Wproj = (const float*)d_in[13];
    const float* bproj = (const float*)d_in[14];
    float* out = (float*)d_out;

    float *qkv, *v, *qg, *kv, *xp, *b1;
    h16 *xh, *qkh, *ch;
    h16 *w1h, *wph;
    cudaGetSymbolAddress((void**)&qkv, g_qkv);
    cudaGetSymbolAddress((void**)&v,   g_v);
    cudaGetSymbolAddress((void**)&qg,  g_qg);
    cudaGetSymbolAddress((void**)&kv,  g_kv);
    cudaGetSymbolAddress((void**)&xp,  g_xp);
    cudaGetSymbolAddress((void**)&b1,  g_b1);
    cudaGetSymbolAddress((void**)&xh,  g_xh);
    cudaGetSymbolAddress((void**)&qkh, g_qkh);
    cudaGetSymbolAddress((void**)&ch,  g_ch);
    cudaGetSymbolAddress((void**)&w1h, g_w1h);
    cudaGetSymbolAddress((void**)&wph, g_wph);

    cudaFuncSetAttribute(gemm_f16<true>,
                         cudaFuncAttributeMaxDynamicSharedMemorySize, SMEM_G);
    cudaFuncSetAttribute(gemm_f16<false>,
                         cudaFuncAttributeMaxDynamicSharedMemorySize, SMEM_G);
    cudaFuncSetAttribute(fused_a1a2,
                         cudaFuncAttributeMaxDynamicSharedMemorySize, F2SMEM);

    static cudaStream_t s1 = nullptr;
    static cudaEvent_t e1 = nullptr, e2 = nullptr, e3 = nullptr;
    if (!s1) {
        cudaStreamCreateWithFlags(&s1, cudaStreamNonBlocking);
        cudaEventCreateWithFlags(&e1, cudaEventDisableTiming);
        cudaEventCreateWithFlags(&e2, cudaEventDisableTiming);
        cudaEventCreateWithFlags(&e3, cudaEventDisableTiming);
    }

    // 0) x cvt/pool + weight prep in one kernel (main stream)
    cvt_prep<<<NB * 128 + 225, 256>>>(x, xh, xp,
                                      Wqkv, Wq, Wa1, Wa2, Wproj, bqkv, bq);
    cudaEventRecord(e1, 0);

    // 1) fused qkv+qg GEMM (single fp16 product, 3-stage ring)
    gemm_f16<true><<<dim3(HW / 256, 4, NB), 256, SMEM_G>>>(
        xh, w1h, b1, 128, HW,
        qkv, 192 * HW, qg, 64 * HW, 192);
    cudaEventRecord(e2, 0);

    // side branch: kv then attention (overlaps dwconv + fused)
    cudaStreamWaitEvent(s1, e1, 0);
    kv_simt<<<NB * 128 * 256 / 256, 256, 0, s1>>>(xp, Wkv, bkv, kv);
    cudaStreamWaitEvent(s1, e2, 0);
    lowfreq_attn<<<dim3(HW / 256, 4, NB), 128, 0, s1>>>(qg, kv, ch);
    cudaEventRecord(e3, s1);

    // 2) depthwise 3x3 with q*k fusion (32-row tiles)
    dwconv_qk<<<dim3(1, 4, NB * 128), 128>>>(qkv, Wdw, bdw, qkh, v);

    // 3+4) fused a1 -> swish -> a2 -> tanh*v -> cat planes [0,64)
    fused_a1a2<<<dim3(HW / 128, NB), 256, F2SMEM>>>(qkh, ba1, ba2, v, ch);

    // join, then 5) out = Wproj @ cat (single product, 3-stage ring)
    cudaStreamWaitEvent(0, e3, 0);
    gemm_f16<false><<<dim3(HW / 256, 2, NB), 256, SMEM_G>>>(
        ch, wph, bproj, 128, HW,
        out, 128 * HW, nullptr, 0, 0);
}

// round 17
// speedup vs baseline: 1.9758x; 1.4710x over previous
#include <cuda_runtime.h>
#include <cuda_fp16.h>
#include <math.h>

#define HW 16384
#define HH 128
#define WW 128
#define NB 4

typedef unsigned long long u64;
typedef unsigned int u32;
typedef __half h16;

// ---------------- scratch ----------------------------------------------------
__device__ __align__(256) float g_qkv [NB * 192 * HW];
__device__ __align__(256) float g_v   [NB * 64  * HW];
__device__ __align__(256) float g_qg  [NB * 64  * HW];
__device__ __align__(256) float g_kv  [NB * 128 * 256];
__device__ __align__(256) float g_xp  [NB * 128 * 256];
__device__ __align__(256) h16   g_xh  [NB * 128 * HW];
__device__ __align__(256) h16   g_qkh [NB * 64 * HW];
__device__ __align__(256) h16   g_ch  [NB * 128 * HW];
__device__ __align__(256) h16   g_w1h [256 * 128];
__device__ __align__(256) h16   g_wa1h[64 * 64];
__device__ __align__(256) h16   g_wa2h[64 * 64];
__device__ __align__(256) h16   g_wa2l[64 * 64];
__device__ __align__(256) h16   g_wph [128 * 128];
__device__ __align__(256) float g_b1  [256];

// ---------------- mma / cp.async helpers ------------------------------------
__device__ __forceinline__ u32 smem_u32(const void* p) {
    u32 a;
    asm("{ .reg .u64 t; cvta.to.shared.u64 t, %1; cvt.u32.u64 %0, t; }"
        : "=r"(a) : "l"(p));
    return a;
}
__device__ __forceinline__ void ldm_x4(u32 a, u32& r0, u32& r1, u32& r2, u32& r3) {
    asm volatile("ldmatrix.sync.aligned.m8n8.x4.shared.b16 {%0,%1,%2,%3},[%4];"
                 : "=r"(r0), "=r"(r1), "=r"(r2), "=r"(r3) : "r"(a));
}
__device__ __forceinline__ void ldm_x4t(u32 a, u32& r0, u32& r1, u32& r2, u32& r3) {
    asm volatile("ldmatrix.sync.aligned.m8n8.x4.trans.shared.b16 {%0,%1,%2,%3},[%4];"
                 : "=r"(r0), "=r"(r1), "=r"(r2), "=r"(r3) : "r"(a));
}
__device__ __forceinline__ void mma_f16(float* c, const u32* a, u32 b0, u32 b1) {
    asm volatile(
        "mma.sync.aligned.m16n8k16.row.col.f32.f16.f16.f32 "
        "{%0,%1,%2,%3},{%4,%5,%6,%7},{%8,%9},{%0,%1,%2,%3};"
        : "+f"(c[0]), "+f"(c[1]), "+f"(c[2]), "+f"(c[3])
        : "r"(a[0]), "r"(a[1]), "r"(a[2]), "r"(a[3]), "r"(b0), "r"(b1));
}
__device__ __forceinline__ void cpa16(u32 d, const void* s) {
    asm volatile("cp.async.cg.shared.global [%0],[%1],16;" :: "r"(d), "l"(s));
}
__device__ __forceinline__ void cp_commit() {
    asm volatile("cp.async.commit_group;" ::: "memory");
}
template<int N> __device__ __forceinline__ void cp_wait() {
    asm volatile("cp.async.wait_group %0;" :: "n"(N) : "memory");
}
__device__ __forceinline__ void split2h(float x0, float x1, u32& h, u32& l) {
    h16 h0 = __float2half(x0);
    h16 h1 = __float2half(x1);
    float r0 = x0 - __half2float(h0);
    float r1 = x1 - __half2float(h1);
    __half2 hp = __halves2half2(h0, h1);
    __half2 lp = __halves2half2(__float2half(r0), __float2half(r1));
    h = *reinterpret_cast<u32*>(&hp);
    l = *reinterpret_cast<u32*>(&lp);
}

// ---------------- GEMM geometry ----------------------------------------------
#define APITCH 40
#define BPITCH 264
#define APB (64 * APITCH * 2)
#define BPB (32 * BPITCH * 2)
#define SSTR (APB + BPB)
#define SMEM_G (3 * SSTR)

// ---------------- fp16 tensor-core GEMM (3-stage cp.async ring) --------------
template<bool DUAL>
__global__ void __launch_bounds__(256, 2) gemm_f16(
    const h16* __restrict__ Xh, const h16* __restrict__ Wh,
    const float* __restrict__ bias, int IC, int NPIX,
    float* dstf, int dstf_stride,
    float* dstf2, int dst2_stride, int oc_split)
{
    extern __shared__ __align__(16) char sm[];
    const int tid = threadIdx.x;
    const int lane = tid & 31, warp = tid >> 5;
    const int px0 = blockIdx.x * 256;
    const int oc0 = blockIdx.y * 64;
    const int b   = blockIdx.z;
    const u32 smb = smem_u32(sm);

    const h16* Xhb = Xh + (size_t)b * IC * NPIX;

    const int ar = tid >> 2, ac = (tid & 3) * 8;
    const int bc = (tid & 31) * 8, br0 = tid >> 5;
    const int nk = IC >> 5;

    float c[4][4][4];
    #pragma unroll
    for (int i = 0; i < 4; i++)
        #pragma unroll
        for (int j = 0; j < 4; j++)
            #pragma unroll
            for (int q = 0; q < 4; q++) c[i][j][q] = 0.f;

    auto issue = [&](int it) {
        const u32 base = smb + (u32)(it % 3) * SSTR;
        const int k0 = it << 5;
        const size_t aO = (size_t)(oc0 + ar) * IC + k0 + ac;
        cpa16(base + (u32)(ar * APITCH + ac) * 2, Wh + aO);
        #pragma unroll
        for (int i = 0; i < 4; i++) {
            const int brr = br0 + i * 8;
            const size_t bO = (size_t)(k0 + brr) * NPIX + px0 + bc;
            cpa16(base + APB + (u32)(brr * BPITCH + bc) * 2, Xhb + bO);
        }
        cp_commit();
    };

    issue(0);
    issue(1);

    const int grp = lane >> 3, lr = lane & 7;
    const int r8  = (grp & 1) * 8 + lr;
    const int kh8 = (grp >> 1) * 8;
    const int wn32 = warp * 32;

    for (int it = 0; it < nk; it++) {
        if (it + 2 < nk)      { issue(it + 2); cp_wait<2>(); }
        else if (it + 1 < nk) { cp_wait<1>(); }
        else                  { cp_wait<0>(); }
        __syncthreads();
        const u32 aHi = smb + (u32)(it % 3) * SSTR;
        const u32 bHi = aHi + APB;
        #pragma unroll
        for (int ks = 0; ks < 2; ks++) {
            u32 bh[2][4];
            #pragma unroll
            for (int g = 0; g < 2; g++) {
                const u32 off = (u32)((ks * 16 + r8) * BPITCH + wn32 + g * 16 + kh8) * 2;
                ldm_x4t(bHi + off, bh[g][0], bh[g][1], bh[g][2], bh[g][3]);
            }
            #pragma unroll
            for (int mi = 0; mi < 4; mi++) {
                u32 ah[4];
                const u32 aoff = (u32)((mi * 16 + r8) * APITCH + ks * 16 + kh8) * 2;
                ldm_x4(aHi + aoff, ah[0], ah[1], ah[2], ah[3]);
                #pragma unroll
                for (int nj = 0; nj < 4; nj++) {
                    const int g = nj >> 1, s2 = nj & 1;
                    mma_f16(c[mi][nj], ah, bh[g][2 * s2], bh[g][2 * s2 + 1]);
                }
            }
        }
        __syncthreads();
    }

    const int r4 = lane >> 2, c2 = (lane & 3) * 2;
    #pragma unroll
    for (int mi = 0; mi < 4; mi++) {
        #pragma unroll
        for (int h = 0; h < 2; h++) {
            const int oc = oc0 + mi * 16 + h * 8 + r4;
            const float bv = bias[oc];
            #pragma unroll
            for (int nj = 0; nj < 4; nj++) {
                const int px = px0 + wn32 + nj * 8 + c2;
                const float v0 = c[mi][nj][h * 2]     + bv;
                const float v1 = c[mi][nj][h * 2 + 1] + bv;
                if (DUAL) {
                    if (oc < oc_split)
                        *reinterpret_cast<float2*>(dstf + (size_t)b * dstf_stride
                            + (size_t)oc * NPIX + px) = make_float2(v0, v1);
                    else
                        *reinterpret_cast<float2*>(dstf2 + (size_t)b * dst2_stride
                            + (size_t)(oc - oc_split) * NPIX + px) = make_float2(v0, v1);
                } else {
                    *reinterpret_cast<float2*>(dstf + (size_t)b * dstf_stride
                        + (size_t)oc * NPIX + px) = make_float2(v0, v1);
                }
            }
        }
    }
}

// ---------------- fused a1->swish->a2->tanh*v, 128-px tiles -----------------
#define F2PITCH 136
#define F2STG (32 * F2PITCH * 2)
#define F2W1H (4 * F2STG)
#define F2W2H (F2W1H + 64 * 72 * 2)
#define F2W2L (F2W2H + 64 * 72 * 2)
#define F2SMEM (F2W2L + 64 * 72 * 2)

__global__ void __launch_bounds__(256, 3) fused_a1a2(
    const h16* __restrict__ qkh,
    const float* __restrict__ ba1, const float* __restrict__ ba2,
    const float* __restrict__ vsrc,
    h16* __restrict__ ch)
{
    extern __shared__ __align__(16) char sm[];
    const int tid = threadIdx.x;
    const int lane = tid & 31, warp = tid >> 5;
    const int px0 = blockIdx.x * 128;
    const int b   = blockIdx.y;
    const u32 smb = smem_u32(sm);

    const h16* qkhb = qkh + (size_t)b * 64 * HW + px0;

    {
        const int r = tid >> 2;
        const int sb = (tid & 3) * 32;
        const size_t go = (size_t)r * 64 + (tid & 3) * 16;
        const u32 so = (u32)(r * 72) * 2 + sb;
        cpa16(smb + F2W1H + so, g_wa1h + go); cpa16(smb + F2W1H + so + 16, g_wa1h + go + 8);
        cpa16(smb + F2W2H + so, g_wa2h + go); cpa16(smb + F2W2H + so + 16, g_wa2h + go + 8);
        cpa16(smb + F2W2L + so, g_wa2l + go); cpa16(smb + F2W2L + so + 16, g_wa2l + go + 8);
    }
    const int bc = (tid & 15) * 8, br0 = tid >> 4;
    auto issueB = [&](int chunk) {
        const u32 base = smb + chunk * F2STG;
        #pragma unroll
        for (int i = 0; i < 2; i++) {
            const int brr = br0 + i * 16;
            const u32 d = base + (u32)(brr * F2PITCH + bc) * 2;
            const size_t o = (size_t)(chunk * 32 + brr) * HW + bc;
            cpa16(d, qkhb + o);
        }
        cp_commit();
    };
    issueB(0);
    issueB(1);

    const int grp = lane >> 3, lr = lane & 7;
    const int r8  = (grp & 1) * 8 + lr;
    const int kh8 = (grp >> 1) * 8;
    const int wn16 = warp * 16;
    const int r4 = lane >> 2, c2 = (lane & 3) * 2;

    float c[4][2][4];
    #pragma unroll
    for (int i = 0; i < 4; i++)
        #pragma unroll
        for (int j = 0; j < 2; j++)
            #pragma unroll
            for (int q = 0; q < 4; q++) c[i][j][q] = 0.f;

    for (int it = 0; it < 2; it++) {
        if (it == 0) cp_wait<1>(); else cp_wait<0>();
        __syncthreads();
        const u32 bBase = smb + it * F2STG;
        #pragma unroll
        for (int ks = 0; ks < 2; ks++) {
            u32 bh[4];
            const u32 off = (u32)((ks * 16 + r8) * F2PITCH + wn16 + kh8) * 2;
            ldm_x4t(bBase + off, bh[0], bh[1], bh[2], bh[3]);
            #pragma unroll
            for (int mi = 0; mi < 4; mi++) {
                u32 ah[4];
                const u32 aoff = (u32)((mi * 16 + r8) * 72 + it * 32 + ks * 16 + kh8) * 2;
                ldm_x4(smb + F2W1H + aoff, ah[0], ah[1], ah[2], ah[3]);
                #pragma unroll
                for (int nj = 0; nj < 2; nj++)
                    mma_f16(c[mi][nj], ah, bh[2 * nj], bh[2 * nj + 1]);
            }
        }
    }
    __syncthreads();

    #pragma unroll
    for (int mi = 0; mi < 4; mi++) {
        #pragma unroll
        for (int h = 0; h < 2; h++) {
            const int oc = mi * 16 + h * 8 + r4;
            const float bv = __ldg(&ba1[oc]);
            const u32 halfb = (oc & 32) ? 2u * F2STG : 0u;
            #pragma unroll
            for (int nj = 0; nj < 2; nj++) {
                float v0 = c[mi][nj][h * 2]     + bv;
                float v1 = c[mi][nj][h * 2 + 1] + bv;
                v0 = v0 / (1.f + __expf(-v0));
                v1 = v1 / (1.f + __expf(-v1));
                u32 hp, lp; split2h(v0, v1, hp, lp);
                const u32 off = (u32)((oc & 31) * F2PITCH + wn16 + nj * 8 + c2) * 2;
                *reinterpret_cast<u32*>(sm + halfb + off)         = hp;
                *reinterpret_cast<u32*>(sm + halfb + F2STG + off) = lp;
            }
        }
    }
    __syncthreads();

    #pragma unroll
    for (int i = 0; i < 4; i++)
        #pragma unroll
        for (int j = 0; j < 2; j++)
            #pragma unroll
            for (int q = 0; q < 4; q++) c[i][j][q] = 0.f;

    #pragma unroll
    for (int it = 0; it < 2; it++) {
        const u32 bHi = smb + it * 2 * F2STG, bLo = bHi + F2STG;
        #pragma unroll
        for (int ks = 0; ks < 2; ks++) {
            u32 bh[4], bl[4];
            const u32 off = (u32)((ks * 16 + r8) * F2PITCH + wn16 + kh8) * 2;
            ldm_x4t(bHi + off, bh[0], bh[1], bh[2], bh[3]);
            ldm_x4t(bLo + off, bl[0], bl[1], bl[2], bl[3]);
            #pragma unroll
            for (int mi = 0; mi < 4; mi++) {
                u32 ah[4], al[4];
                const u32 aoff = (u32)((mi * 16 + r8) * 72 + it * 32 + ks * 16 + kh8) * 2;
                ldm_x4(smb + F2W2H + aoff, ah[0], ah[1], ah[2], ah[3]);
                ldm_x4(smb + F2W2L + aoff, al[0], al[1], al[2], al[3]);
                #pragma unroll
                for (int nj = 0; nj < 2; nj++) {
                    mma_f16(c[mi][nj], ah, bh[2 * nj], bh[2 * nj + 1]);
                    mma_f16(c[mi][nj], ah, bl[2 * nj], bl[2 * nj + 1]);
                    mma_f16(c[mi][nj], al, bh[2 * nj], bh[2 * nj + 1]);
                }
            }
        }
    }

    #pragma unroll
    for (int mi = 0; mi < 4; mi++) {
        #pragma unroll
        for (int h = 0; h < 2; h++) {
            const int oc = mi * 16 + h * 8 + r4;
            const float bv = __ldg(&ba2[oc]);
            #pragma unroll
            for (int nj = 0; nj < 2; nj++) {
                const int px = px0 + wn16 + nj * 8 + c2;
                const float* vr = vsrc + ((size_t)b * 64 + oc) * HW + px;
                float v0 = tanhf((c[mi][nj][h * 2]     + bv) * 0.25f) * __ldg(vr);
                float v1 = tanhf((c[mi][nj][h * 2 + 1] + bv) * 0.25f) * __ldg(vr + 1);
                __half2 hp = __floats2half2_rn(v0, v1);
                const size_t o = ((size_t)b * 128 + oc) * HW + px;
                *reinterpret_cast<u32*>(ch + o) = *reinterpret_cast<u32*>(&hp);
            }
        }
    }
}

// ---------------- x cvt/pool + weight prep, one kernel -----------------------
__device__ __forceinline__ void wsplit(float x, h16* hd, h16* ld, size_t o) {
    h16 h = __float2half(x);
    hd[o] = h;
    ld[o] = __float2half(x - __half2float(h));
}

__global__ void __launch_bounds__(256) cvt_prep(
    const float* __restrict__ x, h16* __restrict__ xh, float* __restrict__ xp,
    const float* __restrict__ Wqkv, const float* __restrict__ Wq,
    const float* __restrict__ Wa1, const float* __restrict__ Wa2,
    const float* __restrict__ Wproj,
    const float* __restrict__ bqkv, const float* __restrict__ bq)
{
    const int blk = blockIdx.x;
    if (blk < NB * 128) {
        const int plane = blk;
        const int t = threadIdx.x;
        const int wi = t >> 4, wj = t & 15;
        const float* sp = x + (size_t)plane * HW + (wi * 8) * WW + wj * 8;
        h16* oh = xh + (size_t)plane * HW + (wi * 8) * WW + wj * 8;

        float s = 0.f;
        #pragma unroll
        for (int r = 0; r < 8; r++) {
            const float4 a = *reinterpret_cast<const float4*>(sp + r * WW);
            const float4 b = *reinterpret_cast<const float4*>(sp + r * WW + 4);
            s += a.x + a.y + a.z + a.w + b.x + b.y + b.z + b.w;
            __half2 p0 = __floats2half2_rn(a.x, a.y);
            __half2 p1 = __floats2half2_rn(a.z, a.w);
            __half2 p2 = __floats2half2_rn(b.x, b.y);
            __half2 p3 = __floats2half2_rn(b.z, b.w);
            *reinterpret_cast<uint4*>(oh + r * WW) =
                make_uint4(*reinterpret_cast<u32*>(&p0), *reinterpret_cast<u32*>(&p1),
                           *reinterpret_cast<u32*>(&p2), *reinterpret_cast<u32*>(&p3));
        }
        xp[(size_t)plane * 256 + wi * 16 + wj] = s * (1.f / 64.f);
    } else {
        const int i = (blk - NB * 128) * 256 + threadIdx.x;
        if (i < 32768) {
            float v = (i < 24576) ? Wqkv[i] : Wq[i - 24576];
            g_w1h[i] = __float2half(v);
        } else if (i < 36864) {
            g_wa1h[i - 32768] = __float2half(Wa1[i - 32768]);
        } else if (i < 40960) {
            wsplit(Wa2[i - 36864], g_wa2h, g_wa2l, i - 36864);
        } else if (i < 57344) {
            g_wph[i - 40960] = __float2half(Wproj[i - 40960]);
        } else if (i < 57600) {
            const int j = i - 57344;
            g_b1[j] = (j < 192) ? bqkv[j] : bq[j - 192];
        }
    }
}

// ---------------- depthwise 3x3, smem-tiled rolling stencil (32-row tiles) --
__global__ void __launch_bounds__(128) dwconv_qk(
    const float* __restrict__ qkv, const float* __restrict__ w,
    const float* __restrict__ bias,
    h16* __restrict__ qkh, float* __restrict__ vout)
{
    const int z = blockIdx.z;
    const int b = z >> 7, t = z & 127;
    const int x = threadIdx.x;
    const int y0 = blockIdx.y * 32;

    __shared__ float s0[34][136];
    __shared__ float s1[34][136];

    if (t < 64) {
        const float* pq = qkv + ((size_t)b * 192 + t) * HW;
        const float* pk = qkv + ((size_t)b * 192 + 64 + t) * HW;
        #pragma unroll
        for (int r = 0; r < 34; r++) {
            const int yy = y0 - 1 + r;
            const bool ok = (yy >= 0) && (yy < HH);
            s0[r][x + 1] = ok ? __ldg(pq + yy * WW + x) : 0.f;
            s1[r][x + 1] = ok ? __ldg(pk + yy * WW + x) : 0.f;
        }
        if (x < 2) {
            const int col = x ? 129 : 0;
            #pragma unroll
            for (int r = 0; r < 34; r++) { s0[r][col] = 0.f; s1[r][col] = 0.f; }
        }
        __syncthreads();

        float wq[9], wk[9];
        #pragma unroll
        for (int i = 0; i < 9; i++) {
            wq[i] = __ldg(&w[t * 9 + i]);
            wk[i] = __ldg(&w[(64 + t) * 9 + i]);
        }
        const float bq = __ldg(&bias[t]);
        const float bk = __ldg(&bias[64 + t]);

        h16* oh = qkh + ((size_t)b * 64 + t) * HW + (size_t)y0 * WW + x;

        float Aq = 0.f, Bq = 0.f, Ak = 0.f, Bk = 0.f;
        #pragma unroll
        for (int r = 0; r < 34; r++) {
            const float lq = s0[r][x], cq = s0[r][x + 1], rq = s0[r][x + 2];
            const float h0q = wq[0]*lq + wq[1]*cq + wq[2]*rq;
            const float h1q = wq[3]*lq + wq[4]*cq + wq[5]*rq;
            const float h2q = wq[6]*lq + wq[7]*cq + wq[8]*rq;
            const float lk = s1[r][x], ck = s1[r][x + 1], rk = s1[r][x + 2];
            const float h0k = wk[0]*lk + wk[1]*ck + wk[2]*rk;
            const float h1k = wk[3]*lk + wk[4]*ck + wk[5]*rk;
            const float h2k = wk[6]*lk + wk[7]*ck + wk[8]*rk;
            Aq += h2q; Ak += h2k;
            if (r >= 2) {
                const float prod = (Aq + bq) * (Ak + bk);
                oh[(r - 2) * WW] = __float2half(prod);
            }
            Aq = Bq + h1q; Bq = h0q;
            Ak = Bk + h1k; Bk = h0k;
        }
    } else {
        const int cv = t - 64;
        const float* pv = qkv + ((size_t)b * 192 + 128 + cv) * HW;
        #pragma unroll
        for (int r = 0; r < 34; r++) {
            const int yy = y0 - 1 + r;
            s0[r][x + 1] = (yy >= 0 && yy < HH) ? __ldg(pv + yy * WW + x) : 0.f;
        }
        if (x < 2) {
            const int col = x ? 129 : 0;
            #pragma unroll
            for (int r = 0; r < 34; r++) s0[r][col] = 0.f;
        }
        __syncthreads();

        float wv[9];
        #pragma unroll
        for (int i = 0; i < 9; i++) wv[i] = __ldg(&w[(128 + cv) * 9 + i]);
        const float bv = __ldg(&bias[128 + cv]);

        float* ov = vout + ((size_t)b * 64 + cv) * HW + (size_t)y0 * WW + x;
        float A = 0.f, Bv = 0.f;
        #pragma unroll
        for (int r = 0; r < 34; r++) {
            const float lv = s0[r][x], cvv = s0[r][x + 1], rv = s0[r][x + 2];
            const float h0 = wv[0]*lv + wv[1]*cvv + wv[2]*rv;
            const float h1 = wv[3]*lv + wv[4]*cvv + wv[5]*rv;
            const float h2 = wv[6]*lv + wv[7]*cvv + wv[8]*rv;
            A += h2;
            if (r >= 2) ov[(r - 2) * WW] = A + bv;
            A = Bv + h1; Bv = h0;
        }
    }
}

// ---------------- kv = Wkv @ xp + bkv (SIMT, fp32) ---------------------------
__global__ void __launch_bounds__(256) kv_simt(
    const float* __restrict__ xp, const float* __restrict__ Wkv,
    const float* __restrict__ bkv, float* __restrict__ kvout)
{
    const int idx = blockIdx.x * 256 + threadIdx.x;
    const int p  = idx & 255;
    const int oc = (idx >> 8) & 127;
    const int b  = idx >> 15;
    const float* xpb = xp + (size_t)b * 128 * 256 + p;
    const float* wr  = Wkv + oc * 128;
    float acc = __ldg(&bkv[oc]);
    #pragma unroll 8
    for (int c = 0; c < 128; c++)
        acc += __ldg(wr + c) * __ldg(xpb + c * 256);
    kvout[((size_t)b * 128 + oc) * 256 + p] = acc;
}

// ---------------- MMA flash attention ----------------------------------------
// Block: 128 px x 1 head x 1 batch, 8 warps x 16 px.
// Scores: 3-product split (QhKh + QhKl + QlKh), fp32 accum, exp fp32 (no max).
// AV: P fp16 x (Vh + Vl).  Output transposed through smem, fp16 to cat.
#define KPITCH 24
#define VPITCH 264
#define A_KH 0
#define A_KL (A_KH + 256 * KPITCH * 2)               // 12288
#define A_VH (A_KL + 256 * KPITCH * 2)               // 24576
#define A_VL (A_VH + 16 * VPITCH * 2)                // 33024
#define A_QH (A_VL + 16 * VPITCH * 2)                // 41472
#define A_QL (A_QH + 128 * KPITCH * 2)               // 47616
#define A_TOT (A_QL + 128 * KPITCH * 2)              // 53760
#define OPITCH 136

__global__ void __launch_bounds__(256, 2) attn_mma(
    const float* __restrict__ qg, const float* __restrict__ kv,
    h16* __restrict__ ch)
{
    extern __shared__ __align__(16) char sm[];
    const int tid = threadIdx.x;
    const int lane = tid & 31, warp = tid >> 5;
    const int px0 = blockIdx.x * 128;
    const int h   = blockIdx.y;
    const int b   = blockIdx.z;
    const u32 smb = smem_u32(sm);

    h16* KH = reinterpret_cast<h16*>(sm + A_KH);
    h16* KL = reinterpret_cast<h16*>(sm + A_KL);
    h16* VH = reinterpret_cast<h16*>(sm + A_VH);
    h16* VL = reinterpret_cast<h16*>(sm + A_VL);
    h16* QH = reinterpret_cast<h16*>(sm + A_QH);
    h16* QL = reinterpret_cast<h16*>(sm + A_QL);

    const float* kvb = kv + (size_t)b * 128 * 256;
    const float* qgb = qg + (size_t)b * 64 * HW + px0;

    // ---- stage K (split, [key][dim]) and V (split, [dim][key])
    #pragma unroll
    for (int i = 0; i < 16; i++) {
        const int idx = tid + 256 * i;
        const int d = idx >> 8, m = idx & 255;
        const float kvv = kvb[(h * 16 + d) * 256 + m];
        h16 khi = __float2half(kvv);
        KH[m * KPITCH + d] = khi;
        KL[m * KPITCH + d] = __float2half(kvv - __half2float(khi));
        const float vvv = kvb[(64 + h * 16 + d) * 256 + m];
        h16 vhi = __float2half(vvv);
        VH[d * VPITCH + m] = vhi;
        VL[d * VPITCH + m] = __float2half(vvv - __half2float(vhi));
    }
    // ---- stage Q (split, [px][dim], scale 0.25 folded)
    #pragma unroll
    for (int i = 0; i < 8; i++) {
        const int idx = tid + 256 * i;
        const int d = idx >> 7, p = idx & 127;
        const float qs = 0.25f * qgb[(size_t)(h * 16 + d) * HW + p];
        h16 qhi = __float2half(qs);
        QH[p * KPITCH + d] = qhi;
        QL[p * KPITCH + d] = __float2half(qs - __half2float(qhi));
    }
    __syncthreads();

    const int grp = lane >> 3, lr = lane & 7;
    // Q fragment addresses (A layout)
    const u32 qoff = (u32)((warp * 16 + (grp & 1) * 8 + lr) * KPITCH
                           + (grp >> 1) * 8) * 2;
    u32 qh[4], ql[4];
    ldm_x4(smb + A_QH + qoff, qh[0], qh[1], qh[2], qh[3]);
    ldm_x4(smb + A_QL + qoff, ql[0], ql[1], ql[2], ql[3]);

    float o0[4] = {0.f, 0.f, 0.f, 0.f};
    float o1[4] = {0.f, 0.f, 0.f, 0.f};
    float sumr = 0.f, sumr8 = 0.f;

    // K B-frag lane offset (row=key, col=dim): tiles (k0 d0)(k0 d8)(k8 d0)(k8 d8)
    const u32 kla = (u32)(((grp >> 1) * 8 + lr) * KPITCH + (grp & 1) * 8) * 2;
    // V B-frag lane offset (row=dim, col=key): tiles (d0 k0)(d0 k8)(d8 k0)(d8 k8)
    const u32 vla = (u32)(((grp >> 1) * 8 + lr) * VPITCH + (grp & 1) * 8) * 2;

    for (int kc = 0; kc < 16; kc++) {
        u32 kh[4], kl[4], vh[4], vl[4];
        const u32 koff = (u32)(kc * 16 * KPITCH) * 2 + kla;
        ldm_x4(smb + A_KH + koff, kh[0], kh[1], kh[2], kh[3]);
        ldm_x4(smb + A_KL + koff, kl[0], kl[1], kl[2], kl[3]);
        const u32 voff = (u32)(kc * 16) * 2 + vla;
        ldm_x4(smb + A_VH + voff, vh[0], vh[1], vh[2], vh[3]);
        ldm_x4(smb + A_VL + voff, vl[0], vl[1], vl[2], vl[3]);

        float s0[4] = {0.f, 0.f, 0.f, 0.f};
        float s1[4] = {0.f, 0.f, 0.f, 0.f};
        mma_f16(s0, qh, kh[0], kh[1]);
        mma_f16(s0, qh, kl[0], kl[1]);
        mma_f16(s0, ql, kh[0], kh[1]);
        mma_f16(s1, qh, kh[2], kh[3]);
        mma_f16(s1, qh, kl[2], kl[3]);
        mma_f16(s1, ql, kh[2], kh[3]);

        const float e00 = __expf(s0[0]), e01 = __expf(s0[1]);
        const float e02 = __expf(s0[2]), e03 = __expf(s0[3]);
        const float e10 = __expf(s1[0]), e11 = __expf(s1[1]);
        const float e12 = __expf(s1[2]), e13 = __expf(s1[3]);
        sumr  += e00 + e01 + e10 + e11;
        sumr8 += e02 + e03 + e12 + e13;

        u32 p[4];
        __half2 pp;
        pp = __floats2half2_rn(e00, e01); p[0] = *reinterpret_cast<u32*>(&pp);
        pp = __floats2half2_rn(e02, e03); p[1] = *reinterpret_cast<u32*>(&pp);
        pp = __floats2half2_rn(e10, e11); p[2] = *reinterpret_cast<u32*>(&pp);
        pp = __floats2half2_rn(e12, e13); p[3] = *reinterpret_cast<u32*>(&pp);

        mma_f16(o0, p, vh[0], vh[1]);
        mma_f16(o0, p, vl[0], vl[1]);
        mma_f16(o1, p, vh[2], vh[3]);
        mma_f16(o1, p, vl[2], vl[3]);
    }

    // ---- row-sum reduction across the 4 lanes sharing each row
    sumr  += __shfl_xor_sync(0xffffffff, sumr, 1);
    sumr  += __shfl_xor_sync(0xffffffff, sumr, 2);
    sumr8 += __shfl_xor_sync(0xffffffff, sumr8, 1);
    sumr8 += __shfl_xor_sync(0xffffffff, sumr8, 2);
    const float invr = 1.f / sumr, invr8 = 1.f / sumr8;

    // ---- stage O into smem [dim][px] (reuse QH region), then coalesced write
    __syncthreads();
    h16* OST = reinterpret_cast<h16*>(sm + A_QH);
    const int r = lane >> 2, tc2 = (lane & 3) * 2;
    const int pxr = warp * 16 + r;
    OST[tc2 * OPITCH + pxr]           = __float2half(o0[0] * invr);
    OST[(tc2 + 1) * OPITCH + pxr]     = __float2half(o0[1] * invr);
    OST[tc2 * OPITCH + pxr + 8]       = __float2half(o0[2] * invr8);
    OST[(tc2 + 1) * OPITCH + pxr + 8] = __float2half(o0[3] * invr8);
    OST[(tc2 + 8) * OPITCH + pxr]         = __float2half(o1[0] * invr);
    OST[(tc2 + 9) * OPITCH + pxr]         = __float2half(o1[1] * invr);
    OST[(tc2 + 8) * OPITCH + pxr + 8]     = __float2half(o1[2] * invr8);
    OST[(tc2 + 9) * OPITCH + pxr + 8]     = __float2half(o1[3] * invr8);
    __syncthreads();

    const int d = tid >> 4, seg = (tid & 15) * 8;
    h16* dst = ch + ((size_t)b * 128 + 64 + h * 16 + d) * HW + px0 + seg;
    *reinterpret_cast<uint4*>(dst) =
        *reinterpret_cast<const uint4*>(OST + d * OPITCH + seg);
}

// ---------------- launch -----------------------------------------------------
extern "C" void kernel_launch(void* const* d_in, const int* in_sizes, int n_in,
                              void* d_out, int out_size)
{
    const float* x     = (const float*)d_in[0];
    const float* Wqkv  = (const float*)d_in[1];
    const float* bqkv  = (const float*)d_in[2];
    const float* Wdw   = (const float*)d_in[3];
    const float* bdw   = (const float*)d_in[4];
    const float* Wa1   = (const float*)d_in[5];
    const float* ba1   = (const float*)d_in[6];
    const float* Wa2   = (const float*)d_in[7];
    const float* ba2   = (const float*)d_in[8];
    const float* Wq    = (const float*)d_in[9];
    const float* bq    = (const float*)d_in[10];
    const float* Wkv   = (const float*)d_in[11];
    const float* bkv   = (const float*)d_in[12];
    const float* Wproj = (const float*)d_in[13];
    const float* bproj = (const float*)d_in[14];
    float* out = (float*)d_out;

    float *qkv, *v, *qg, *kv, *xp, *b1;
    h16 *xh, *qkh, *ch;
    h16 *w1h, *wph;
    cudaGetSymbolAddress((void**)&qkv, g_qkv);
    cudaGetSymbolAddress((void**)&v,   g_v);
    cudaGetSymbolAddress((void**)&qg,  g_qg);
    cudaGetSymbolAddress((void**)&kv,  g_kv);
    cudaGetSymbolAddress((void**)&xp,  g_xp);
    cudaGetSymbolAddress((void**)&b1,  g_b1);
    cudaGetSymbolAddress((void**)&xh,  g_xh);
    cudaGetSymbolAddress((void**)&qkh, g_qkh);
    cudaGetSymbolAddress((void**)&ch,  g_ch);
    cudaGetSymbolAddress((void**)&w1h, g_w1h);
    cudaGetSymbolAddress((void**)&wph, g_wph);

    cudaFuncSetAttribute(gemm_f16<true>,
                         cudaFuncAttributeMaxDynamicSharedMemorySize, SMEM_G);
    cudaFuncSetAttribute(gemm_f16<false>,
                         cudaFuncAttributeMaxDynamicSharedMemorySize, SMEM_G);
    cudaFuncSetAttribute(fused_a1a2,
                         cudaFuncAttributeMaxDynamicSharedMemorySize, F2SMEM);
    cudaFuncSetAttribute(attn_mma,
                         cudaFuncAttributeMaxDynamicSharedMemorySize, A_TOT);

    static cudaStream_t s1 = nullptr;
    static cudaEvent_t e1 = nullptr, e2 = nullptr, e3 = nullptr;
    if (!s1) {
        cudaStreamCreateWithFlags(&s1, cudaStreamNonBlocking);
        cudaEventCreateWithFlags(&e1, cudaEventDisableTiming);
        cudaEventCreateWithFlags(&e2, cudaEventDisableTiming);
        cudaEventCreateWithFlags(&e3, cudaEventDisableTiming);
    }

    // 0) x cvt/pool + weight prep (main stream)
    cvt_prep<<<NB * 128 + 225, 256>>>(x, xh, xp,
                                      Wqkv, Wq, Wa1, Wa2, Wproj, bqkv, bq);
    cudaEventRecord(e1, 0);

    // 1) fused qkv+qg GEMM
    gemm_f16<true><<<dim3(HW / 256, 4, NB), 256, SMEM_G>>>(
        xh, w1h, b1, 128, HW,
        qkv, 192 * HW, qg, 64 * HW, 192);
    cudaEventRecord(e2, 0);

    // side branch: kv then MMA attention (overlaps dwconv + fused)
    cudaStreamWaitEvent(s1, e1, 0);
    kv_simt<<<NB * 128 * 256 / 256, 256, 0, s1>>>(xp, Wkv, bkv, kv);
    cudaStreamWaitEvent(s1, e2, 0);
    attn_mma<<<dim3(HW / 128, 4, NB), 256, A_TOT, s1>>>(qg, kv, ch);
    cudaEventRecord(e3, s1);

    // 2) depthwise 3x3 with q*k fusion
    dwconv_qk<<<dim3(1, 4, NB * 128), 128>>>(qkv, Wdw, bdw, qkh, v);

    // 3+4) fused a1 -> swish -> a2 -> tanh*v -> cat planes [0,64)
    fused_a1a2<<<dim3(HW / 128, NB), 256, F2SMEM>>>(qkh, ba1, ba2, v, ch);

    // join, then 5) out = Wproj @ cat
    cudaStreamWaitEvent(0, e3, 0);
    gemm_f16<false><<<dim3(HW / 256, 2, NB), 256, SMEM_G>>>(
        ch, wph, bproj, 128, HW,
        out, 128 * HW, nullptr, 0, 0);
}